// round 7
// baseline (speedup 1.0000x reference)
#include <cuda_runtime.h>
#include <cuda_bf16.h>
#include <stdint.h>
#include <stddef.h>
#include <math.h>

// Round 7: pass-major mma ordering. Previous inner loop issued hi*hi, hi*lo,
// lo*hi back-to-back into the SAME accumulator (RAW chain -> warp stalls ~2x
// HMMA latency per group -> tensor pipe pinned at ~51%). Now each of the 3
// passes sweeps all 16 accumulators before the next pass touches them again.
// Per-accumulator FP addition order unchanged -> rel_err must stay identical.

// ---------------------------------------------------------------------------
// Problem constants
// ---------------------------------------------------------------------------
#define EMBED   1280
#define HEADS   16
#define HDIM    80
#define HDIMP   96            // HDIM padded to multiple of BK (zero tail)
#define S_TOTAL 4096
#define NSEG    4
#define SEG_LEN 1024
#define QKV_F   (3 * EMBED)   // 3840

// ---------------------------------------------------------------------------
// Scratch (device globals; zero-initialized at module load -> K-pad stays 0)
// ---------------------------------------------------------------------------
__device__ float    g_qkv[(size_t)S_TOTAL * QKV_F];
__device__ float    g_scores[(size_t)NSEG * HEADS * SEG_LEN * SEG_LEN];
__device__ float    g_ctx[(size_t)S_TOTAL * EMBED];

__device__ uint16_t g_xh[(size_t)S_TOTAL * EMBED],   g_xl[(size_t)S_TOTAL * EMBED];
__device__ uint16_t g_wh[(size_t)QKV_F * EMBED],     g_wl[(size_t)QKV_F * EMBED];
__device__ uint16_t g_pwh[(size_t)EMBED * EMBED],    g_pwl[(size_t)EMBED * EMBED];
__device__ uint16_t g_Qh[(size_t)HEADS * S_TOTAL * HDIMP], g_Ql[(size_t)HEADS * S_TOTAL * HDIMP];
__device__ uint16_t g_Kh[(size_t)HEADS * S_TOTAL * HDIMP], g_Kl[(size_t)HEADS * S_TOTAL * HDIMP];
__device__ uint16_t g_Vth[(size_t)HEADS * HDIM * S_TOTAL], g_Vtl[(size_t)HEADS * HDIM * S_TOTAL];
__device__ uint16_t g_Ph[(size_t)NSEG * HEADS * SEG_LEN * SEG_LEN];
__device__ uint16_t g_Pl[(size_t)NSEG * HEADS * SEG_LEN * SEG_LEN];
__device__ uint16_t g_ch[(size_t)S_TOTAL * EMBED],   g_cl[(size_t)S_TOTAL * EMBED];

// ---------------------------------------------------------------------------
// helpers
// ---------------------------------------------------------------------------
__device__ __forceinline__ uint16_t bf_bits(__nv_bfloat16 h)
{
    return *reinterpret_cast<uint16_t*>(&h);
}

__device__ __forceinline__ void split1(float x, uint16_t& hi, uint16_t& lo)
{
    __nv_bfloat16 h = __float2bfloat16(x);
    float r = x - __bfloat162float(h);
    hi = bf_bits(h);
    lo = bf_bits(__float2bfloat16(r));
}

__device__ __forceinline__ void mma16816(float* c, const uint32_t* a,
                                         uint32_t b0, uint32_t b1)
{
    asm volatile(
        "mma.sync.aligned.m16n8k16.row.col.f32.bf16.bf16.f32 "
        "{%0,%1,%2,%3}, {%4,%5,%6,%7}, {%8,%9}, {%0,%1,%2,%3};"
        : "+f"(c[0]), "+f"(c[1]), "+f"(c[2]), "+f"(c[3])
        : "r"(a[0]), "r"(a[1]), "r"(a[2]), "r"(a[3]), "r"(b0), "r"(b1));
}

__device__ __forceinline__ void ldsm_x4(uint32_t* r, uint32_t addr)
{
    asm volatile("ldmatrix.sync.aligned.m8n8.x4.shared.b16 {%0,%1,%2,%3}, [%4];"
                 : "=r"(r[0]), "=r"(r[1]), "=r"(r[2]), "=r"(r[3]) : "r"(addr));
}

__device__ __forceinline__ void cp_async16(uint32_t dst_smem, const void* src)
{
    asm volatile("cp.async.cg.shared.global [%0], [%1], 16;"
                 :: "r"(dst_smem), "l"(src));
}
__device__ __forceinline__ void cp_async16z(uint32_t dst_smem, const void* src, int src_bytes)
{
    asm volatile("cp.async.cg.shared.global [%0], [%1], 16, %2;"
                 :: "r"(dst_smem), "l"(src), "r"(src_bytes));
}
__device__ __forceinline__ void cp_commit()
{
    asm volatile("cp.async.commit_group;");
}
template <int N>
__device__ __forceinline__ void cp_wait()
{
    asm volatile("cp.async.wait_group %0;" :: "n"(N));
}

// ---------------------------------------------------------------------------
// Tensor-core batched GEMM:  C = alpha * (A @ B^T) + bias
//   A,B as bf16 hi/lo pairs (row-major). M % 128 == 0, K % 32 == 0, N guarded.
// Block 128x128, BK=32, 256 threads (8 warps 4x2), 2-stage cp.async pipeline,
// ldmatrix fragment loads, pass-major mma ordering.
// ---------------------------------------------------------------------------
#define BM 128
#define BN 128
#define BK 32
#define BKP 20                    // u32 per smem row (16 used + 4 pad)
#define SUB (128 * BKP)           // u32 per sub-array
#define STG (4 * SUB)             // u32 per stage
#define SMEM_BYTES (2 * STG * 4)  // 81920

__global__ __launch_bounds__(256, 2)
void gemm_bf16x3(const uint16_t* __restrict__ Ah, const uint16_t* __restrict__ Al,
                 const uint16_t* __restrict__ Bh, const uint16_t* __restrict__ Bl,
                 const float* __restrict__ bias, float* __restrict__ C,
                 int N, int K, int lda, int ldb, int ldc,
                 long oAs, long oAh_, long oBs, long oBh_, long oCs, long oCh_,
                 int nh, float alpha)
{
    extern __shared__ uint32_t sm[];

    const int z   = blockIdx.z;
    const int seg = z / nh;
    const int h   = z % nh;
    Ah += oAs * seg + oAh_ * h;  Al += oAs * seg + oAh_ * h;
    Bh += oBs * seg + oBh_ * h;  Bl += oBs * seg + oBh_ * h;
    C  += oCs * seg + oCh_ * h;

    const int brow = blockIdx.y * BM;
    const int bcol = blockIdx.x * BN;

    const int tid  = threadIdx.x;
    const int warp = tid >> 5;
    const int lane = tid & 31;
    const int wm = (warp >> 1) * 32;
    const int wn = (warp & 1) * 64;
    const int lg = lane >> 2;
    const int lq = lane & 3;

    const uint32_t smem_base = (uint32_t)__cvta_generic_to_shared(sm);

    // ldmatrix per-thread addressing
    const int lm_r = lane & 15;
    const int lm_c = (lane >> 4) * 4;

    // loader indices
    const int lrow = tid >> 2;
    const int lq4  = (tid & 3) * 4;
    const int lk8  = (tid & 3) * 8;

    float acc[2][8][4];
#pragma unroll
    for (int i = 0; i < 2; i++)
#pragma unroll
        for (int j = 0; j < 8; j++)
#pragma unroll
            for (int q = 0; q < 4; q++) acc[i][j][q] = 0.f;

    const int nit = K / BK;

    auto load_stage = [&](int stage, int k0) {
        const uint32_t sb = smem_base + (uint32_t)stage * STG * 4;
#pragma unroll
        for (int r2 = 0; r2 < 2; r2++) {
            const int row = lrow + r2 * 64;
            const uint32_t doff = (uint32_t)(row * BKP + lq4) * 4;
            cp_async16(sb + 0 * SUB * 4 + doff,
                       Ah + (long)(brow + row) * lda + k0 + lk8);
            cp_async16(sb + 1 * SUB * 4 + doff,
                       Al + (long)(brow + row) * lda + k0 + lk8);
            const int bn  = bcol + row;
            const int ok  = (bn < N) ? 16 : 0;
            const int bno = (bn < N) ? bn : 0;
            cp_async16z(sb + 2 * SUB * 4 + doff,
                        Bh + (long)bno * ldb + k0 + lk8, ok);
            cp_async16z(sb + 3 * SUB * 4 + doff,
                        Bl + (long)bno * ldb + k0 + lk8, ok);
        }
    };

    load_stage(0, 0);
    cp_commit();

    const uint32_t aOff0 = (uint32_t)((wm + lm_r) * BKP + lm_c) * 4;
    const uint32_t aOff1 = (uint32_t)((wm + 16 + lm_r) * BKP + lm_c) * 4;
    const uint32_t bOffBase = (uint32_t)((wn + lm_r) * BKP + lm_c) * 4;

    for (int it = 0; it < nit; it++) {
        if (it + 1 < nit) {
            load_stage((it + 1) & 1, (it + 1) * BK);
            cp_commit();
            cp_wait<1>();
        } else {
            cp_wait<0>();
        }
        __syncthreads();

        const uint32_t stageB = smem_base + (uint32_t)(it & 1) * STG * 4;
        const uint32_t aBaseH = stageB;
        const uint32_t aBaseL = stageB + SUB * 4;
        const uint32_t bBaseH = stageB + 2 * SUB * 4;
        const uint32_t bBaseL = stageB + 3 * SUB * 4;

#pragma unroll
        for (int kc = 0; kc < 2; kc++) {
            const uint32_t kbyte = (uint32_t)(kc * 8) * 4;

            uint32_t aH[2][4], aL[2][4];
            ldsm_x4(aH[0], aBaseH + aOff0 + kbyte);
            ldsm_x4(aH[1], aBaseH + aOff1 + kbyte);
            ldsm_x4(aL[0], aBaseL + aOff0 + kbyte);
            ldsm_x4(aL[1], aBaseL + aOff1 + kbyte);

            // B-hi fragments for all 8 n-tiles, held across passes 1 and 3
            uint32_t bh[4][4];
#pragma unroll
            for (int ntp = 0; ntp < 4; ntp++)
                ldsm_x4(bh[ntp], bBaseH + bOffBase + (uint32_t)(ntp * 16 * BKP) * 4 + kbyte);

            // ---- pass 1: hi*hi (16 independent accumulators) ----
#pragma unroll
            for (int ntp = 0; ntp < 4; ntp++)
#pragma unroll
                for (int half = 0; half < 2; half++)
#pragma unroll
                    for (int mt = 0; mt < 2; mt++)
                        mma16816(acc[mt][ntp * 2 + half], aH[mt],
                                 bh[ntp][half], bh[ntp][2 + half]);

            // ---- pass 2: hi*lo ----
#pragma unroll
            for (int ntp = 0; ntp < 4; ntp++) {
                uint32_t bl[4];
                ldsm_x4(bl, bBaseL + bOffBase + (uint32_t)(ntp * 16 * BKP) * 4 + kbyte);
#pragma unroll
                for (int half = 0; half < 2; half++)
#pragma unroll
                    for (int mt = 0; mt < 2; mt++)
                        mma16816(acc[mt][ntp * 2 + half], aH[mt],
                                 bl[half], bl[2 + half]);
            }

            // ---- pass 3: lo*hi ----
#pragma unroll
            for (int ntp = 0; ntp < 4; ntp++)
#pragma unroll
                for (int half = 0; half < 2; half++)
#pragma unroll
                    for (int mt = 0; mt < 2; mt++)
                        mma16816(acc[mt][ntp * 2 + half], aL[mt],
                                 bh[ntp][half], bh[ntp][2 + half]);
        }
        __syncthreads();
    }

    // ---- epilogue (same mapping as rounds 4-6) ----
#pragma unroll
    for (int mt = 0; mt < 2; mt++) {
        const int r0 = brow + wm + mt * 16 + lg;
#pragma unroll
        for (int nt = 0; nt < 8; nt++) {
            const int c0 = bcol + wn + nt * 8 + lq * 2;
            float* p0 = C + (long)r0 * ldc;
            float* p1 = C + (long)(r0 + 8) * ldc;
            const float b0 = bias ? bias[min(c0, N - 1)] : 0.f;
            const float b1 = bias ? bias[min(c0 + 1, N - 1)] : 0.f;
            if (c0 < N) {
                p0[c0] = alpha * acc[mt][nt][0] + b0;
                p1[c0] = alpha * acc[mt][nt][2] + b0;
            }
            if (c0 + 1 < N) {
                p0[c0 + 1] = alpha * acc[mt][nt][1] + b1;
                p1[c0 + 1] = alpha * acc[mt][nt][3] + b1;
            }
        }
    }
}

// ---------------------------------------------------------------------------
// fp32 -> bf16 hi/lo split (elementwise)
// ---------------------------------------------------------------------------
__global__ void split_f32(const float* __restrict__ in,
                          uint16_t* __restrict__ hi, uint16_t* __restrict__ lo,
                          long n)
{
    const long i = (long)blockIdx.x * blockDim.x + threadIdx.x;
    if (i < n) {
        uint16_t h, l;
        split1(in[i], h, l);
        hi[i] = h;
        lo[i] = l;
    }
}

// ---------------------------------------------------------------------------
// Rotary + relayout, writing bf16 hi/lo
// ---------------------------------------------------------------------------
__global__ void rotary_relayout(const float* __restrict__ qkv,
                                const float* __restrict__ rope,
                                uint16_t* __restrict__ Qh, uint16_t* __restrict__ Ql,
                                uint16_t* __restrict__ Kh, uint16_t* __restrict__ Kl,
                                uint16_t* __restrict__ Vth, uint16_t* __restrict__ Vtl)
{
    const int s = blockIdx.x;
    const float* row = qkv + (long)s * QKV_F;

    for (int e = threadIdx.x; e < EMBED; e += blockDim.x) {
        const int h = e / HDIM;
        const int d = e % HDIM;
        const float f = rope[s * (HDIM / 2) + ((d < HDIM / 2) ? d : d - HDIM / 2)];
        float sn, cs;
        sincosf(f, &sn, &cs);

        const float qv = row[e];
        const float kv = row[EMBED + e];
        const float qp = (d < HDIM / 2) ? -row[e + HDIM / 2] : row[e - HDIM / 2];
        const float kp = (d < HDIM / 2) ? -row[EMBED + e + HDIM / 2]
                                        :  row[EMBED + e - HDIM / 2];

        const float qr = qv * cs + qp * sn;
        const float kr = kv * cs + kp * sn;

        const long oq = ((long)h * S_TOTAL + s) * HDIMP + d;
        uint16_t hh, ll;
        split1(qr, hh, ll);  Qh[oq] = hh;  Ql[oq] = ll;
        split1(kr, hh, ll);  Kh[oq] = hh;  Kl[oq] = ll;

        const long ov = ((long)h * HDIM + d) * S_TOTAL + s;
        split1(row[2 * EMBED + e], hh, ll);  Vth[ov] = hh;  Vtl[ov] = ll;
    }
}

// ---------------------------------------------------------------------------
// Row softmax over 1024 cols; one warp per row; outputs bf16 hi/lo probs.
// ---------------------------------------------------------------------------
__global__ void softmax_rows(const float* __restrict__ S,
                             uint16_t* __restrict__ Ph, uint16_t* __restrict__ Pl)
{
    const long row  = (long)blockIdx.x * 8 + (threadIdx.x >> 5);
    const int  lane = threadIdx.x & 31;
    const float* p = S + row * SEG_LEN;

    float v[32];
    float mx = -INFINITY;
#pragma unroll
    for (int i = 0; i < 32; i++) {
        v[i] = p[lane + i * 32];
        mx = fmaxf(mx, v[i]);
    }
#pragma unroll
    for (int o = 16; o; o >>= 1) mx = fmaxf(mx, __shfl_xor_sync(0xffffffffu, mx, o));

    float sum = 0.f;
#pragma unroll
    for (int i = 0; i < 32; i++) {
        v[i] = __expf(v[i] - mx);
        sum += v[i];
    }
#pragma unroll
    for (int o = 16; o; o >>= 1) sum += __shfl_xor_sync(0xffffffffu, sum, o);

    const float r = 1.f / sum;
    uint16_t* ph = Ph + row * SEG_LEN;
    uint16_t* pl = Pl + row * SEG_LEN;
#pragma unroll
    for (int i = 0; i < 32; i++) {
        uint16_t hh, ll;
        split1(v[i] * r, hh, ll);
        ph[lane + i * 32] = hh;
        pl[lane + i * 32] = ll;
    }
}

// ---------------------------------------------------------------------------
// Launch helper
// ---------------------------------------------------------------------------
static void launch_gemm(const uint16_t* Ah, const uint16_t* Al,
                        const uint16_t* Bh, const uint16_t* Bl,
                        const float* bias, float* C,
                        int M, int N, int K, int lda, int ldb, int ldc,
                        long oAs, long oAh_, long oBs, long oBh_,
                        long oCs, long oCh_, int nbatch, int nh, float alpha)
{
    dim3 grid((N + BN - 1) / BN, M / BM, nbatch);
    gemm_bf16x3<<<grid, 256, SMEM_BYTES>>>(Ah, Al, Bh, Bl, bias, C,
                                           N, K, lda, ldb, ldc,
                                           oAs, oAh_, oBs, oBh_, oCs, oCh_,
                                           nh, alpha);
}

// ---------------------------------------------------------------------------
// Entry point
// ---------------------------------------------------------------------------
extern "C" void kernel_launch(void* const* d_in, const int* in_sizes, int n_in,
                              void* d_out, int out_size)
{
    const float* x      = (const float*)d_in[0];
    const float* qkv_w  = (const float*)d_in[1];
    const float* qkv_b  = (const float*)d_in[2];
    const float* proj_w = (const float*)d_in[3];
    const float* proj_b = (const float*)d_in[4];
    const float* rope   = (const float*)d_in[5];
    float* out = (float*)d_out;

    cudaFuncSetAttribute(gemm_bf16x3,
                         cudaFuncAttributeMaxDynamicSharedMemorySize, SMEM_BYTES);

    float *qkv, *scores, *ctx;
    uint16_t *xh, *xl, *wh, *wl, *pwh, *pwl;
    uint16_t *Qh, *Ql, *Kh, *Kl, *Vth, *Vtl, *Ph, *Pl, *ch, *cl;
    cudaGetSymbolAddress((void**)&qkv,    g_qkv);
    cudaGetSymbolAddress((void**)&scores, g_scores);
    cudaGetSymbolAddress((void**)&ctx,    g_ctx);
    cudaGetSymbolAddress((void**)&xh,  g_xh);   cudaGetSymbolAddress((void**)&xl,  g_xl);
    cudaGetSymbolAddress((void**)&wh,  g_wh);   cudaGetSymbolAddress((void**)&wl,  g_wl);
    cudaGetSymbolAddress((void**)&pwh, g_pwh);  cudaGetSymbolAddress((void**)&pwl, g_pwl);
    cudaGetSymbolAddress((void**)&Qh,  g_Qh);   cudaGetSymbolAddress((void**)&Ql,  g_Ql);
    cudaGetSymbolAddress((void**)&Kh,  g_Kh);   cudaGetSymbolAddress((void**)&Kl,  g_Kl);
    cudaGetSymbolAddress((void**)&Vth, g_Vth);  cudaGetSymbolAddress((void**)&Vtl, g_Vtl);
    cudaGetSymbolAddress((void**)&Ph,  g_Ph);   cudaGetSymbolAddress((void**)&Pl,  g_Pl);
    cudaGetSymbolAddress((void**)&ch,  g_ch);   cudaGetSymbolAddress((void**)&cl,  g_cl);

    // 0) split inputs/weights to bf16 hi/lo
    {
        long n1 = (long)S_TOTAL * EMBED;
        long n2 = (long)QKV_F * EMBED;
        long n3 = (long)EMBED * EMBED;
        split_f32<<<(unsigned)((n1 + 255) / 256), 256>>>(x, xh, xl, n1);
        split_f32<<<(unsigned)((n2 + 255) / 256), 256>>>(qkv_w, wh, wl, n2);
        split_f32<<<(unsigned)((n3 + 255) / 256), 256>>>(proj_w, pwh, pwl, n3);
    }

    // 1) QKV GEMM: qkv[4096,3840] = x @ qkv_w^T + qkv_b
    launch_gemm(xh, xl, wh, wl, qkv_b, qkv,
                S_TOTAL, QKV_F, EMBED, EMBED, EMBED, QKV_F,
                0, 0, 0, 0, 0, 0, 1, 1, 1.0f);

    // 2) rotary + relayout -> bf16 hi/lo Q,K (K-dim padded to 96), Vt
    rotary_relayout<<<S_TOTAL, 256>>>(qkv, rope, Qh, Ql, Kh, Kl, Vth, Vtl);

    // 3) scores = scale * Q @ K^T   (64 batches of 1024x1024x96)
    const float scale = 0.11180339887498949f; // 1/sqrt(80)
    launch_gemm(Qh, Ql, Kh, Kl, nullptr, scores,
                SEG_LEN, SEG_LEN, HDIMP, HDIMP, HDIMP, SEG_LEN,
                (long)SEG_LEN * HDIMP, (long)S_TOTAL * HDIMP,
                (long)SEG_LEN * HDIMP, (long)S_TOTAL * HDIMP,
                (long)HEADS * SEG_LEN * SEG_LEN, (long)SEG_LEN * SEG_LEN,
                NSEG * HEADS, HEADS, scale);

    // 4) softmax -> bf16 hi/lo probs
    softmax_rows<<<(NSEG * HEADS * SEG_LEN) / 8, 256>>>(scores, Ph, Pl);

    // 5) ctx = P @ Vt^T   (N=80 ragged, zero-filled)
    launch_gemm(Ph, Pl, Vth, Vtl, nullptr, ctx,
                SEG_LEN, HDIM, SEG_LEN, SEG_LEN, S_TOTAL, EMBED,
                (long)HEADS * SEG_LEN * SEG_LEN, (long)SEG_LEN * SEG_LEN,
                (long)SEG_LEN, (long)HDIM * S_TOTAL,
                (long)SEG_LEN * EMBED, (long)HDIM,
                NSEG * HEADS, HEADS, 1.0f);

    // 6) split ctx, then out = ctx @ proj_w^T + proj_b
    {
        long n = (long)S_TOTAL * EMBED;
        split_f32<<<(unsigned)((n + 255) / 256), 256>>>(ctx, ch, cl, n);
    }
    launch_gemm(ch, cl, pwh, pwl, proj_b, out,
                S_TOTAL, EMBED, EMBED, EMBED, EMBED, EMBED,
                0, 0, 0, 0, 0, 0, 1, 1, 1.0f);
}

// round 9
// speedup vs baseline: 1.3231x; 1.3231x over previous
#include <cuda_runtime.h>
#include <cuda_bf16.h>
#include <cuda_fp16.h>
#include <stdint.h>
#include <stddef.h>
#include <math.h>

// Round 9: tcgen05 is toolchain-blocked (harness compiles PTX at compute_100,
// no 'a' features). Legacy mma.sync rate is fixed -> cut mma COUNT instead:
// precision-critical path (x->QK, scores) keeps bf16x3; the V->ctx->proj path
// (no softmax downstream) drops to single-pass fp16 mma (3x fewer mmas).

// ---------------------------------------------------------------------------
// Problem constants
// ---------------------------------------------------------------------------
#define EMBED   1280
#define HEADS   16
#define HDIM    80
#define HDIMP   96            // HDIM padded to multiple of BK (zero tail)
#define S_TOTAL 4096
#define NSEG    4
#define SEG_LEN 1024
#define QKV_F   (3 * EMBED)   // 3840
#define QK_F    (2 * EMBED)   // 2560

// ---------------------------------------------------------------------------
// Scratch (device globals; zero-initialized -> pads stay 0)
// ---------------------------------------------------------------------------
__device__ float    g_qkv[(size_t)S_TOTAL * QKV_F];
__device__ float    g_scores[(size_t)NSEG * HEADS * SEG_LEN * SEG_LEN];
__device__ float    g_ctx[(size_t)S_TOTAL * EMBED];

__device__ uint16_t g_xh[(size_t)S_TOTAL * EMBED], g_xl[(size_t)S_TOTAL * EMBED];
__device__ uint16_t g_xf[(size_t)S_TOTAL * EMBED];                       // fp16
__device__ uint16_t g_wh[(size_t)QK_F * EMBED],  g_wl[(size_t)QK_F * EMBED];
__device__ uint16_t g_wvf[(size_t)EMBED * EMBED];                        // fp16
__device__ uint16_t g_pwf[(size_t)EMBED * EMBED];                        // fp16
__device__ uint16_t g_Qh[(size_t)HEADS * S_TOTAL * HDIMP], g_Ql[(size_t)HEADS * S_TOTAL * HDIMP];
__device__ uint16_t g_Kh[(size_t)HEADS * S_TOTAL * HDIMP], g_Kl[(size_t)HEADS * S_TOTAL * HDIMP];
__device__ uint16_t g_Vtf[(size_t)HEADS * HDIM * S_TOTAL];               // fp16
__device__ uint16_t g_Pf[(size_t)NSEG * HEADS * SEG_LEN * SEG_LEN];      // fp16
__device__ uint16_t g_cf[(size_t)S_TOTAL * EMBED];                       // fp16

// ---------------------------------------------------------------------------
// helpers
// ---------------------------------------------------------------------------
__device__ __forceinline__ uint16_t bf_bits(__nv_bfloat16 h)
{
    return *reinterpret_cast<uint16_t*>(&h);
}

__device__ __forceinline__ void split1(float x, uint16_t& hi, uint16_t& lo)
{
    __nv_bfloat16 h = __float2bfloat16(x);
    float r = x - __bfloat162float(h);
    hi = bf_bits(h);
    lo = bf_bits(__float2bfloat16(r));
}

__device__ __forceinline__ uint16_t f2h(float x)
{
    __half h = __float2half_rn(x);
    return *reinterpret_cast<uint16_t*>(&h);
}

__device__ __forceinline__ void mma_bf16(float* c, const uint32_t* a,
                                         uint32_t b0, uint32_t b1)
{
    asm volatile(
        "mma.sync.aligned.m16n8k16.row.col.f32.bf16.bf16.f32 "
        "{%0,%1,%2,%3}, {%4,%5,%6,%7}, {%8,%9}, {%0,%1,%2,%3};"
        : "+f"(c[0]), "+f"(c[1]), "+f"(c[2]), "+f"(c[3])
        : "r"(a[0]), "r"(a[1]), "r"(a[2]), "r"(a[3]), "r"(b0), "r"(b1));
}

__device__ __forceinline__ void mma_fp16(float* c, const uint32_t* a,
                                         uint32_t b0, uint32_t b1)
{
    asm volatile(
        "mma.sync.aligned.m16n8k16.row.col.f32.f16.f16.f32 "
        "{%0,%1,%2,%3}, {%4,%5,%6,%7}, {%8,%9}, {%0,%1,%2,%3};"
        : "+f"(c[0]), "+f"(c[1]), "+f"(c[2]), "+f"(c[3])
        : "r"(a[0]), "r"(a[1]), "r"(a[2]), "r"(a[3]), "r"(b0), "r"(b1));
}

__device__ __forceinline__ void ldsm_x4(uint32_t* r, uint32_t addr)
{
    asm volatile("ldmatrix.sync.aligned.m8n8.x4.shared.b16 {%0,%1,%2,%3}, [%4];"
                 : "=r"(r[0]), "=r"(r[1]), "=r"(r[2]), "=r"(r[3]) : "r"(addr));
}

__device__ __forceinline__ void cp_async16(uint32_t dst_smem, const void* src)
{
    asm volatile("cp.async.cg.shared.global [%0], [%1], 16;"
                 :: "r"(dst_smem), "l"(src));
}
__device__ __forceinline__ void cp_async16z(uint32_t dst_smem, const void* src, int src_bytes)
{
    asm volatile("cp.async.cg.shared.global [%0], [%1], 16, %2;"
                 :: "r"(dst_smem), "l"(src), "r"(src_bytes));
}
__device__ __forceinline__ void cp_commit()
{
    asm volatile("cp.async.commit_group;");
}
template <int N>
__device__ __forceinline__ void cp_wait()
{
    asm volatile("cp.async.wait_group %0;" :: "n"(N));
}

// ---------------------------------------------------------------------------
// Shared tiling constants (both GEMMs)
// ---------------------------------------------------------------------------
#define BM 128
#define BN 128
#define BK 32
#define BKP 20                    // u32 per smem row (16 used + 4 pad)
#define SUB (128 * BKP)           // u32 per sub-array (10240 B)
#define STG3 (4 * SUB)            // bf16x3 stage: AH AL BH BL
#define SMEM3_BYTES (2 * STG3 * 4)  // 81920
#define STG1 (2 * SUB)            // fp16 stage: A B
#define SMEM1_BYTES (2 * STG1 * 4)  // 40960

// ---------------------------------------------------------------------------
// bf16x3 batched GEMM (identical to round 7): C = alpha*(A@B^T)+bias
// ---------------------------------------------------------------------------
__global__ __launch_bounds__(256, 2)
void gemm_bf16x3(const uint16_t* __restrict__ Ah, const uint16_t* __restrict__ Al,
                 const uint16_t* __restrict__ Bh, const uint16_t* __restrict__ Bl,
                 const float* __restrict__ bias, float* __restrict__ C,
                 int N, int K, int lda, int ldb, int ldc,
                 long oAs, long oAh_, long oBs, long oBh_, long oCs, long oCh_,
                 int nh, float alpha)
{
    extern __shared__ uint32_t sm[];

    const int z   = blockIdx.z;
    const int seg = z / nh;
    const int h   = z % nh;
    Ah += oAs * seg + oAh_ * h;  Al += oAs * seg + oAh_ * h;
    Bh += oBs * seg + oBh_ * h;  Bl += oBs * seg + oBh_ * h;
    C  += oCs * seg + oCh_ * h;

    const int brow = blockIdx.y * BM;
    const int bcol = blockIdx.x * BN;

    const int tid  = threadIdx.x;
    const int warp = tid >> 5;
    const int lane = tid & 31;
    const int wm = (warp >> 1) * 32;
    const int wn = (warp & 1) * 64;
    const int lg = lane >> 2;
    const int lq = lane & 3;

    const uint32_t smem_base = (uint32_t)__cvta_generic_to_shared(sm);
    const int lm_r = lane & 15;
    const int lm_c = (lane >> 4) * 4;
    const int lrow = tid >> 1;
    const int lq4  = (tid & 1) ? 0 : 0; (void)lq4;
    const int lrow2 = tid >> 2;
    const int lc4  = (tid & 3) * 4;
    const int lk8  = (tid & 3) * 8;

    float acc[2][8][4];
#pragma unroll
    for (int i = 0; i < 2; i++)
#pragma unroll
        for (int j = 0; j < 8; j++)
#pragma unroll
            for (int q = 0; q < 4; q++) acc[i][j][q] = 0.f;

    const int nit = K / BK;

    auto load_stage = [&](int stage, int k0) {
        const uint32_t sb = smem_base + (uint32_t)stage * STG3 * 4;
#pragma unroll
        for (int r2 = 0; r2 < 2; r2++) {
            const int row = lrow2 + r2 * 64;
            const uint32_t doff = (uint32_t)(row * BKP + lc4) * 4;
            cp_async16(sb + 0 * SUB * 4 + doff,
                       Ah + (long)(brow + row) * lda + k0 + lk8);
            cp_async16(sb + 1 * SUB * 4 + doff,
                       Al + (long)(brow + row) * lda + k0 + lk8);
            const int bn  = bcol + row;
            const int ok  = (bn < N) ? 16 : 0;
            const int bno = (bn < N) ? bn : 0;
            cp_async16z(sb + 2 * SUB * 4 + doff,
                        Bh + (long)bno * ldb + k0 + lk8, ok);
            cp_async16z(sb + 3 * SUB * 4 + doff,
                        Bl + (long)bno * ldb + k0 + lk8, ok);
        }
    };

    load_stage(0, 0);
    cp_commit();

    const uint32_t aOff0 = (uint32_t)((wm + lm_r) * BKP + lm_c) * 4;
    const uint32_t aOff1 = (uint32_t)((wm + 16 + lm_r) * BKP + lm_c) * 4;
    const uint32_t bOffBase = (uint32_t)((wn + lm_r) * BKP + lm_c) * 4;

    for (int it = 0; it < nit; it++) {
        if (it + 1 < nit) {
            load_stage((it + 1) & 1, (it + 1) * BK);
            cp_commit();
            cp_wait<1>();
        } else {
            cp_wait<0>();
        }
        __syncthreads();

        const uint32_t stageB = smem_base + (uint32_t)(it & 1) * STG3 * 4;
        const uint32_t aBaseH = stageB;
        const uint32_t aBaseL = stageB + SUB * 4;
        const uint32_t bBaseH = stageB + 2 * SUB * 4;
        const uint32_t bBaseL = stageB + 3 * SUB * 4;

#pragma unroll
        for (int kc = 0; kc < 2; kc++) {
            const uint32_t kbyte = (uint32_t)(kc * 8) * 4;

            uint32_t aH[2][4], aL[2][4];
            ldsm_x4(aH[0], aBaseH + aOff0 + kbyte);
            ldsm_x4(aH[1], aBaseH + aOff1 + kbyte);
            ldsm_x4(aL[0], aBaseL + aOff0 + kbyte);
            ldsm_x4(aL[1], aBaseL + aOff1 + kbyte);

            uint32_t bh[4][4];
#pragma unroll
            for (int ntp = 0; ntp < 4; ntp++)
                ldsm_x4(bh[ntp], bBaseH + bOffBase + (uint32_t)(ntp * 16 * BKP) * 4 + kbyte);

#pragma unroll
            for (int ntp = 0; ntp < 4; ntp++)
#pragma unroll
                for (int half = 0; half < 2; half++)
#pragma unroll
                    for (int mt = 0; mt < 2; mt++)
                        mma_bf16(acc[mt][ntp * 2 + half], aH[mt],
                                 bh[ntp][half], bh[ntp][2 + half]);

#pragma unroll
            for (int ntp = 0; ntp < 4; ntp++) {
                uint32_t bl[4];
                ldsm_x4(bl, bBaseL + bOffBase + (uint32_t)(ntp * 16 * BKP) * 4 + kbyte);
#pragma unroll
                for (int half = 0; half < 2; half++)
#pragma unroll
                    for (int mt = 0; mt < 2; mt++)
                        mma_bf16(acc[mt][ntp * 2 + half], aH[mt],
                                 bl[half], bl[2 + half]);
            }

#pragma unroll
            for (int ntp = 0; ntp < 4; ntp++)
#pragma unroll
                for (int half = 0; half < 2; half++)
#pragma unroll
                    for (int mt = 0; mt < 2; mt++)
                        mma_bf16(acc[mt][ntp * 2 + half], aL[mt],
                                 bh[ntp][half], bh[ntp][2 + half]);
        }
        __syncthreads();
    }

#pragma unroll
    for (int mt = 0; mt < 2; mt++) {
        const int r0 = brow + wm + mt * 16 + lg;
#pragma unroll
        for (int nt = 0; nt < 8; nt++) {
            const int c0 = bcol + wn + nt * 8 + lq * 2;
            float* p0 = C + (long)r0 * ldc;
            float* p1 = C + (long)(r0 + 8) * ldc;
            const float b0 = bias ? bias[min(c0, N - 1)] : 0.f;
            const float b1 = bias ? bias[min(c0 + 1, N - 1)] : 0.f;
            if (c0 < N) {
                p0[c0] = alpha * acc[mt][nt][0] + b0;
                p1[c0] = alpha * acc[mt][nt][2] + b0;
            }
            if (c0 + 1 < N) {
                p0[c0 + 1] = alpha * acc[mt][nt][1] + b1;
                p1[c0 + 1] = alpha * acc[mt][nt][3] + b1;
            }
        }
    }
}

// ---------------------------------------------------------------------------
// fp16 single-pass batched GEMM: C = alpha*(A@B^T)+bias   (same structure)
// ---------------------------------------------------------------------------
__global__ __launch_bounds__(256, 2)
void gemm_fp16(const uint16_t* __restrict__ Af, const uint16_t* __restrict__ Bf,
               const float* __restrict__ bias, float* __restrict__ C,
               int N, int K, int lda, int ldb, int ldc,
               long oAs, long oAh_, long oBs, long oBh_, long oCs, long oCh_,
               int nh, float alpha)
{
    extern __shared__ uint32_t sm[];

    const int z   = blockIdx.z;
    const int seg = z / nh;
    const int h   = z % nh;
    Af += oAs * seg + oAh_ * h;
    Bf += oBs * seg + oBh_ * h;
    C  += oCs * seg + oCh_ * h;

    const int brow = blockIdx.y * BM;
    const int bcol = blockIdx.x * BN;

    const int tid  = threadIdx.x;
    const int warp = tid >> 5;
    const int lane = tid & 31;
    const int wm = (warp >> 1) * 32;
    const int wn = (warp & 1) * 64;
    const int lg = lane >> 2;
    const int lq = lane & 3;

    const uint32_t smem_base = (uint32_t)__cvta_generic_to_shared(sm);
    const int lm_r = lane & 15;
    const int lm_c = (lane >> 4) * 4;
    const int lrow2 = tid >> 2;
    const int lc4  = (tid & 3) * 4;
    const int lk8  = (tid & 3) * 8;

    float acc[2][8][4];
#pragma unroll
    for (int i = 0; i < 2; i++)
#pragma unroll
        for (int j = 0; j < 8; j++)
#pragma unroll
            for (int q = 0; q < 4; q++) acc[i][j][q] = 0.f;

    const int nit = K / BK;

    auto load_stage = [&](int stage, int k0) {
        const uint32_t sb = smem_base + (uint32_t)stage * STG1 * 4;
#pragma unroll
        for (int r2 = 0; r2 < 2; r2++) {
            const int row = lrow2 + r2 * 64;
            const uint32_t doff = (uint32_t)(row * BKP + lc4) * 4;
            cp_async16(sb + 0 * SUB * 4 + doff,
                       Af + (long)(brow + row) * lda + k0 + lk8);
            const int bn  = bcol + row;
            const int ok  = (bn < N) ? 16 : 0;
            const int bno = (bn < N) ? bn : 0;
            cp_async16z(sb + 1 * SUB * 4 + doff,
                        Bf + (long)bno * ldb + k0 + lk8, ok);
        }
    };

    load_stage(0, 0);
    cp_commit();

    const uint32_t aOff0 = (uint32_t)((wm + lm_r) * BKP + lm_c) * 4;
    const uint32_t aOff1 = (uint32_t)((wm + 16 + lm_r) * BKP + lm_c) * 4;
    const uint32_t bOffBase = (uint32_t)((wn + lm_r) * BKP + lm_c) * 4;

    for (int it = 0; it < nit; it++) {
        if (it + 1 < nit) {
            load_stage((it + 1) & 1, (it + 1) * BK);
            cp_commit();
            cp_wait<1>();
        } else {
            cp_wait<0>();
        }
        __syncthreads();

        const uint32_t stageB = smem_base + (uint32_t)(it & 1) * STG1 * 4;
        const uint32_t aBase = stageB;
        const uint32_t bBase = stageB + SUB * 4;

#pragma unroll
        for (int kc = 0; kc < 2; kc++) {
            const uint32_t kbyte = (uint32_t)(kc * 8) * 4;

            uint32_t a[2][4];
            ldsm_x4(a[0], aBase + aOff0 + kbyte);
            ldsm_x4(a[1], aBase + aOff1 + kbyte);

#pragma unroll
            for (int ntp = 0; ntp < 4; ntp++) {
                uint32_t b[4];
                ldsm_x4(b, bBase + bOffBase + (uint32_t)(ntp * 16 * BKP) * 4 + kbyte);
#pragma unroll
                for (int half = 0; half < 2; half++)
#pragma unroll
                    for (int mt = 0; mt < 2; mt++)
                        mma_fp16(acc[mt][ntp * 2 + half], a[mt],
                                 b[half], b[2 + half]);
            }
        }
        __syncthreads();
    }

#pragma unroll
    for (int mt = 0; mt < 2; mt++) {
        const int r0 = brow + wm + mt * 16 + lg;
#pragma unroll
        for (int nt = 0; nt < 8; nt++) {
            const int c0 = bcol + wn + nt * 8 + lq * 2;
            float* p0 = C + (long)r0 * ldc;
            float* p1 = C + (long)(r0 + 8) * ldc;
            const float b0 = bias ? bias[min(c0, N - 1)] : 0.f;
            const float b1 = bias ? bias[min(c0 + 1, N - 1)] : 0.f;
            if (c0 < N) {
                p0[c0] = alpha * acc[mt][nt][0] + b0;
                p1[c0] = alpha * acc[mt][nt][2] + b0;
            }
            if (c0 + 1 < N) {
                p0[c0 + 1] = alpha * acc[mt][nt][1] + b1;
                p1[c0 + 1] = alpha * acc[mt][nt][3] + b1;
            }
        }
    }
}

// ---------------------------------------------------------------------------
// elementwise conversions
// ---------------------------------------------------------------------------
__global__ void split_f32(const float* __restrict__ in,
                          uint16_t* __restrict__ hi, uint16_t* __restrict__ lo,
                          long n)
{
    const long i = (long)blockIdx.x * blockDim.x + threadIdx.x;
    if (i < n) {
        uint16_t h, l;
        split1(in[i], h, l);
        hi[i] = h;
        lo[i] = l;
    }
}

__global__ void f32_to_f16(const float* __restrict__ in,
                           uint16_t* __restrict__ out, long n)
{
    const long i = (long)blockIdx.x * blockDim.x + threadIdx.x;
    if (i < n) out[i] = f2h(in[i]);
}

// ---------------------------------------------------------------------------
// Rotary + relayout: Q,K -> bf16 hi/lo [h][s][HDIMP], V -> fp16 [h][d][s]
// ---------------------------------------------------------------------------
__global__ void rotary_relayout(const float* __restrict__ qkv,
                                const float* __restrict__ rope,
                                uint16_t* __restrict__ Qh, uint16_t* __restrict__ Ql,
                                uint16_t* __restrict__ Kh, uint16_t* __restrict__ Kl,
                                uint16_t* __restrict__ Vtf)
{
    const int s = blockIdx.x;
    const float* row = qkv + (long)s * QKV_F;

    for (int e = threadIdx.x; e < EMBED; e += blockDim.x) {
        const int h = e / HDIM;
        const int d = e % HDIM;
        const float f = rope[s * (HDIM / 2) + ((d < HDIM / 2) ? d : d - HDIM / 2)];
        float sn, cs;
        sincosf(f, &sn, &cs);

        const float qv = row[e];
        const float kv = row[EMBED + e];
        const float qp = (d < HDIM / 2) ? -row[e + HDIM / 2] : row[e - HDIM / 2];
        const float kp = (d < HDIM / 2) ? -row[EMBED + e + HDIM / 2]
                                        :  row[EMBED + e - HDIM / 2];

        const float qr = qv * cs + qp * sn;
        const float kr = kv * cs + kp * sn;

        const long oq = ((long)h * S_TOTAL + s) * HDIMP + d;
        uint16_t hh, ll;
        split1(qr, hh, ll);  Qh[oq] = hh;  Ql[oq] = ll;
        split1(kr, hh, ll);  Kh[oq] = hh;  Kl[oq] = ll;

        Vtf[((long)h * HDIM + d) * S_TOTAL + s] = f2h(row[2 * EMBED + e]);
    }
}

// ---------------------------------------------------------------------------
// Row softmax over 1024 cols; one warp per row; outputs fp16 probs.
// ---------------------------------------------------------------------------
__global__ void softmax_rows(const float* __restrict__ S,
                             uint16_t* __restrict__ Pf)
{
    const long row  = (long)blockIdx.x * 8 + (threadIdx.x >> 5);
    const int  lane = threadIdx.x & 31;
    const float* p = S + row * SEG_LEN;

    float v[32];
    float mx = -INFINITY;
#pragma unroll
    for (int i = 0; i < 32; i++) {
        v[i] = p[lane + i * 32];
        mx = fmaxf(mx, v[i]);
    }
#pragma unroll
    for (int o = 16; o; o >>= 1) mx = fmaxf(mx, __shfl_xor_sync(0xffffffffu, mx, o));

    float sum = 0.f;
#pragma unroll
    for (int i = 0; i < 32; i++) {
        v[i] = __expf(v[i] - mx);
        sum += v[i];
    }
#pragma unroll
    for (int o = 16; o; o >>= 1) sum += __shfl_xor_sync(0xffffffffu, sum, o);

    const float r = 1.f / sum;
    uint16_t* ph = Pf + row * SEG_LEN;
#pragma unroll
    for (int i = 0; i < 32; i++)
        ph[lane + i * 32] = f2h(v[i] * r);
}

// ---------------------------------------------------------------------------
// Launch helpers
// ---------------------------------------------------------------------------
static void launch_g3(const uint16_t* Ah, const uint16_t* Al,
                      const uint16_t* Bh, const uint16_t* Bl,
                      const float* bias, float* C,
                      int M, int N, int K, int lda, int ldb, int ldc,
                      long oAs, long oAh_, long oBs, long oBh_,
                      long oCs, long oCh_, int nbatch, int nh, float alpha)
{
    dim3 grid((N + BN - 1) / BN, M / BM, nbatch);
    gemm_bf16x3<<<grid, 256, SMEM3_BYTES>>>(Ah, Al, Bh, Bl, bias, C,
                                            N, K, lda, ldb, ldc,
                                            oAs, oAh_, oBs, oBh_, oCs, oCh_,
                                            nh, alpha);
}

static void launch_g1(const uint16_t* Af, const uint16_t* Bf,
                      const float* bias, float* C,
                      int M, int N, int K, int lda, int ldb, int ldc,
                      long oAs, long oAh_, long oBs, long oBh_,
                      long oCs, long oCh_, int nbatch, int nh, float alpha)
{
    dim3 grid((N + BN - 1) / BN, M / BM, nbatch);
    gemm_fp16<<<grid, 256, SMEM1_BYTES>>>(Af, Bf, bias, C,
                                          N, K, lda, ldb, ldc,
                                          oAs, oAh_, oBs, oBh_, oCs, oCh_,
                                          nh, alpha);
}

// ---------------------------------------------------------------------------
// Entry point
// ---------------------------------------------------------------------------
extern "C" void kernel_launch(void* const* d_in, const int* in_sizes, int n_in,
                              void* d_out, int out_size)
{
    const float* x      = (const float*)d_in[0];
    const float* qkv_w  = (const float*)d_in[1];
    const float* qkv_b  = (const float*)d_in[2];
    const float* proj_w = (const float*)d_in[3];
    const float* proj_b = (const float*)d_in[4];
    const float* rope   = (const float*)d_in[5];
    float* out = (float*)d_out;

    cudaFuncSetAttribute(gemm_bf16x3,
                         cudaFuncAttributeMaxDynamicSharedMemorySize, SMEM3_BYTES);
    cudaFuncSetAttribute(gemm_fp16,
                         cudaFuncAttributeMaxDynamicSharedMemorySize, SMEM1_BYTES);

    float *qkv, *scores, *ctx;
    uint16_t *xh, *xl, *xf, *wh, *wl, *wvf, *pwf;
    uint16_t *Qh, *Ql, *Kh, *Kl, *Vtf, *Pf, *cf;
    cudaGetSymbolAddress((void**)&qkv,    g_qkv);
    cudaGetSymbolAddress((void**)&scores, g_scores);
    cudaGetSymbolAddress((void**)&ctx,    g_ctx);
    cudaGetSymbolAddress((void**)&xh,  g_xh);   cudaGetSymbolAddress((void**)&xl,  g_xl);
    cudaGetSymbolAddress((void**)&xf,  g_xf);
    cudaGetSymbolAddress((void**)&wh,  g_wh);   cudaGetSymbolAddress((void**)&wl,  g_wl);
    cudaGetSymbolAddress((void**)&wvf, g_wvf);  cudaGetSymbolAddress((void**)&pwf, g_pwf);
    cudaGetSymbolAddress((void**)&Qh,  g_Qh);   cudaGetSymbolAddress((void**)&Ql,  g_Ql);
    cudaGetSymbolAddress((void**)&Kh,  g_Kh);   cudaGetSymbolAddress((void**)&Kl,  g_Kl);
    cudaGetSymbolAddress((void**)&Vtf, g_Vtf);
    cudaGetSymbolAddress((void**)&Pf,  g_Pf);
    cudaGetSymbolAddress((void**)&cf,  g_cf);

    // 0) conversions
    {
        long n1 = (long)S_TOTAL * EMBED;
        long n2 = (long)QK_F * EMBED;          // QK rows of qkv_w (first 2560)
        long n3 = (long)EMBED * EMBED;
        split_f32<<<(unsigned)((n1 + 255) / 256), 256>>>(x, xh, xl, n1);
        f32_to_f16<<<(unsigned)((n1 + 255) / 256), 256>>>(x, xf, n1);
        split_f32<<<(unsigned)((n2 + 255) / 256), 256>>>(qkv_w, wh, wl, n2);
        f32_to_f16<<<(unsigned)((n3 + 255) / 256), 256>>>(qkv_w + n2, wvf, n3);
        f32_to_f16<<<(unsigned)((n3 + 255) / 256), 256>>>(proj_w, pwf, n3);
    }

    // 1a) QK part of QKV (bf16x3): qkv[:, 0:2560]
    launch_g3(xh, xl, wh, wl, qkv_b, qkv,
              S_TOTAL, QK_F, EMBED, EMBED, EMBED, QKV_F,
              0, 0, 0, 0, 0, 0, 1, 1, 1.0f);

    // 1b) V part of QKV (fp16 x1): qkv[:, 2560:3840]
    launch_g1(xf, wvf, qkv_b + QK_F, qkv + QK_F,
              S_TOTAL, EMBED, EMBED, EMBED, EMBED, QKV_F,
              0, 0, 0, 0, 0, 0, 1, 1, 1.0f);

    // 2) rotary + relayout
    rotary_relayout<<<S_TOTAL, 256>>>(qkv, rope, Qh, Ql, Kh, Kl, Vtf);

    // 3) scores = scale * Q @ K^T   (bf16x3, 64 batches 1024x1024x96)
    const float scale = 0.11180339887498949f; // 1/sqrt(80)
    launch_g3(Qh, Ql, Kh, Kl, nullptr, scores,
              SEG_LEN, SEG_LEN, HDIMP, HDIMP, HDIMP, SEG_LEN,
              (long)SEG_LEN * HDIMP, (long)S_TOTAL * HDIMP,
              (long)SEG_LEN * HDIMP, (long)S_TOTAL * HDIMP,
              (long)HEADS * SEG_LEN * SEG_LEN, (long)SEG_LEN * SEG_LEN,
              NSEG * HEADS, HEADS, scale);

    // 4) softmax -> fp16 probs
    softmax_rows<<<(NSEG * HEADS * SEG_LEN) / 8, 256>>>(scores, Pf);

    // 5) ctx = P @ Vt^T  (fp16 x1, N=80 ragged)
    launch_g1(Pf, Vtf, nullptr, ctx,
              SEG_LEN, HDIM, SEG_LEN, SEG_LEN, S_TOTAL, EMBED,
              (long)HEADS * SEG_LEN * SEG_LEN, (long)SEG_LEN * SEG_LEN,
              (long)SEG_LEN, (long)HDIM * S_TOTAL,
              (long)SEG_LEN * EMBED, (long)HDIM,
              NSEG * HEADS, HEADS, 1.0f);

    // 6) ctx -> fp16, then out = ctx @ proj_w^T + proj_b  (fp16 x1)
    {
        long n = (long)S_TOTAL * EMBED;
        f32_to_f16<<<(unsigned)((n + 255) / 256), 256>>>(ctx, cf, n);
    }
    launch_g1(cf, pwf, proj_b, out,
              S_TOTAL, EMBED, EMBED, EMBED, EMBED, EMBED,
              0, 0, 0, 0, 0, 0, 1, 1, 1.0f);
}

// round 11
// speedup vs baseline: 1.6095x; 1.2164x over previous
#include <cuda_runtime.h>
#include <cuda_bf16.h>
#include <cuda_fp16.h>
#include <stdint.h>
#include <stddef.h>
#include <math.h>

// Round 11: byte-identical logic to round 10 — that bench died in the GB300
// broker (container failed twice) before compiling or running anything.
// Re-bench to get an attributable datapoint for the one-sided fp16 splits.
//
// Round 10 changes under test: QKV-QK and scores GEMMs use A=fp16 hi/lo x
// B=fp16 single (2 passes instead of bf16x3's 3); PV uses an exact N=80
// kernel writing fp16 ctx directly (fp32 ctx buffer + convert deleted).

// ---------------------------------------------------------------------------
// Problem constants
// ---------------------------------------------------------------------------
#define EMBED   1280
#define HEADS   16
#define HDIM    80
#define HDIMP   96            // HDIM padded to multiple of BK (zero tail)
#define S_TOTAL 4096
#define NSEG    4
#define SEG_LEN 1024
#define QKV_F   (3 * EMBED)   // 3840
#define QK_F    (2 * EMBED)   // 2560

// ---------------------------------------------------------------------------
// Scratch (device globals; zero-initialized -> pads stay 0)
// ---------------------------------------------------------------------------
__device__ float    g_qkv[(size_t)S_TOTAL * QKV_F];
__device__ float    g_scores[(size_t)NSEG * HEADS * SEG_LEN * SEG_LEN];

__device__ uint16_t g_xh16[(size_t)S_TOTAL * EMBED], g_xl16[(size_t)S_TOTAL * EMBED];
__device__ uint16_t g_wf[(size_t)QKV_F * EMBED];                          // fp16 all qkv_w
__device__ uint16_t g_pwf[(size_t)EMBED * EMBED];                         // fp16 proj_w
__device__ uint16_t g_Qh16[(size_t)HEADS * S_TOTAL * HDIMP];
__device__ uint16_t g_Ql16[(size_t)HEADS * S_TOTAL * HDIMP];
__device__ uint16_t g_Kf16[(size_t)HEADS * S_TOTAL * HDIMP];
__device__ uint16_t g_Vtf[(size_t)HEADS * HDIM * S_TOTAL];                // fp16 [h][d][s]
__device__ uint16_t g_Pf[(size_t)NSEG * HEADS * SEG_LEN * SEG_LEN];       // fp16
__device__ uint16_t g_cf[(size_t)S_TOTAL * EMBED];                        // fp16 ctx

// ---------------------------------------------------------------------------
// helpers
// ---------------------------------------------------------------------------
__device__ __forceinline__ uint16_t f2h(float x)
{
    __half h = __float2half_rn(x);
    return *reinterpret_cast<uint16_t*>(&h);
}

__device__ __forceinline__ void split1h(float x, uint16_t& hi, uint16_t& lo)
{
    __half h = __float2half_rn(x);
    float r = x - __half2float(h);
    hi = *reinterpret_cast<uint16_t*>(&h);
    __half l = __float2half_rn(r);
    lo = *reinterpret_cast<uint16_t*>(&l);
}

__device__ __forceinline__ void mma_fp16(float* c, const uint32_t* a,
                                         uint32_t b0, uint32_t b1)
{
    asm volatile(
        "mma.sync.aligned.m16n8k16.row.col.f32.f16.f16.f32 "
        "{%0,%1,%2,%3}, {%4,%5,%6,%7}, {%8,%9}, {%0,%1,%2,%3};"
        : "+f"(c[0]), "+f"(c[1]), "+f"(c[2]), "+f"(c[3])
        : "r"(a[0]), "r"(a[1]), "r"(a[2]), "r"(a[3]), "r"(b0), "r"(b1));
}

__device__ __forceinline__ void ldsm_x4(uint32_t* r, uint32_t addr)
{
    asm volatile("ldmatrix.sync.aligned.m8n8.x4.shared.b16 {%0,%1,%2,%3}, [%4];"
                 : "=r"(r[0]), "=r"(r[1]), "=r"(r[2]), "=r"(r[3]) : "r"(addr));
}

__device__ __forceinline__ void cp_async16(uint32_t dst_smem, const void* src)
{
    asm volatile("cp.async.cg.shared.global [%0], [%1], 16;"
                 :: "r"(dst_smem), "l"(src));
}
__device__ __forceinline__ void cp_async16z(uint32_t dst_smem, const void* src, int src_bytes)
{
    asm volatile("cp.async.cg.shared.global [%0], [%1], 16, %2;"
                 :: "r"(dst_smem), "l"(src), "r"(src_bytes));
}
__device__ __forceinline__ void cp_commit()
{
    asm volatile("cp.async.commit_group;");
}
template <int N>
__device__ __forceinline__ void cp_wait()
{
    asm volatile("cp.async.wait_group %0;" :: "n"(N));
}

// ---------------------------------------------------------------------------
// Shared tiling constants
// ---------------------------------------------------------------------------
#define BM 128
#define BN 128
#define BK 32
#define BKP 20                    // u32 per smem row (16 used + 4 pad)
#define SUB (128 * BKP)           // u32 per sub-array (10240 B)
#define STG2 (3 * SUB)            // Asplit stage: AH AL B
#define SMEM2_BYTES (2 * STG2 * 4)  // 61440
#define STG1 (2 * SUB)            // fp16 stage: A B
#define SMEM1_BYTES (2 * STG1 * 4)  // 40960

// ---------------------------------------------------------------------------
// fp16 A-split x2 batched GEMM: C = alpha*((Ah+Al)@B^T)+bias, fp32 out.
//   Ah,Al fp16 hi/lo; B fp16. M%128==0, K%32==0, N guarded.
// ---------------------------------------------------------------------------
__global__ __launch_bounds__(256, 2)
void gemm_f16ax2(const uint16_t* __restrict__ Ah, const uint16_t* __restrict__ Al,
                 const uint16_t* __restrict__ Bf,
                 const float* __restrict__ bias, float* __restrict__ C,
                 int N, int K, int lda, int ldb, int ldc,
                 long oAs, long oAh_, long oBs, long oBh_, long oCs, long oCh_,
                 int nh, float alpha)
{
    extern __shared__ uint32_t sm[];

    const int z   = blockIdx.z;
    const int seg = z / nh;
    const int h   = z % nh;
    Ah += oAs * seg + oAh_ * h;  Al += oAs * seg + oAh_ * h;
    Bf += oBs * seg + oBh_ * h;
    C  += oCs * seg + oCh_ * h;

    const int brow = blockIdx.y * BM;
    const int bcol = blockIdx.x * BN;

    const int tid  = threadIdx.x;
    const int warp = tid >> 5;
    const int lane = tid & 31;
    const int wm = (warp >> 1) * 32;
    const int wn = (warp & 1) * 64;
    const int lg = lane >> 2;
    const int lq = lane & 3;

    const uint32_t smem_base = (uint32_t)__cvta_generic_to_shared(sm);
    const int lm_r = lane & 15;
    const int lm_c = (lane >> 4) * 4;
    const int lrow2 = tid >> 2;
    const int lc4  = (tid & 3) * 4;
    const int lk8  = (tid & 3) * 8;

    float acc[2][8][4];
#pragma unroll
    for (int i = 0; i < 2; i++)
#pragma unroll
        for (int j = 0; j < 8; j++)
#pragma unroll
            for (int q = 0; q < 4; q++) acc[i][j][q] = 0.f;

    const int nit = K / BK;

    auto load_stage = [&](int stage, int k0) {
        const uint32_t sb = smem_base + (uint32_t)stage * STG2 * 4;
#pragma unroll
        for (int r2 = 0; r2 < 2; r2++) {
            const int row = lrow2 + r2 * 64;
            const uint32_t doff = (uint32_t)(row * BKP + lc4) * 4;
            cp_async16(sb + 0 * SUB * 4 + doff,
                       Ah + (long)(brow + row) * lda + k0 + lk8);
            cp_async16(sb + 1 * SUB * 4 + doff,
                       Al + (long)(brow + row) * lda + k0 + lk8);
            const int bn  = bcol + row;
            const int ok  = (bn < N) ? 16 : 0;
            const int bno = (bn < N) ? bn : 0;
            cp_async16z(sb + 2 * SUB * 4 + doff,
                        Bf + (long)bno * ldb + k0 + lk8, ok);
        }
    };

    load_stage(0, 0);
    cp_commit();

    const uint32_t aOff0 = (uint32_t)((wm + lm_r) * BKP + lm_c) * 4;
    const uint32_t aOff1 = (uint32_t)((wm + 16 + lm_r) * BKP + lm_c) * 4;
    const uint32_t bOffBase = (uint32_t)((wn + lm_r) * BKP + lm_c) * 4;

    for (int it = 0; it < nit; it++) {
        if (it + 1 < nit) {
            load_stage((it + 1) & 1, (it + 1) * BK);
            cp_commit();
            cp_wait<1>();
        } else {
            cp_wait<0>();
        }
        __syncthreads();

        const uint32_t stageB = smem_base + (uint32_t)(it & 1) * STG2 * 4;
        const uint32_t aBaseH = stageB;
        const uint32_t aBaseL = stageB + SUB * 4;
        const uint32_t bBase  = stageB + 2 * SUB * 4;

#pragma unroll
        for (int kc = 0; kc < 2; kc++) {
            const uint32_t kbyte = (uint32_t)(kc * 8) * 4;

            uint32_t aH[2][4], aL[2][4];
            ldsm_x4(aH[0], aBaseH + aOff0 + kbyte);
            ldsm_x4(aH[1], aBaseH + aOff1 + kbyte);
            ldsm_x4(aL[0], aBaseL + aOff0 + kbyte);
            ldsm_x4(aL[1], aBaseL + aOff1 + kbyte);

            uint32_t b[4][4];
#pragma unroll
            for (int ntp = 0; ntp < 4; ntp++)
                ldsm_x4(b[ntp], bBase + bOffBase + (uint32_t)(ntp * 16 * BKP) * 4 + kbyte);

            // pass 1: Ah * B
#pragma unroll
            for (int ntp = 0; ntp < 4; ntp++)
#pragma unroll
                for (int half = 0; half < 2; half++)
#pragma unroll
                    for (int mt = 0; mt < 2; mt++)
                        mma_fp16(acc[mt][ntp * 2 + half], aH[mt],
                                 b[ntp][half], b[ntp][2 + half]);
            // pass 2: Al * B
#pragma unroll
            for (int ntp = 0; ntp < 4; ntp++)
#pragma unroll
                for (int half = 0; half < 2; half++)
#pragma unroll
                    for (int mt = 0; mt < 2; mt++)
                        mma_fp16(acc[mt][ntp * 2 + half], aL[mt],
                                 b[ntp][half], b[ntp][2 + half]);
        }
        __syncthreads();
    }

#pragma unroll
    for (int mt = 0; mt < 2; mt++) {
        const int r0 = brow + wm + mt * 16 + lg;
#pragma unroll
        for (int nt = 0; nt < 8; nt++) {
            const int c0 = bcol + wn + nt * 8 + lq * 2;
            float* p0 = C + (long)r0 * ldc;
            float* p1 = C + (long)(r0 + 8) * ldc;
            const float b0 = bias ? bias[min(c0, N - 1)] : 0.f;
            const float b1 = bias ? bias[min(c0 + 1, N - 1)] : 0.f;
            if (c0 < N) {
                p0[c0] = alpha * acc[mt][nt][0] + b0;
                p1[c0] = alpha * acc[mt][nt][2] + b0;
            }
            if (c0 + 1 < N) {
                p0[c0 + 1] = alpha * acc[mt][nt][1] + b1;
                p1[c0 + 1] = alpha * acc[mt][nt][3] + b1;
            }
        }
    }
}

// ---------------------------------------------------------------------------
// fp16 single-pass batched GEMM: fp32 out + bias
// ---------------------------------------------------------------------------
__global__ __launch_bounds__(256, 2)
void gemm_fp16(const uint16_t* __restrict__ Af, const uint16_t* __restrict__ Bf,
               const float* __restrict__ bias, float* __restrict__ C,
               int N, int K, int lda, int ldb, int ldc,
               long oAs, long oAh_, long oBs, long oBh_, long oCs, long oCh_,
               int nh, float alpha)
{
    extern __shared__ uint32_t sm[];

    const int z   = blockIdx.z;
    const int seg = z / nh;
    const int h   = z % nh;
    Af += oAs * seg + oAh_ * h;
    Bf += oBs * seg + oBh_ * h;
    C  += oCs * seg + oCh_ * h;

    const int brow = blockIdx.y * BM;
    const int bcol = blockIdx.x * BN;

    const int tid  = threadIdx.x;
    const int warp = tid >> 5;
    const int lane = tid & 31;
    const int wm = (warp >> 1) * 32;
    const int wn = (warp & 1) * 64;
    const int lg = lane >> 2;
    const int lq = lane & 3;

    const uint32_t smem_base = (uint32_t)__cvta_generic_to_shared(sm);
    const int lm_r = lane & 15;
    const int lm_c = (lane >> 4) * 4;
    const int lrow2 = tid >> 2;
    const int lc4  = (tid & 3) * 4;
    const int lk8  = (tid & 3) * 8;

    float acc[2][8][4];
#pragma unroll
    for (int i = 0; i < 2; i++)
#pragma unroll
        for (int j = 0; j < 8; j++)
#pragma unroll
            for (int q = 0; q < 4; q++) acc[i][j][q] = 0.f;

    const int nit = K / BK;

    auto load_stage = [&](int stage, int k0) {
        const uint32_t sb = smem_base + (uint32_t)stage * STG1 * 4;
#pragma unroll
        for (int r2 = 0; r2 < 2; r2++) {
            const int row = lrow2 + r2 * 64;
            const uint32_t doff = (uint32_t)(row * BKP + lc4) * 4;
            cp_async16(sb + 0 * SUB * 4 + doff,
                       Af + (long)(brow + row) * lda + k0 + lk8);
            const int bn  = bcol + row;
            const int ok  = (bn < N) ? 16 : 0;
            const int bno = (bn < N) ? bn : 0;
            cp_async16z(sb + 1 * SUB * 4 + doff,
                        Bf + (long)bno * ldb + k0 + lk8, ok);
        }
    };

    load_stage(0, 0);
    cp_commit();

    const uint32_t aOff0 = (uint32_t)((wm + lm_r) * BKP + lm_c) * 4;
    const uint32_t aOff1 = (uint32_t)((wm + 16 + lm_r) * BKP + lm_c) * 4;
    const uint32_t bOffBase = (uint32_t)((wn + lm_r) * BKP + lm_c) * 4;

    for (int it = 0; it < nit; it++) {
        if (it + 1 < nit) {
            load_stage((it + 1) & 1, (it + 1) * BK);
            cp_commit();
            cp_wait<1>();
        } else {
            cp_wait<0>();
        }
        __syncthreads();

        const uint32_t stageB = smem_base + (uint32_t)(it & 1) * STG1 * 4;
        const uint32_t aBase = stageB;
        const uint32_t bBase = stageB + SUB * 4;

#pragma unroll
        for (int kc = 0; kc < 2; kc++) {
            const uint32_t kbyte = (uint32_t)(kc * 8) * 4;

            uint32_t a[2][4];
            ldsm_x4(a[0], aBase + aOff0 + kbyte);
            ldsm_x4(a[1], aBase + aOff1 + kbyte);

#pragma unroll
            for (int ntp = 0; ntp < 4; ntp++) {
                uint32_t b[4];
                ldsm_x4(b, bBase + bOffBase + (uint32_t)(ntp * 16 * BKP) * 4 + kbyte);
#pragma unroll
                for (int half = 0; half < 2; half++)
#pragma unroll
                    for (int mt = 0; mt < 2; mt++)
                        mma_fp16(acc[mt][ntp * 2 + half], a[mt],
                                 b[half], b[2 + half]);
            }
        }
        __syncthreads();
    }

#pragma unroll
    for (int mt = 0; mt < 2; mt++) {
        const int r0 = brow + wm + mt * 16 + lg;
#pragma unroll
        for (int nt = 0; nt < 8; nt++) {
            const int c0 = bcol + wn + nt * 8 + lq * 2;
            float* p0 = C + (long)r0 * ldc;
            float* p1 = C + (long)(r0 + 8) * ldc;
            const float b0 = bias ? bias[min(c0, N - 1)] : 0.f;
            const float b1 = bias ? bias[min(c0 + 1, N - 1)] : 0.f;
            if (c0 < N) {
                p0[c0] = alpha * acc[mt][nt][0] + b0;
                p1[c0] = alpha * acc[mt][nt][2] + b0;
            }
            if (c0 + 1 < N) {
                p0[c0 + 1] = alpha * acc[mt][nt][1] + b1;
                p1[c0 + 1] = alpha * acc[mt][nt][3] + b1;
            }
        }
    }
}

// ---------------------------------------------------------------------------
// PV GEMM, exact N=80, fp16 output: cf = P @ Vt^T
//   Warp layout: 8 warps x (16 rows x 80 cols). A=P fp16, B=Vt fp16.
// ---------------------------------------------------------------------------
__global__ __launch_bounds__(256, 2)
void gemm_pv80(const uint16_t* __restrict__ Pf, const uint16_t* __restrict__ Vt,
               uint16_t* __restrict__ Cf,
               int K, int lda, int ldb, int ldc,
               long oAs, long oAh_, long oBs, long oBh_, long oCs, long oCh_,
               int nh)
{
    extern __shared__ uint32_t sm[];
    const int NPV = 80;

    const int z   = blockIdx.z;
    const int seg = z / nh;
    const int h   = z % nh;
    Pf += oAs * seg + oAh_ * h;
    Vt += oBs * seg + oBh_ * h;
    Cf += oCs * seg + oCh_ * h;

    const int brow = blockIdx.y * BM;

    const int tid  = threadIdx.x;
    const int warp = tid >> 5;
    const int lane = tid & 31;
    const int lg = lane >> 2;
    const int lq = lane & 3;

    const uint32_t smem_base = (uint32_t)__cvta_generic_to_shared(sm);
    const int lm_r = lane & 15;
    const int lm_c = (lane >> 4) * 4;
    const int lrow2 = tid >> 2;
    const int lc4  = (tid & 3) * 4;
    const int lk8  = (tid & 3) * 8;

    float acc[10][4];
#pragma unroll
    for (int j = 0; j < 10; j++)
#pragma unroll
        for (int q = 0; q < 4; q++) acc[j][q] = 0.f;

    const int nit = K / BK;

    auto load_stage = [&](int stage, int k0) {
        const uint32_t sb = smem_base + (uint32_t)stage * STG1 * 4;
#pragma unroll
        for (int r2 = 0; r2 < 2; r2++) {
            const int row = lrow2 + r2 * 64;
            const uint32_t doff = (uint32_t)(row * BKP + lc4) * 4;
            cp_async16(sb + 0 * SUB * 4 + doff,
                       Pf + (long)(brow + row) * lda + k0 + lk8);
            const int ok  = (row < NPV) ? 16 : 0;
            const int bno = (row < NPV) ? row : 0;
            cp_async16z(sb + 1 * SUB * 4 + doff,
                        Vt + (long)bno * ldb + k0 + lk8, ok);
        }
    };

    load_stage(0, 0);
    cp_commit();

    const uint32_t aOff = (uint32_t)((warp * 16 + lm_r) * BKP + lm_c) * 4;
    const uint32_t bOffBase = (uint32_t)(lm_r * BKP + lm_c) * 4;

    for (int it = 0; it < nit; it++) {
        if (it + 1 < nit) {
            load_stage((it + 1) & 1, (it + 1) * BK);
            cp_commit();
            cp_wait<1>();
        } else {
            cp_wait<0>();
        }
        __syncthreads();

        const uint32_t stageB = smem_base + (uint32_t)(it & 1) * STG1 * 4;
        const uint32_t aBase = stageB;
        const uint32_t bBase = stageB + SUB * 4;

#pragma unroll
        for (int kc = 0; kc < 2; kc++) {
            const uint32_t kbyte = (uint32_t)(kc * 8) * 4;

            uint32_t a[4];
            ldsm_x4(a, aBase + aOff + kbyte);

#pragma unroll
            for (int g = 0; g < 5; g++) {
                uint32_t b[4];
                ldsm_x4(b, bBase + bOffBase + (uint32_t)(g * 16 * BKP) * 4 + kbyte);
#pragma unroll
                for (int half = 0; half < 2; half++)
                    mma_fp16(acc[g * 2 + half], a, b[half], b[2 + half]);
            }
        }
        __syncthreads();
    }

    // epilogue: fp16 out, N=80 exact (no guards)
    const int r0 = brow + warp * 16 + lg;
#pragma unroll
    for (int nt = 0; nt < 10; nt++) {
        const int c0 = nt * 8 + lq * 2;
        __half2 v0 = __floats2half2_rn(acc[nt][0], acc[nt][1]);
        __half2 v1 = __floats2half2_rn(acc[nt][2], acc[nt][3]);
        *(uint32_t*)(Cf + (long)r0 * ldc + c0)       = *reinterpret_cast<uint32_t*>(&v0);
        *(uint32_t*)(Cf + (long)(r0 + 8) * ldc + c0) = *reinterpret_cast<uint32_t*>(&v1);
    }
}

// ---------------------------------------------------------------------------
// elementwise conversions
// ---------------------------------------------------------------------------
__global__ void split_f16(const float* __restrict__ in,
                          uint16_t* __restrict__ hi, uint16_t* __restrict__ lo,
                          long n)
{
    const long i = (long)blockIdx.x * blockDim.x + threadIdx.x;
    if (i < n) {
        uint16_t h, l;
        split1h(in[i], h, l);
        hi[i] = h;
        lo[i] = l;
    }
}

__global__ void f32_to_f16(const float* __restrict__ in,
                           uint16_t* __restrict__ out, long n)
{
    const long i = (long)blockIdx.x * blockDim.x + threadIdx.x;
    if (i < n) out[i] = f2h(in[i]);
}

// ---------------------------------------------------------------------------
// Rotary + relayout: Q -> fp16 hi/lo [h][s][96], K -> fp16 [h][s][96],
// V -> fp16 [h][d][s]
// ---------------------------------------------------------------------------
__global__ void rotary_relayout(const float* __restrict__ qkv,
                                const float* __restrict__ rope,
                                uint16_t* __restrict__ Qh, uint16_t* __restrict__ Ql,
                                uint16_t* __restrict__ Kf,
                                uint16_t* __restrict__ Vtf)
{
    const int s = blockIdx.x;
    const float* row = qkv + (long)s * QKV_F;

    for (int e = threadIdx.x; e < EMBED; e += blockDim.x) {
        const int h = e / HDIM;
        const int d = e % HDIM;
        const float f = rope[s * (HDIM / 2) + ((d < HDIM / 2) ? d : d - HDIM / 2)];
        float sn, cs;
        sincosf(f, &sn, &cs);

        const float qv = row[e];
        const float kv = row[EMBED + e];
        const float qp = (d < HDIM / 2) ? -row[e + HDIM / 2] : row[e - HDIM / 2];
        const float kp = (d < HDIM / 2) ? -row[EMBED + e + HDIM / 2]
                                        :  row[EMBED + e - HDIM / 2];

        const float qr = qv * cs + qp * sn;
        const float kr = kv * cs + kp * sn;

        const long oq = ((long)h * S_TOTAL + s) * HDIMP + d;
        uint16_t hh, ll;
        split1h(qr, hh, ll);
        Qh[oq] = hh;  Ql[oq] = ll;
        Kf[oq] = f2h(kr);

        Vtf[((long)h * HDIM + d) * S_TOTAL + s] = f2h(row[2 * EMBED + e]);
    }
}

// ---------------------------------------------------------------------------
// Row softmax over 1024 cols; one warp per row; outputs fp16 probs.
// ---------------------------------------------------------------------------
__global__ void softmax_rows(const float* __restrict__ S,
                             uint16_t* __restrict__ Pf)
{
    const long row  = (long)blockIdx.x * 8 + (threadIdx.x >> 5);
    const int  lane = threadIdx.x & 31;
    const float* p = S + row * SEG_LEN;

    float v[32];
    float mx = -INFINITY;
#pragma unroll
    for (int i = 0; i < 32; i++) {
        v[i] = p[lane + i * 32];
        mx = fmaxf(mx, v[i]);
    }
#pragma unroll
    for (int o = 16; o; o >>= 1) mx = fmaxf(mx, __shfl_xor_sync(0xffffffffu, mx, o));

    float sum = 0.f;
#pragma unroll
    for (int i = 0; i < 32; i++) {
        v[i] = __expf(v[i] - mx);
        sum += v[i];
    }
#pragma unroll
    for (int o = 16; o; o >>= 1) sum += __shfl_xor_sync(0xffffffffu, sum, o);

    const float r = 1.f / sum;
    uint16_t* ph = Pf + row * SEG_LEN;
#pragma unroll
    for (int i = 0; i < 32; i++)
        ph[lane + i * 32] = f2h(v[i] * r);
}

// ---------------------------------------------------------------------------
// Launch helpers
// ---------------------------------------------------------------------------
static void launch_g2(const uint16_t* Ah, const uint16_t* Al, const uint16_t* Bf,
                      const float* bias, float* C,
                      int M, int N, int K, int lda, int ldb, int ldc,
                      long oAs, long oAh_, long oBs, long oBh_,
                      long oCs, long oCh_, int nbatch, int nh, float alpha)
{
    dim3 grid((N + BN - 1) / BN, M / BM, nbatch);
    gemm_f16ax2<<<grid, 256, SMEM2_BYTES>>>(Ah, Al, Bf, bias, C,
                                            N, K, lda, ldb, ldc,
                                            oAs, oAh_, oBs, oBh_, oCs, oCh_,
                                            nh, alpha);
}

static void launch_g1(const uint16_t* Af, const uint16_t* Bf,
                      const float* bias, float* C,
                      int M, int N, int K, int lda, int ldb, int ldc,
                      long oAs, long oAh_, long oBs, long oBh_,
                      long oCs, long oCh_, int nbatch, int nh, float alpha)
{
    dim3 grid((N + BN - 1) / BN, M / BM, nbatch);
    gemm_fp16<<<grid, 256, SMEM1_BYTES>>>(Af, Bf, bias, C,
                                          N, K, lda, ldb, ldc,
                                          oAs, oAh_, oBs, oBh_, oCs, oCh_,
                                          nh, alpha);
}

// ---------------------------------------------------------------------------
// Entry point
// ---------------------------------------------------------------------------
extern "C" void kernel_launch(void* const* d_in, const int* in_sizes, int n_in,
                              void* d_out, int out_size)
{
    const float* x      = (const float*)d_in[0];
    const float* qkv_w  = (const float*)d_in[1];
    const float* qkv_b  = (const float*)d_in[2];
    const float* proj_w = (const float*)d_in[3];
    const float* proj_b = (const float*)d_in[4];
    const float* rope   = (const float*)d_in[5];
    float* out = (float*)d_out;

    cudaFuncSetAttribute(gemm_f16ax2,
                         cudaFuncAttributeMaxDynamicSharedMemorySize, SMEM2_BYTES);
    cudaFuncSetAttribute(gemm_fp16,
                         cudaFuncAttributeMaxDynamicSharedMemorySize, SMEM1_BYTES);
    cudaFuncSetAttribute(gemm_pv80,
                         cudaFuncAttributeMaxDynamicSharedMemorySize, SMEM1_BYTES);

    float *qkv, *scores;
    uint16_t *xh, *xl, *wf, *pwf;
    uint16_t *Qh, *Ql, *Kf, *Vtf, *Pf, *cf;
    cudaGetSymbolAddress((void**)&qkv,    g_qkv);
    cudaGetSymbolAddress((void**)&scores, g_scores);
    cudaGetSymbolAddress((void**)&xh,  g_xh16);  cudaGetSymbolAddress((void**)&xl, g_xl16);
    cudaGetSymbolAddress((void**)&wf,  g_wf);    cudaGetSymbolAddress((void**)&pwf, g_pwf);
    cudaGetSymbolAddress((void**)&Qh,  g_Qh16);  cudaGetSymbolAddress((void**)&Ql, g_Ql16);
    cudaGetSymbolAddress((void**)&Kf,  g_Kf16);
    cudaGetSymbolAddress((void**)&Vtf, g_Vtf);
    cudaGetSymbolAddress((void**)&Pf,  g_Pf);
    cudaGetSymbolAddress((void**)&cf,  g_cf);

    // 0) conversions
    {
        long n1 = (long)S_TOTAL * EMBED;
        long n2 = (long)QKV_F * EMBED;
        long n3 = (long)EMBED * EMBED;
        split_f16<<<(unsigned)((n1 + 255) / 256), 256>>>(x, xh, xl, n1);
        f32_to_f16<<<(unsigned)((n2 + 255) / 256), 256>>>(qkv_w, wf, n2);
        f32_to_f16<<<(unsigned)((n3 + 255) / 256), 256>>>(proj_w, pwf, n3);
    }

    // 1a) QK part of QKV (fp16 A-split x2): qkv[:, 0:2560]
    launch_g2(xh, xl, wf, qkv_b, qkv,
              S_TOTAL, QK_F, EMBED, EMBED, EMBED, QKV_F,
              0, 0, 0, 0, 0, 0, 1, 1, 1.0f);

    // 1b) V part of QKV (fp16 x1): qkv[:, 2560:3840]
    launch_g1(xh, wf + (long)QK_F * EMBED, qkv_b + QK_F, qkv + QK_F,
              S_TOTAL, EMBED, EMBED, EMBED, EMBED, QKV_F,
              0, 0, 0, 0, 0, 0, 1, 1, 1.0f);

    // 2) rotary + relayout
    rotary_relayout<<<S_TOTAL, 256>>>(qkv, rope, Qh, Ql, Kf, Vtf);

    // 3) scores = scale * Q @ K^T   (fp16 A-split x2; 64 batches 1024x1024x96)
    const float scale = 0.11180339887498949f; // 1/sqrt(80)
    launch_g2(Qh, Ql, Kf, nullptr, scores,
              SEG_LEN, SEG_LEN, HDIMP, HDIMP, HDIMP, SEG_LEN,
              (long)SEG_LEN * HDIMP, (long)S_TOTAL * HDIMP,
              (long)SEG_LEN * HDIMP, (long)S_TOTAL * HDIMP,
              (long)HEADS * SEG_LEN * SEG_LEN, (long)SEG_LEN * SEG_LEN,
              NSEG * HEADS, HEADS, scale);

    // 4) softmax -> fp16 probs
    softmax_rows<<<(NSEG * HEADS * SEG_LEN) / 8, 256>>>(scores, Pf);

    // 5) ctx(fp16) = P @ Vt^T  (exact N=80 kernel, fp16 out)
    {
        dim3 grid(1, SEG_LEN / BM, NSEG * HEADS);
        gemm_pv80<<<grid, 256, SMEM1_BYTES>>>(Pf, Vtf, cf,
            SEG_LEN, SEG_LEN, S_TOTAL, EMBED,
            (long)HEADS * SEG_LEN * SEG_LEN, (long)SEG_LEN * SEG_LEN,
            (long)SEG_LEN, (long)HDIM * S_TOTAL,
            (long)SEG_LEN * EMBED, (long)HDIM,
            HEADS);
    }

    // 6) out = ctx @ proj_w^T + proj_b  (fp16 x1)
    launch_g1(cf, pwf, proj_b, out,
              S_TOTAL, EMBED, EMBED, EMBED, EMBED, EMBED,
              0, 0, 0, 0, 0, 0, 1, 1, 1.0f);
}

// round 12
// speedup vs baseline: 1.7378x; 1.0797x over previous
#include <cuda_runtime.h>
#include <cuda_bf16.h>
#include <cuda_fp16.h>
#include <stdint.h>
#include <stddef.h>
#include <math.h>

// Round 12: BK templated; K%64==0 GEMMs (QKV-QK, QKV-V, proj, PV) move to
// BK=64 -> 2x mma work per sync pair (tensor pipe 42.9% was sync-diluted vs
// the 51% ceiling). scores keeps BK=32 (K=96). mma ordering per accumulator
// unchanged -> rel_err must stay exactly 6.341e-4.

// ---------------------------------------------------------------------------
// Problem constants
// ---------------------------------------------------------------------------
#define EMBED   1280
#define HEADS   16
#define HDIM    80
#define HDIMP   96            // HDIM padded (zero tail) for scores GEMM
#define S_TOTAL 4096
#define NSEG    4
#define SEG_LEN 1024
#define QKV_F   (3 * EMBED)   // 3840
#define QK_F    (2 * EMBED)   // 2560

// ---------------------------------------------------------------------------
// Scratch (device globals; zero-initialized -> pads stay 0)
// ---------------------------------------------------------------------------
__device__ float    g_qkv[(size_t)S_TOTAL * QKV_F];
__device__ float    g_scores[(size_t)NSEG * HEADS * SEG_LEN * SEG_LEN];

__device__ uint16_t g_xh16[(size_t)S_TOTAL * EMBED], g_xl16[(size_t)S_TOTAL * EMBED];
__device__ uint16_t g_wf[(size_t)QKV_F * EMBED];
__device__ uint16_t g_pwf[(size_t)EMBED * EMBED];
__device__ uint16_t g_Qh16[(size_t)HEADS * S_TOTAL * HDIMP];
__device__ uint16_t g_Ql16[(size_t)HEADS * S_TOTAL * HDIMP];
__device__ uint16_t g_Kf16[(size_t)HEADS * S_TOTAL * HDIMP];
__device__ uint16_t g_Vtf[(size_t)HEADS * HDIM * S_TOTAL];
__device__ uint16_t g_Pf[(size_t)NSEG * HEADS * SEG_LEN * SEG_LEN];
__device__ uint16_t g_cf[(size_t)S_TOTAL * EMBED];

// ---------------------------------------------------------------------------
// helpers
// ---------------------------------------------------------------------------
__device__ __forceinline__ uint16_t f2h(float x)
{
    __half h = __float2half_rn(x);
    return *reinterpret_cast<uint16_t*>(&h);
}

__device__ __forceinline__ void split1h(float x, uint16_t& hi, uint16_t& lo)
{
    __half h = __float2half_rn(x);
    float r = x - __half2float(h);
    hi = *reinterpret_cast<uint16_t*>(&h);
    __half l = __float2half_rn(r);
    lo = *reinterpret_cast<uint16_t*>(&l);
}

__device__ __forceinline__ void mma_fp16(float* c, const uint32_t* a,
                                         uint32_t b0, uint32_t b1)
{
    asm volatile(
        "mma.sync.aligned.m16n8k16.row.col.f32.f16.f16.f32 "
        "{%0,%1,%2,%3}, {%4,%5,%6,%7}, {%8,%9}, {%0,%1,%2,%3};"
        : "+f"(c[0]), "+f"(c[1]), "+f"(c[2]), "+f"(c[3])
        : "r"(a[0]), "r"(a[1]), "r"(a[2]), "r"(a[3]), "r"(b0), "r"(b1));
}

__device__ __forceinline__ void ldsm_x4(uint32_t* r, uint32_t addr)
{
    asm volatile("ldmatrix.sync.aligned.m8n8.x4.shared.b16 {%0,%1,%2,%3}, [%4];"
                 : "=r"(r[0]), "=r"(r[1]), "=r"(r[2]), "=r"(r[3]) : "r"(addr));
}

__device__ __forceinline__ void cp_async16(uint32_t dst_smem, const void* src)
{
    asm volatile("cp.async.cg.shared.global [%0], [%1], 16;"
                 :: "r"(dst_smem), "l"(src));
}
__device__ __forceinline__ void cp_async16z(uint32_t dst_smem, const void* src, int src_bytes)
{
    asm volatile("cp.async.cg.shared.global [%0], [%1], 16, %2;"
                 :: "r"(dst_smem), "l"(src), "r"(src_bytes));
}
__device__ __forceinline__ void cp_commit()
{
    asm volatile("cp.async.commit_group;");
}
template <int N>
__device__ __forceinline__ void cp_wait()
{
    asm volatile("cp.async.wait_group %0;" :: "n"(N));
}

// ---------------------------------------------------------------------------
// Tiling: BM=BN=128 fixed; BK templated. BKP(BK) = BK/2 + 4 u32 row stride.
// ---------------------------------------------------------------------------
#define BM 128
#define BN 128
template <int BK_> struct TileCfg {
    static constexpr int BKP = BK_ / 2 + 4;          // u32 per smem row
    static constexpr int SUBu = 128 * BKP;           // u32 per sub-array
    static constexpr int TPR  = BK_ / 8;             // threads per row (16B chunks)
    static constexpr int RSTEP = 256 / TPR;          // row step for loader
};
// stage sizes in bytes
template <int BK_> constexpr int STG2B() { return 3 * TileCfg<BK_>::SUBu * 4; }
template <int BK_> constexpr int STG1B() { return 2 * TileCfg<BK_>::SUBu * 4; }

// ---------------------------------------------------------------------------
// fp16 A-split x2 batched GEMM: C = alpha*((Ah+Al)@B^T)+bias, fp32 out.
// ---------------------------------------------------------------------------
template <int BK_>
__global__ __launch_bounds__(256, 2)
void gemm_f16ax2(const uint16_t* __restrict__ Ah, const uint16_t* __restrict__ Al,
                 const uint16_t* __restrict__ Bf,
                 const float* __restrict__ bias, float* __restrict__ C,
                 int N, int K, int lda, int ldb, int ldc,
                 long oAs, long oAh_, long oBs, long oBh_, long oCs, long oCh_,
                 int nh, float alpha)
{
    using T = TileCfg<BK_>;
    constexpr int BKP = T::BKP;
    constexpr int SUBu = T::SUBu;
    constexpr int STGu = 3 * SUBu;
    extern __shared__ uint32_t sm[];

    const int z   = blockIdx.z;
    const int seg = z / nh;
    const int h   = z % nh;
    Ah += oAs * seg + oAh_ * h;  Al += oAs * seg + oAh_ * h;
    Bf += oBs * seg + oBh_ * h;
    C  += oCs * seg + oCh_ * h;

    const int brow = blockIdx.y * BM;
    const int bcol = blockIdx.x * BN;

    const int tid  = threadIdx.x;
    const int warp = tid >> 5;
    const int lane = tid & 31;
    const int wm = (warp >> 1) * 32;
    const int wn = (warp & 1) * 64;
    const int lg = lane >> 2;
    const int lq = lane & 3;

    const uint32_t smem_base = (uint32_t)__cvta_generic_to_shared(sm);
    const int lm_r = lane & 15;
    const int lm_c = (lane >> 4) * 4;
    const int lrow0 = tid / T::TPR;
    const int chk   = tid % T::TPR;

    float acc[2][8][4];
#pragma unroll
    for (int i = 0; i < 2; i++)
#pragma unroll
        for (int j = 0; j < 8; j++)
#pragma unroll
            for (int q = 0; q < 4; q++) acc[i][j][q] = 0.f;

    const int nit = K / BK_;

    auto load_stage = [&](int stage, int k0) {
        const uint32_t sb = smem_base + (uint32_t)stage * STGu * 4;
#pragma unroll
        for (int row = lrow0; row < 128; row += T::RSTEP) {
            const uint32_t doff = (uint32_t)(row * BKP + chk * 4) * 4;
            const long acol = (long)k0 + chk * 8;
            cp_async16(sb + 0 * SUBu * 4 + doff,
                       Ah + (long)(brow + row) * lda + acol);
            cp_async16(sb + 1 * SUBu * 4 + doff,
                       Al + (long)(brow + row) * lda + acol);
            const int bn  = bcol + row;
            const int ok  = (bn < N) ? 16 : 0;
            const int bno = (bn < N) ? bn : 0;
            cp_async16z(sb + 2 * SUBu * 4 + doff,
                        Bf + (long)bno * ldb + acol, ok);
        }
    };

    load_stage(0, 0);
    cp_commit();

    const uint32_t aOff0 = (uint32_t)((wm + lm_r) * BKP + lm_c) * 4;
    const uint32_t aOff1 = (uint32_t)((wm + 16 + lm_r) * BKP + lm_c) * 4;
    const uint32_t bOffBase = (uint32_t)((wn + lm_r) * BKP + lm_c) * 4;

    for (int it = 0; it < nit; it++) {
        if (it + 1 < nit) {
            load_stage((it + 1) & 1, (it + 1) * BK_);
            cp_commit();
            cp_wait<1>();
        } else {
            cp_wait<0>();
        }
        __syncthreads();

        const uint32_t stageB = smem_base + (uint32_t)(it & 1) * STGu * 4;
        const uint32_t aBaseH = stageB;
        const uint32_t aBaseL = stageB + SUBu * 4;
        const uint32_t bBase  = stageB + 2 * SUBu * 4;

#pragma unroll
        for (int kc = 0; kc < BK_ / 16; kc++) {
            const uint32_t kbyte = (uint32_t)(kc * 8) * 4;

            uint32_t aH[2][4], aL[2][4];
            ldsm_x4(aH[0], aBaseH + aOff0 + kbyte);
            ldsm_x4(aH[1], aBaseH + aOff1 + kbyte);
            ldsm_x4(aL[0], aBaseL + aOff0 + kbyte);
            ldsm_x4(aL[1], aBaseL + aOff1 + kbyte);

            uint32_t b[4][4];
#pragma unroll
            for (int ntp = 0; ntp < 4; ntp++)
                ldsm_x4(b[ntp], bBase + bOffBase + (uint32_t)(ntp * 16 * BKP) * 4 + kbyte);

            // pass 1: Ah * B
#pragma unroll
            for (int ntp = 0; ntp < 4; ntp++)
#pragma unroll
                for (int half = 0; half < 2; half++)
#pragma unroll
                    for (int mt = 0; mt < 2; mt++)
                        mma_fp16(acc[mt][ntp * 2 + half], aH[mt],
                                 b[ntp][half], b[ntp][2 + half]);
            // pass 2: Al * B
#pragma unroll
            for (int ntp = 0; ntp < 4; ntp++)
#pragma unroll
                for (int half = 0; half < 2; half++)
#pragma unroll
                    for (int mt = 0; mt < 2; mt++)
                        mma_fp16(acc[mt][ntp * 2 + half], aL[mt],
                                 b[ntp][half], b[ntp][2 + half]);
        }
        __syncthreads();
    }

#pragma unroll
    for (int mt = 0; mt < 2; mt++) {
        const int r0 = brow + wm + mt * 16 + lg;
#pragma unroll
        for (int nt = 0; nt < 8; nt++) {
            const int c0 = bcol + wn + nt * 8 + lq * 2;
            float* p0 = C + (long)r0 * ldc;
            float* p1 = C + (long)(r0 + 8) * ldc;
            const float b0 = bias ? bias[min(c0, N - 1)] : 0.f;
            const float b1 = bias ? bias[min(c0 + 1, N - 1)] : 0.f;
            if (c0 < N) {
                p0[c0] = alpha * acc[mt][nt][0] + b0;
                p1[c0] = alpha * acc[mt][nt][2] + b0;
            }
            if (c0 + 1 < N) {
                p0[c0 + 1] = alpha * acc[mt][nt][1] + b1;
                p1[c0 + 1] = alpha * acc[mt][nt][3] + b1;
            }
        }
    }
}

// ---------------------------------------------------------------------------
// fp16 single-pass batched GEMM: fp32 out + bias
// ---------------------------------------------------------------------------
template <int BK_>
__global__ __launch_bounds__(256, 2)
void gemm_fp16(const uint16_t* __restrict__ Af, const uint16_t* __restrict__ Bf,
               const float* __restrict__ bias, float* __restrict__ C,
               int N, int K, int lda, int ldb, int ldc,
               long oAs, long oAh_, long oBs, long oBh_, long oCs, long oCh_,
               int nh, float alpha)
{
    using T = TileCfg<BK_>;
    constexpr int BKP = T::BKP;
    constexpr int SUBu = T::SUBu;
    constexpr int STGu = 2 * SUBu;
    extern __shared__ uint32_t sm[];

    const int z   = blockIdx.z;
    const int seg = z / nh;
    const int h   = z % nh;
    Af += oAs * seg + oAh_ * h;
    Bf += oBs * seg + oBh_ * h;
    C  += oCs * seg + oCh_ * h;

    const int brow = blockIdx.y * BM;
    const int bcol = blockIdx.x * BN;

    const int tid  = threadIdx.x;
    const int warp = tid >> 5;
    const int lane = tid & 31;
    const int wm = (warp >> 1) * 32;
    const int wn = (warp & 1) * 64;
    const int lg = lane >> 2;
    const int lq = lane & 3;

    const uint32_t smem_base = (uint32_t)__cvta_generic_to_shared(sm);
    const int lm_r = lane & 15;
    const int lm_c = (lane >> 4) * 4;
    const int lrow0 = tid / T::TPR;
    const int chk   = tid % T::TPR;

    float acc[2][8][4];
#pragma unroll
    for (int i = 0; i < 2; i++)
#pragma unroll
        for (int j = 0; j < 8; j++)
#pragma unroll
            for (int q = 0; q < 4; q++) acc[i][j][q] = 0.f;

    const int nit = K / BK_;

    auto load_stage = [&](int stage, int k0) {
        const uint32_t sb = smem_base + (uint32_t)stage * STGu * 4;
#pragma unroll
        for (int row = lrow0; row < 128; row += T::RSTEP) {
            const uint32_t doff = (uint32_t)(row * BKP + chk * 4) * 4;
            const long acol = (long)k0 + chk * 8;
            cp_async16(sb + 0 * SUBu * 4 + doff,
                       Af + (long)(brow + row) * lda + acol);
            const int bn  = bcol + row;
            const int ok  = (bn < N) ? 16 : 0;
            const int bno = (bn < N) ? bn : 0;
            cp_async16z(sb + 1 * SUBu * 4 + doff,
                        Bf + (long)bno * ldb + acol, ok);
        }
    };

    load_stage(0, 0);
    cp_commit();

    const uint32_t aOff0 = (uint32_t)((wm + lm_r) * BKP + lm_c) * 4;
    const uint32_t aOff1 = (uint32_t)((wm + 16 + lm_r) * BKP + lm_c) * 4;
    const uint32_t bOffBase = (uint32_t)((wn + lm_r) * BKP + lm_c) * 4;

    for (int it = 0; it < nit; it++) {
        if (it + 1 < nit) {
            load_stage((it + 1) & 1, (it + 1) * BK_);
            cp_commit();
            cp_wait<1>();
        } else {
            cp_wait<0>();
        }
        __syncthreads();

        const uint32_t stageB = smem_base + (uint32_t)(it & 1) * STGu * 4;
        const uint32_t aBase = stageB;
        const uint32_t bBase = stageB + SUBu * 4;

#pragma unroll
        for (int kc = 0; kc < BK_ / 16; kc++) {
            const uint32_t kbyte = (uint32_t)(kc * 8) * 4;

            uint32_t a[2][4];
            ldsm_x4(a[0], aBase + aOff0 + kbyte);
            ldsm_x4(a[1], aBase + aOff1 + kbyte);

#pragma unroll
            for (int ntp = 0; ntp < 4; ntp++) {
                uint32_t b[4];
                ldsm_x4(b, bBase + bOffBase + (uint32_t)(ntp * 16 * BKP) * 4 + kbyte);
#pragma unroll
                for (int half = 0; half < 2; half++)
#pragma unroll
                    for (int mt = 0; mt < 2; mt++)
                        mma_fp16(acc[mt][ntp * 2 + half], a[mt],
                                 b[half], b[2 + half]);
            }
        }
        __syncthreads();
    }

#pragma unroll
    for (int mt = 0; mt < 2; mt++) {
        const int r0 = brow + wm + mt * 16 + lg;
#pragma unroll
        for (int nt = 0; nt < 8; nt++) {
            const int c0 = bcol + wn + nt * 8 + lq * 2;
            float* p0 = C + (long)r0 * ldc;
            float* p1 = C + (long)(r0 + 8) * ldc;
            const float b0 = bias ? bias[min(c0, N - 1)] : 0.f;
            const float b1 = bias ? bias[min(c0 + 1, N - 1)] : 0.f;
            if (c0 < N) {
                p0[c0] = alpha * acc[mt][nt][0] + b0;
                p1[c0] = alpha * acc[mt][nt][2] + b0;
            }
            if (c0 + 1 < N) {
                p0[c0 + 1] = alpha * acc[mt][nt][1] + b1;
                p1[c0 + 1] = alpha * acc[mt][nt][3] + b1;
            }
        }
    }
}

// ---------------------------------------------------------------------------
// PV GEMM, exact N=80, fp16 output: cf = P @ Vt^T
// ---------------------------------------------------------------------------
template <int BK_>
__global__ __launch_bounds__(256, 2)
void gemm_pv80(const uint16_t* __restrict__ Pf, const uint16_t* __restrict__ Vt,
               uint16_t* __restrict__ Cf,
               int K, int lda, int ldb, int ldc,
               long oAs, long oAh_, long oBs, long oBh_, long oCs, long oCh_,
               int nh)
{
    using T = TileCfg<BK_>;
    constexpr int BKP = T::BKP;
    constexpr int SUBu = T::SUBu;
    constexpr int STGu = 2 * SUBu;
    extern __shared__ uint32_t sm[];
    const int NPV = 80;

    const int z   = blockIdx.z;
    const int seg = z / nh;
    const int h   = z % nh;
    Pf += oAs * seg + oAh_ * h;
    Vt += oBs * seg + oBh_ * h;
    Cf += oCs * seg + oCh_ * h;

    const int brow = blockIdx.y * BM;

    const int tid  = threadIdx.x;
    const int warp = tid >> 5;
    const int lane = tid & 31;
    const int lg = lane >> 2;
    const int lq = lane & 3;

    const uint32_t smem_base = (uint32_t)__cvta_generic_to_shared(sm);
    const int lm_r = lane & 15;
    const int lm_c = (lane >> 4) * 4;
    const int lrow0 = tid / T::TPR;
    const int chk   = tid % T::TPR;

    float acc[10][4];
#pragma unroll
    for (int j = 0; j < 10; j++)
#pragma unroll
        for (int q = 0; q < 4; q++) acc[j][q] = 0.f;

    const int nit = K / BK_;

    auto load_stage = [&](int stage, int k0) {
        const uint32_t sb = smem_base + (uint32_t)stage * STGu * 4;
#pragma unroll
        for (int row = lrow0; row < 128; row += T::RSTEP) {
            const uint32_t doff = (uint32_t)(row * BKP + chk * 4) * 4;
            const long acol = (long)k0 + chk * 8;
            cp_async16(sb + 0 * SUBu * 4 + doff,
                       Pf + (long)(brow + row) * lda + acol);
            const int ok  = (row < NPV) ? 16 : 0;
            const int bno = (row < NPV) ? row : 0;
            cp_async16z(sb + 1 * SUBu * 4 + doff,
                        Vt + (long)bno * ldb + acol, ok);
        }
    };

    load_stage(0, 0);
    cp_commit();

    const uint32_t aOff = (uint32_t)((warp * 16 + lm_r) * BKP + lm_c) * 4;
    const uint32_t bOffBase = (uint32_t)(lm_r * BKP + lm_c) * 4;

    for (int it = 0; it < nit; it++) {
        if (it + 1 < nit) {
            load_stage((it + 1) & 1, (it + 1) * BK_);
            cp_commit();
            cp_wait<1>();
        } else {
            cp_wait<0>();
        }
        __syncthreads();

        const uint32_t stageB = smem_base + (uint32_t)(it & 1) * STGu * 4;
        const uint32_t aBase = stageB;
        const uint32_t bBase = stageB + SUBu * 4;

#pragma unroll
        for (int kc = 0; kc < BK_ / 16; kc++) {
            const uint32_t kbyte = (uint32_t)(kc * 8) * 4;

            uint32_t a[4];
            ldsm_x4(a, aBase + aOff + kbyte);

#pragma unroll
            for (int g = 0; g < 5; g++) {
                uint32_t b[4];
                ldsm_x4(b, bBase + bOffBase + (uint32_t)(g * 16 * BKP) * 4 + kbyte);
#pragma unroll
                for (int half = 0; half < 2; half++)
                    mma_fp16(acc[g * 2 + half], a, b[half], b[2 + half]);
            }
        }
        __syncthreads();
    }

    const int r0 = brow + warp * 16 + lg;
#pragma unroll
    for (int nt = 0; nt < 10; nt++) {
        const int c0 = nt * 8 + lq * 2;
        __half2 v0 = __floats2half2_rn(acc[nt][0], acc[nt][1]);
        __half2 v1 = __floats2half2_rn(acc[nt][2], acc[nt][3]);
        *(uint32_t*)(Cf + (long)r0 * ldc + c0)       = *reinterpret_cast<uint32_t*>(&v0);
        *(uint32_t*)(Cf + (long)(r0 + 8) * ldc + c0) = *reinterpret_cast<uint32_t*>(&v1);
    }
}

// ---------------------------------------------------------------------------
// elementwise conversions
// ---------------------------------------------------------------------------
__global__ void split_f16(const float* __restrict__ in,
                          uint16_t* __restrict__ hi, uint16_t* __restrict__ lo,
                          long n)
{
    const long i = (long)blockIdx.x * blockDim.x + threadIdx.x;
    if (i < n) {
        uint16_t h, l;
        split1h(in[i], h, l);
        hi[i] = h;
        lo[i] = l;
    }
}

__global__ void f32_to_f16(const float* __restrict__ in,
                           uint16_t* __restrict__ out, long n)
{
    const long i = (long)blockIdx.x * blockDim.x + threadIdx.x;
    if (i < n) out[i] = f2h(in[i]);
}

// ---------------------------------------------------------------------------
// Rotary + relayout: Q -> fp16 hi/lo [h][s][96], K -> fp16 [h][s][96],
// V -> fp16 [h][d][s]
// ---------------------------------------------------------------------------
__global__ void rotary_relayout(const float* __restrict__ qkv,
                                const float* __restrict__ rope,
                                uint16_t* __restrict__ Qh, uint16_t* __restrict__ Ql,
                                uint16_t* __restrict__ Kf,
                                uint16_t* __restrict__ Vtf)
{
    const int s = blockIdx.x;
    const float* row = qkv + (long)s * QKV_F;

    for (int e = threadIdx.x; e < EMBED; e += blockDim.x) {
        const int h = e / HDIM;
        const int d = e % HDIM;
        const float f = rope[s * (HDIM / 2) + ((d < HDIM / 2) ? d : d - HDIM / 2)];
        float sn, cs;
        sincosf(f, &sn, &cs);

        const float qv = row[e];
        const float kv = row[EMBED + e];
        const float qp = (d < HDIM / 2) ? -row[e + HDIM / 2] : row[e - HDIM / 2];
        const float kp = (d < HDIM / 2) ? -row[EMBED + e + HDIM / 2]
                                        :  row[EMBED + e - HDIM / 2];

        const float qr = qv * cs + qp * sn;
        const float kr = kv * cs + kp * sn;

        const long oq = ((long)h * S_TOTAL + s) * HDIMP + d;
        uint16_t hh, ll;
        split1h(qr, hh, ll);
        Qh[oq] = hh;  Ql[oq] = ll;
        Kf[oq] = f2h(kr);

        Vtf[((long)h * HDIM + d) * S_TOTAL + s] = f2h(row[2 * EMBED + e]);
    }
}

// ---------------------------------------------------------------------------
// Row softmax over 1024 cols; one warp per row; outputs fp16 probs.
// ---------------------------------------------------------------------------
__global__ void softmax_rows(const float* __restrict__ S,
                             uint16_t* __restrict__ Pf)
{
    const long row  = (long)blockIdx.x * 8 + (threadIdx.x >> 5);
    const int  lane = threadIdx.x & 31;
    const float* p = S + row * SEG_LEN;

    float v[32];
    float mx = -INFINITY;
#pragma unroll
    for (int i = 0; i < 32; i++) {
        v[i] = p[lane + i * 32];
        mx = fmaxf(mx, v[i]);
    }
#pragma unroll
    for (int o = 16; o; o >>= 1) mx = fmaxf(mx, __shfl_xor_sync(0xffffffffu, mx, o));

    float sum = 0.f;
#pragma unroll
    for (int i = 0; i < 32; i++) {
        v[i] = __expf(v[i] - mx);
        sum += v[i];
    }
#pragma unroll
    for (int o = 16; o; o >>= 1) sum += __shfl_xor_sync(0xffffffffu, sum, o);

    const float r = 1.f / sum;
    uint16_t* ph = Pf + row * SEG_LEN;
#pragma unroll
    for (int i = 0; i < 32; i++)
        ph[lane + i * 32] = f2h(v[i] * r);
}

// ---------------------------------------------------------------------------
// Entry point
// ---------------------------------------------------------------------------
extern "C" void kernel_launch(void* const* d_in, const int* in_sizes, int n_in,
                              void* d_out, int out_size)
{
    const float* x      = (const float*)d_in[0];
    const float* qkv_w  = (const float*)d_in[1];
    const float* qkv_b  = (const float*)d_in[2];
    const float* proj_w = (const float*)d_in[3];
    const float* proj_b = (const float*)d_in[4];
    const float* rope   = (const float*)d_in[5];
    float* out = (float*)d_out;

    cudaFuncSetAttribute(gemm_f16ax2<64>,
                         cudaFuncAttributeMaxDynamicSharedMemorySize, 2 * STG2B<64>());
    cudaFuncSetAttribute(gemm_f16ax2<32>,
                         cudaFuncAttributeMaxDynamicSharedMemorySize, 2 * STG2B<32>());
    cudaFuncSetAttribute(gemm_fp16<64>,
                         cudaFuncAttributeMaxDynamicSharedMemorySize, 2 * STG1B<64>());
    cudaFuncSetAttribute(gemm_pv80<64>,
                         cudaFuncAttributeMaxDynamicSharedMemorySize, 2 * STG1B<64>());

    float *qkv, *scores;
    uint16_t *xh, *xl, *wf, *pwf;
    uint16_t *Qh, *Ql, *Kf, *Vtf, *Pf, *cf;
    cudaGetSymbolAddress((void**)&qkv,    g_qkv);
    cudaGetSymbolAddress((void**)&scores, g_scores);
    cudaGetSymbolAddress((void**)&xh,  g_xh16);  cudaGetSymbolAddress((void**)&xl, g_xl16);
    cudaGetSymbolAddress((void**)&wf,  g_wf);    cudaGetSymbolAddress((void**)&pwf, g_pwf);
    cudaGetSymbolAddress((void**)&Qh,  g_Qh16);  cudaGetSymbolAddress((void**)&Ql, g_Ql16);
    cudaGetSymbolAddress((void**)&Kf,  g_Kf16);
    cudaGetSymbolAddress((void**)&Vtf, g_Vtf);
    cudaGetSymbolAddress((void**)&Pf,  g_Pf);
    cudaGetSymbolAddress((void**)&cf,  g_cf);

    // 0) conversions
    {
        long n1 = (long)S_TOTAL * EMBED;
        long n2 = (long)QKV_F * EMBED;
        long n3 = (long)EMBED * EMBED;
        split_f16<<<(unsigned)((n1 + 255) / 256), 256>>>(x, xh, xl, n1);
        f32_to_f16<<<(unsigned)((n2 + 255) / 256), 256>>>(qkv_w, wf, n2);
        f32_to_f16<<<(unsigned)((n3 + 255) / 256), 256>>>(proj_w, pwf, n3);
    }

    // 1a) QK part of QKV (fp16 A-split x2, BK=64): qkv[:, 0:2560]
    {
        dim3 grid(QK_F / BN, S_TOTAL / BM, 1);
        gemm_f16ax2<64><<<grid, 256, 2 * STG2B<64>()>>>(xh, xl, wf, qkv_b, qkv,
            QK_F, EMBED, EMBED, EMBED, QKV_F, 0, 0, 0, 0, 0, 0, 1, 1.0f);
    }

    // 1b) V part of QKV (fp16 x1, BK=64): qkv[:, 2560:3840]
    {
        dim3 grid(EMBED / BN, S_TOTAL / BM, 1);
        gemm_fp16<64><<<grid, 256, 2 * STG1B<64>()>>>(xh, wf + (long)QK_F * EMBED,
            qkv_b + QK_F, qkv + QK_F,
            EMBED, EMBED, EMBED, EMBED, QKV_F, 0, 0, 0, 0, 0, 0, 1, 1.0f);
    }

    // 2) rotary + relayout
    rotary_relayout<<<S_TOTAL, 256>>>(qkv, rope, Qh, Ql, Kf, Vtf);

    // 3) scores = scale * Q @ K^T   (fp16 A-split x2, BK=32, K=96)
    const float scale = 0.11180339887498949f; // 1/sqrt(80)
    {
        dim3 grid(SEG_LEN / BN, SEG_LEN / BM, NSEG * HEADS);
        gemm_f16ax2<32><<<grid, 256, 2 * STG2B<32>()>>>(Qh, Ql, Kf, nullptr, scores,
            SEG_LEN, HDIMP, HDIMP, HDIMP, SEG_LEN,
            (long)SEG_LEN * HDIMP, (long)S_TOTAL * HDIMP,
            (long)SEG_LEN * HDIMP, (long)S_TOTAL * HDIMP,
            (long)HEADS * SEG_LEN * SEG_LEN, (long)SEG_LEN * SEG_LEN,
            HEADS, scale);
    }

    // 4) softmax -> fp16 probs
    softmax_rows<<<(NSEG * HEADS * SEG_LEN) / 8, 256>>>(scores, Pf);

    // 5) ctx(fp16) = P @ Vt^T  (exact N=80, BK=64, K=1024)
    {
        dim3 grid(1, SEG_LEN / BM, NSEG * HEADS);
        gemm_pv80<64><<<grid, 256, 2 * STG1B<64>()>>>(Pf, Vtf, cf,
            SEG_LEN, SEG_LEN, S_TOTAL, EMBED,
            (long)HEADS * SEG_LEN * SEG_LEN, (long)SEG_LEN * SEG_LEN,
            (long)SEG_LEN, (long)HDIM * S_TOTAL,
            (long)SEG_LEN * EMBED, (long)HDIM,
            HEADS);
    }

    // 6) out = ctx @ proj_w^T + proj_b  (fp16 x1, BK=64)
    {
        dim3 grid(EMBED / BN, S_TOTAL / BM, 1);
        gemm_fp16<64><<<grid, 256, 2 * STG1B<64>()>>>(cf, pwf, proj_b, out,
            EMBED, EMBED, EMBED, EMBED, EMBED, 0, 0, 0, 0, 0, 0, 1, 1.0f);
    }
}

// round 14
// speedup vs baseline: 2.0987x; 1.2077x over previous
#include <cuda_runtime.h>
#include <cuda_bf16.h>
#include <cuda_fp16.h>
#include <stdint.h>
#include <stddef.h>
#include <math.h>

// Round 14: byte-identical logic to round 13 — that bench died in the GB300
// broker (container failed twice; third infra failure this session, rounds 1
// and 10 resubmissions both ran cleanly). Re-bench for an attributable
// datapoint on the flash-attention fusion.
//
// Under test: scores GEMM + softmax + PV (327 us, 770 MB round-trip at round
// 12) fused into one kernel: per 128 q-rows, loop 16 k-tiles of 64;
// S = (Qh+Ql)@K^T (2-pass fp16), online softmax, P fragments reused as A
// operands for P@V straight from registers. QKV/proj GEMMs identical to
// round 12 (699.8 us).

// ---------------------------------------------------------------------------
// Problem constants
// ---------------------------------------------------------------------------
#define EMBED   1280
#define HEADS   16
#define HDIM    80
#define HDIMP   96            // padded head dim for Q/K (zero tail)
#define S_TOTAL 4096
#define NSEG    4
#define SEG_LEN 1024
#define QKV_F   (3 * EMBED)   // 3840
#define QK_F    (2 * EMBED)   // 2560

// ---------------------------------------------------------------------------
// Scratch
// ---------------------------------------------------------------------------
__device__ float    g_qkv[(size_t)S_TOTAL * QKV_F];

__device__ uint16_t g_xh16[(size_t)S_TOTAL * EMBED], g_xl16[(size_t)S_TOTAL * EMBED];
__device__ uint16_t g_wf[(size_t)QKV_F * EMBED];
__device__ uint16_t g_pwf[(size_t)EMBED * EMBED];
__device__ uint16_t g_Qh16[(size_t)HEADS * S_TOTAL * HDIMP];
__device__ uint16_t g_Ql16[(size_t)HEADS * S_TOTAL * HDIMP];
__device__ uint16_t g_Kf16[(size_t)HEADS * S_TOTAL * HDIMP];
__device__ uint16_t g_Vtf[(size_t)HEADS * HDIM * S_TOTAL];
__device__ uint16_t g_cf[(size_t)S_TOTAL * EMBED];

// ---------------------------------------------------------------------------
// helpers
// ---------------------------------------------------------------------------
__device__ __forceinline__ uint16_t f2h(float x)
{
    __half h = __float2half_rn(x);
    return *reinterpret_cast<uint16_t*>(&h);
}

__device__ __forceinline__ uint32_t pack_h2(float a, float b)
{
    __half2 h = __floats2half2_rn(a, b);
    return *reinterpret_cast<uint32_t*>(&h);
}

__device__ __forceinline__ void split1h(float x, uint16_t& hi, uint16_t& lo)
{
    __half h = __float2half_rn(x);
    float r = x - __half2float(h);
    hi = *reinterpret_cast<uint16_t*>(&h);
    __half l = __float2half_rn(r);
    lo = *reinterpret_cast<uint16_t*>(&l);
}

__device__ __forceinline__ void mma_fp16(float* c, const uint32_t* a,
                                         uint32_t b0, uint32_t b1)
{
    asm volatile(
        "mma.sync.aligned.m16n8k16.row.col.f32.f16.f16.f32 "
        "{%0,%1,%2,%3}, {%4,%5,%6,%7}, {%8,%9}, {%0,%1,%2,%3};"
        : "+f"(c[0]), "+f"(c[1]), "+f"(c[2]), "+f"(c[3])
        : "r"(a[0]), "r"(a[1]), "r"(a[2]), "r"(a[3]), "r"(b0), "r"(b1));
}

__device__ __forceinline__ void ldsm_x4(uint32_t* r, uint32_t addr)
{
    asm volatile("ldmatrix.sync.aligned.m8n8.x4.shared.b16 {%0,%1,%2,%3}, [%4];"
                 : "=r"(r[0]), "=r"(r[1]), "=r"(r[2]), "=r"(r[3]) : "r"(addr));
}

__device__ __forceinline__ void cp_async16(uint32_t dst_smem, const void* src)
{
    asm volatile("cp.async.cg.shared.global [%0], [%1], 16;"
                 :: "r"(dst_smem), "l"(src));
}
__device__ __forceinline__ void cp_async16z(uint32_t dst_smem, const void* src, int src_bytes)
{
    asm volatile("cp.async.cg.shared.global [%0], [%1], 16, %2;"
                 :: "r"(dst_smem), "l"(src), "r"(src_bytes));
}
__device__ __forceinline__ void cp_commit()
{
    asm volatile("cp.async.commit_group;");
}
template <int N>
__device__ __forceinline__ void cp_wait()
{
    asm volatile("cp.async.wait_group %0;" :: "n"(N));
}

// ---------------------------------------------------------------------------
// GEMM tiling (QKV / proj kernels, as round 12)
// ---------------------------------------------------------------------------
#define BM 128
#define BN 128
template <int BK_> struct TileCfg {
    static constexpr int BKP = BK_ / 2 + 4;
    static constexpr int SUBu = 128 * BKP;
    static constexpr int TPR  = BK_ / 8;
    static constexpr int RSTEP = 256 / TPR;
};
template <int BK_> constexpr int STG2B() { return 3 * TileCfg<BK_>::SUBu * 4; }
template <int BK_> constexpr int STG1B() { return 2 * TileCfg<BK_>::SUBu * 4; }

// ---------------------------------------------------------------------------
// fp16 A-split x2 batched GEMM (round 12, unchanged)
// ---------------------------------------------------------------------------
template <int BK_>
__global__ __launch_bounds__(256, 2)
void gemm_f16ax2(const uint16_t* __restrict__ Ah, const uint16_t* __restrict__ Al,
                 const uint16_t* __restrict__ Bf,
                 const float* __restrict__ bias, float* __restrict__ C,
                 int N, int K, int lda, int ldb, int ldc,
                 long oAs, long oAh_, long oBs, long oBh_, long oCs, long oCh_,
                 int nh, float alpha)
{
    using T = TileCfg<BK_>;
    constexpr int BKP = T::BKP;
    constexpr int SUBu = T::SUBu;
    constexpr int STGu = 3 * SUBu;
    extern __shared__ uint32_t sm[];

    const int z   = blockIdx.z;
    const int seg = z / nh;
    const int h   = z % nh;
    Ah += oAs * seg + oAh_ * h;  Al += oAs * seg + oAh_ * h;
    Bf += oBs * seg + oBh_ * h;
    C  += oCs * seg + oCh_ * h;

    const int brow = blockIdx.y * BM;
    const int bcol = blockIdx.x * BN;

    const int tid  = threadIdx.x;
    const int warp = tid >> 5;
    const int lane = tid & 31;
    const int wm = (warp >> 1) * 32;
    const int wn = (warp & 1) * 64;
    const int lg = lane >> 2;
    const int lq = lane & 3;

    const uint32_t smem_base = (uint32_t)__cvta_generic_to_shared(sm);
    const int lm_r = lane & 15;
    const int lm_c = (lane >> 4) * 4;
    const int lrow0 = tid / T::TPR;
    const int chk   = tid % T::TPR;

    float acc[2][8][4];
#pragma unroll
    for (int i = 0; i < 2; i++)
#pragma unroll
        for (int j = 0; j < 8; j++)
#pragma unroll
            for (int q = 0; q < 4; q++) acc[i][j][q] = 0.f;

    const int nit = K / BK_;

    auto load_stage = [&](int stage, int k0) {
        const uint32_t sb = smem_base + (uint32_t)stage * STGu * 4;
#pragma unroll
        for (int row = lrow0; row < 128; row += T::RSTEP) {
            const uint32_t doff = (uint32_t)(row * BKP + chk * 4) * 4;
            const long acol = (long)k0 + chk * 8;
            cp_async16(sb + 0 * SUBu * 4 + doff,
                       Ah + (long)(brow + row) * lda + acol);
            cp_async16(sb + 1 * SUBu * 4 + doff,
                       Al + (long)(brow + row) * lda + acol);
            const int bn  = bcol + row;
            const int ok  = (bn < N) ? 16 : 0;
            const int bno = (bn < N) ? bn : 0;
            cp_async16z(sb + 2 * SUBu * 4 + doff,
                        Bf + (long)bno * ldb + acol, ok);
        }
    };

    load_stage(0, 0);
    cp_commit();

    const uint32_t aOff0 = (uint32_t)((wm + lm_r) * BKP + lm_c) * 4;
    const uint32_t aOff1 = (uint32_t)((wm + 16 + lm_r) * BKP + lm_c) * 4;
    const uint32_t bOffBase = (uint32_t)((wn + lm_r) * BKP + lm_c) * 4;

    for (int it = 0; it < nit; it++) {
        if (it + 1 < nit) {
            load_stage((it + 1) & 1, (it + 1) * BK_);
            cp_commit();
            cp_wait<1>();
        } else {
            cp_wait<0>();
        }
        __syncthreads();

        const uint32_t stageB = smem_base + (uint32_t)(it & 1) * STGu * 4;
        const uint32_t aBaseH = stageB;
        const uint32_t aBaseL = stageB + SUBu * 4;
        const uint32_t bBase  = stageB + 2 * SUBu * 4;

#pragma unroll
        for (int kc = 0; kc < BK_ / 16; kc++) {
            const uint32_t kbyte = (uint32_t)(kc * 8) * 4;

            uint32_t aH[2][4], aL[2][4];
            ldsm_x4(aH[0], aBaseH + aOff0 + kbyte);
            ldsm_x4(aH[1], aBaseH + aOff1 + kbyte);
            ldsm_x4(aL[0], aBaseL + aOff0 + kbyte);
            ldsm_x4(aL[1], aBaseL + aOff1 + kbyte);

            uint32_t b[4][4];
#pragma unroll
            for (int ntp = 0; ntp < 4; ntp++)
                ldsm_x4(b[ntp], bBase + bOffBase + (uint32_t)(ntp * 16 * BKP) * 4 + kbyte);

#pragma unroll
            for (int ntp = 0; ntp < 4; ntp++)
#pragma unroll
                for (int half = 0; half < 2; half++)
#pragma unroll
                    for (int mt = 0; mt < 2; mt++)
                        mma_fp16(acc[mt][ntp * 2 + half], aH[mt],
                                 b[ntp][half], b[ntp][2 + half]);
#pragma unroll
            for (int ntp = 0; ntp < 4; ntp++)
#pragma unroll
                for (int half = 0; half < 2; half++)
#pragma unroll
                    for (int mt = 0; mt < 2; mt++)
                        mma_fp16(acc[mt][ntp * 2 + half], aL[mt],
                                 b[ntp][half], b[ntp][2 + half]);
        }
        __syncthreads();
    }

#pragma unroll
    for (int mt = 0; mt < 2; mt++) {
        const int r0 = brow + wm + mt * 16 + lg;
#pragma unroll
        for (int nt = 0; nt < 8; nt++) {
            const int c0 = bcol + wn + nt * 8 + lq * 2;
            float* p0 = C + (long)r0 * ldc;
            float* p1 = C + (long)(r0 + 8) * ldc;
            const float b0 = bias ? bias[min(c0, N - 1)] : 0.f;
            const float b1 = bias ? bias[min(c0 + 1, N - 1)] : 0.f;
            if (c0 < N) {
                p0[c0] = alpha * acc[mt][nt][0] + b0;
                p1[c0] = alpha * acc[mt][nt][2] + b0;
            }
            if (c0 + 1 < N) {
                p0[c0 + 1] = alpha * acc[mt][nt][1] + b1;
                p1[c0 + 1] = alpha * acc[mt][nt][3] + b1;
            }
        }
    }
}

// ---------------------------------------------------------------------------
// fp16 single-pass batched GEMM (round 12, unchanged)
// ---------------------------------------------------------------------------
template <int BK_>
__global__ __launch_bounds__(256, 2)
void gemm_fp16(const uint16_t* __restrict__ Af, const uint16_t* __restrict__ Bf,
               const float* __restrict__ bias, float* __restrict__ C,
               int N, int K, int lda, int ldb, int ldc,
               long oAs, long oAh_, long oBs, long oBh_, long oCs, long oCh_,
               int nh, float alpha)
{
    using T = TileCfg<BK_>;
    constexpr int BKP = T::BKP;
    constexpr int SUBu = T::SUBu;
    constexpr int STGu = 2 * SUBu;
    extern __shared__ uint32_t sm[];

    const int z   = blockIdx.z;
    const int seg = z / nh;
    const int h   = z % nh;
    Af += oAs * seg + oAh_ * h;
    Bf += oBs * seg + oBh_ * h;
    C  += oCs * seg + oCh_ * h;

    const int brow = blockIdx.y * BM;
    const int bcol = blockIdx.x * BN;

    const int tid  = threadIdx.x;
    const int warp = tid >> 5;
    const int lane = tid & 31;
    const int wm = (warp >> 1) * 32;
    const int wn = (warp & 1) * 64;
    const int lg = lane >> 2;
    const int lq = lane & 3;

    const uint32_t smem_base = (uint32_t)__cvta_generic_to_shared(sm);
    const int lm_r = lane & 15;
    const int lm_c = (lane >> 4) * 4;
    const int lrow0 = tid / T::TPR;
    const int chk   = tid % T::TPR;

    float acc[2][8][4];
#pragma unroll
    for (int i = 0; i < 2; i++)
#pragma unroll
        for (int j = 0; j < 8; j++)
#pragma unroll
            for (int q = 0; q < 4; q++) acc[i][j][q] = 0.f;

    const int nit = K / BK_;

    auto load_stage = [&](int stage, int k0) {
        const uint32_t sb = smem_base + (uint32_t)stage * STGu * 4;
#pragma unroll
        for (int row = lrow0; row < 128; row += T::RSTEP) {
            const uint32_t doff = (uint32_t)(row * BKP + chk * 4) * 4;
            const long acol = (long)k0 + chk * 8;
            cp_async16(sb + 0 * SUBu * 4 + doff,
                       Af + (long)(brow + row) * lda + acol);
            const int bn  = bcol + row;
            const int ok  = (bn < N) ? 16 : 0;
            const int bno = (bn < N) ? bn : 0;
            cp_async16z(sb + 1 * SUBu * 4 + doff,
                        Bf + (long)bno * ldb + acol, ok);
        }
    };

    load_stage(0, 0);
    cp_commit();

    const uint32_t aOff0 = (uint32_t)((wm + lm_r) * BKP + lm_c) * 4;
    const uint32_t aOff1 = (uint32_t)((wm + 16 + lm_r) * BKP + lm_c) * 4;
    const uint32_t bOffBase = (uint32_t)((wn + lm_r) * BKP + lm_c) * 4;

    for (int it = 0; it < nit; it++) {
        if (it + 1 < nit) {
            load_stage((it + 1) & 1, (it + 1) * BK_);
            cp_commit();
            cp_wait<1>();
        } else {
            cp_wait<0>();
        }
        __syncthreads();

        const uint32_t stageB = smem_base + (uint32_t)(it & 1) * STGu * 4;
        const uint32_t aBase = stageB;
        const uint32_t bBase = stageB + SUBu * 4;

#pragma unroll
        for (int kc = 0; kc < BK_ / 16; kc++) {
            const uint32_t kbyte = (uint32_t)(kc * 8) * 4;

            uint32_t a[2][4];
            ldsm_x4(a[0], aBase + aOff0 + kbyte);
            ldsm_x4(a[1], aBase + aOff1 + kbyte);

#pragma unroll
            for (int ntp = 0; ntp < 4; ntp++) {
                uint32_t b[4];
                ldsm_x4(b, bBase + bOffBase + (uint32_t)(ntp * 16 * BKP) * 4 + kbyte);
#pragma unroll
                for (int half = 0; half < 2; half++)
#pragma unroll
                    for (int mt = 0; mt < 2; mt++)
                        mma_fp16(acc[mt][ntp * 2 + half], a[mt],
                                 b[half], b[2 + half]);
            }
        }
        __syncthreads();
    }

#pragma unroll
    for (int mt = 0; mt < 2; mt++) {
        const int r0 = brow + wm + mt * 16 + lg;
#pragma unroll
        for (int nt = 0; nt < 8; nt++) {
            const int c0 = bcol + wn + nt * 8 + lq * 2;
            float* p0 = C + (long)r0 * ldc;
            float* p1 = C + (long)(r0 + 8) * ldc;
            const float b0 = bias ? bias[min(c0, N - 1)] : 0.f;
            const float b1 = bias ? bias[min(c0 + 1, N - 1)] : 0.f;
            if (c0 < N) {
                p0[c0] = alpha * acc[mt][nt][0] + b0;
                p1[c0] = alpha * acc[mt][nt][2] + b0;
            }
            if (c0 + 1 < N) {
                p0[c0 + 1] = alpha * acc[mt][nt][1] + b1;
                p1[c0 + 1] = alpha * acc[mt][nt][3] + b1;
            }
        }
    }
}

// ---------------------------------------------------------------------------
// Flash attention: per block 128 q rows x full head; 16 k-tiles of 64.
//   S = scale*(Qh+Ql)@K^T (fp16 2-pass), online softmax, O += P@V.
//   Warp w owns q rows [w*16, w*16+16). Output fp16 ctx [s][h*80+d].
// smem (bytes): Qh 0 (26624), Ql 26624, K buf 53248 (+13312), V buf 79872 (+11520)
// ---------------------------------------------------------------------------
#define FQT 128
#define FKT 64
#define FNJ (SEG_LEN / FKT)       // 16
#define QKROW 52                  // u32 per Q/K smem row (48 + 4)
#define VROW  36                  // u32 per V smem row (32 + 4)
#define FSQH 0
#define FSQL 26624
#define FSK  53248
#define FSKS 13312
#define FSV  79872
#define FSVS 11520
#define FSMEM_B 102912

__global__ __launch_bounds__(256, 2)
void flash_attn(const uint16_t* __restrict__ Qh, const uint16_t* __restrict__ Ql,
                const uint16_t* __restrict__ Kf, const uint16_t* __restrict__ Vtf,
                uint16_t* __restrict__ Cf)
{
    extern __shared__ uint32_t sm[];
    const uint32_t smem_base = (uint32_t)__cvta_generic_to_shared(sm);

    const int bh  = blockIdx.z;          // seg*HEADS + h
    const int seg = bh / HEADS;
    const int h   = bh % HEADS;
    const int q0  = blockIdx.y * FQT;    // q offset within segment

    const int tid  = threadIdx.x;
    const int warp = tid >> 5;
    const int lane = tid & 31;
    const int lg = lane >> 2;
    const int lq = lane & 3;
    const int lm_r = lane & 15;
    const int lm_c = (lane >> 4) * 4;

    const long qkbase = ((long)h * S_TOTAL + (long)seg * SEG_LEN);

    // ---- load Q (hi+lo) once: 128 rows x 96 fp16 = 12 x 16B chunks/row ----
    for (int c = tid; c < 2 * 128 * 12; c += 256) {
        const int arr = c / 1536;
        const int cc  = c % 1536;
        const int row = cc / 12;
        const int ch  = cc % 12;
        const uint32_t dst = smem_base + (arr ? FSQL : FSQH)
                           + (uint32_t)(row * QKROW) * 4 + ch * 16;
        const uint16_t* src = (arr ? Ql : Qh) + (qkbase + q0 + row) * HDIMP + ch * 8;
        cp_async16(dst, src);
    }
    cp_commit();

    // ---- K/V tile loader ----
    auto load_kv = [&](int buf, int j) {
        const uint32_t kb = smem_base + FSK + (uint32_t)buf * FSKS;
        const uint32_t vb = smem_base + FSV + (uint32_t)buf * FSVS;
        for (int c = tid; c < 64 * 12 + 80 * 8; c += 256) {
            if (c < 768) {
                const int row = c / 12, ch = c % 12;
                cp_async16(kb + (uint32_t)(row * QKROW) * 4 + ch * 16,
                           Kf + (qkbase + (long)j * FKT + row) * HDIMP + ch * 8);
            } else {
                const int v = c - 768;
                const int d = v / 8, ch = v % 8;
                cp_async16(vb + (uint32_t)(d * VROW) * 4 + ch * 16,
                           Vtf + ((long)h * HDIM + d) * S_TOTAL
                               + (long)seg * SEG_LEN + (long)j * FKT + ch * 8);
            }
        }
    };

    load_kv(0, 0);
    cp_commit();
    cp_wait<0>();
    __syncthreads();

    // ---- state ----
    float o[10][4];
#pragma unroll
    for (int g = 0; g < 10; g++)
#pragma unroll
        for (int q = 0; q < 4; q++) o[g][q] = 0.f;
    float m0 = -INFINITY, m1 = -INFINITY, l0 = 0.f, l1 = 0.f;

    const float scale = 0.11180339887498949f; // 1/sqrt(80)
    const uint32_t qOff = (uint32_t)((warp * 16 + lm_r) * QKROW + lm_c) * 4;

    for (int j = 0; j < FNJ; j++) {
        if (j + 1 < FNJ) { load_kv((j + 1) & 1, j + 1); cp_commit(); }

        const uint32_t kB = smem_base + FSK + (uint32_t)(j & 1) * FSKS;
        const uint32_t vB = smem_base + FSV + (uint32_t)(j & 1) * FSVS;

        // ---- S = (Qh+Ql) @ K^T ----
        float s[8][4];
#pragma unroll
        for (int t = 0; t < 8; t++)
#pragma unroll
            for (int q = 0; q < 4; q++) s[t][q] = 0.f;

#pragma unroll
        for (int kc = 0; kc < 6; kc++) {
            const uint32_t kbyte = (uint32_t)kc * 32;
            uint32_t qh[4], ql[4];
            ldsm_x4(qh, smem_base + FSQH + qOff + kbyte);
            ldsm_x4(ql, smem_base + FSQL + qOff + kbyte);
#pragma unroll
            for (int ntp = 0; ntp < 4; ntp++) {
                uint32_t kb[4];
                ldsm_x4(kb, kB + (uint32_t)((ntp * 16 + lm_r) * QKROW + lm_c) * 4 + kbyte);
                mma_fp16(s[2 * ntp],     qh, kb[0], kb[2]);
                mma_fp16(s[2 * ntp + 1], qh, kb[1], kb[3]);
                mma_fp16(s[2 * ntp],     ql, kb[0], kb[2]);
                mma_fp16(s[2 * ntp + 1], ql, kb[1], kb[3]);
            }
        }

        // ---- online softmax (rows r=wq+lg and r+8) ----
        float mt0 = -INFINITY, mt1 = -INFINITY;
#pragma unroll
        for (int t = 0; t < 8; t++) {
            s[t][0] *= scale; s[t][1] *= scale;
            s[t][2] *= scale; s[t][3] *= scale;
            mt0 = fmaxf(mt0, fmaxf(s[t][0], s[t][1]));
            mt1 = fmaxf(mt1, fmaxf(s[t][2], s[t][3]));
        }
        mt0 = fmaxf(mt0, __shfl_xor_sync(0xffffffffu, mt0, 1));
        mt0 = fmaxf(mt0, __shfl_xor_sync(0xffffffffu, mt0, 2));
        mt1 = fmaxf(mt1, __shfl_xor_sync(0xffffffffu, mt1, 1));
        mt1 = fmaxf(mt1, __shfl_xor_sync(0xffffffffu, mt1, 2));

        const float mn0 = fmaxf(m0, mt0);
        const float mn1 = fmaxf(m1, mt1);
        const float c0 = __expf(m0 - mn0);
        const float c1 = __expf(m1 - mn1);
        m0 = mn0; m1 = mn1;

        float ls0 = 0.f, ls1 = 0.f;
#pragma unroll
        for (int t = 0; t < 8; t++) {
            s[t][0] = __expf(s[t][0] - mn0);
            s[t][1] = __expf(s[t][1] - mn0);
            s[t][2] = __expf(s[t][2] - mn1);
            s[t][3] = __expf(s[t][3] - mn1);
            ls0 += s[t][0] + s[t][1];
            ls1 += s[t][2] + s[t][3];
        }
        ls0 += __shfl_xor_sync(0xffffffffu, ls0, 1);
        ls0 += __shfl_xor_sync(0xffffffffu, ls0, 2);
        ls1 += __shfl_xor_sync(0xffffffffu, ls1, 1);
        ls1 += __shfl_xor_sync(0xffffffffu, ls1, 2);
        l0 = l0 * c0 + ls0;
        l1 = l1 * c1 + ls1;

#pragma unroll
        for (int g = 0; g < 10; g++) {
            o[g][0] *= c0; o[g][1] *= c0;
            o[g][2] *= c1; o[g][3] *= c1;
        }

        // ---- O += P @ V  (P fragments straight from registers) ----
#pragma unroll
        for (int u = 0; u < 4; u++) {
            uint32_t pa[4];
            pa[0] = pack_h2(s[2 * u][0],     s[2 * u][1]);
            pa[1] = pack_h2(s[2 * u][2],     s[2 * u][3]);
            pa[2] = pack_h2(s[2 * u + 1][0], s[2 * u + 1][1]);
            pa[3] = pack_h2(s[2 * u + 1][2], s[2 * u + 1][3]);
#pragma unroll
            for (int g = 0; g < 5; g++) {
                uint32_t vb[4];
                ldsm_x4(vb, vB + (uint32_t)((g * 16 + lm_r) * VROW + lm_c) * 4
                            + (uint32_t)u * 32);
                mma_fp16(o[2 * g],     pa, vb[0], vb[2]);
                mma_fp16(o[2 * g + 1], pa, vb[1], vb[3]);
            }
        }

        if (j + 1 < FNJ) cp_wait<0>();
        __syncthreads();
    }

    // ---- epilogue: O /= l, fp16 out ----
    const float r0inv = 1.f / l0;
    const float r1inv = 1.f / l1;
    const long qrow = (long)seg * SEG_LEN + q0 + warp * 16 + lg;
    uint16_t* out0 = Cf + qrow * EMBED + h * HDIM;
    uint16_t* out1 = out0 + 8 * EMBED;
#pragma unroll
    for (int g = 0; g < 10; g++) {
        const int c0 = g * 8 + lq * 2;
        const uint32_t v0 = pack_h2(o[g][0] * r0inv, o[g][1] * r0inv);
        const uint32_t v1 = pack_h2(o[g][2] * r1inv, o[g][3] * r1inv);
        *(uint32_t*)(out0 + c0) = v0;
        *(uint32_t*)(out1 + c0) = v1;
    }
}

// ---------------------------------------------------------------------------
// elementwise conversions
// ---------------------------------------------------------------------------
__global__ void split_f16(const float* __restrict__ in,
                          uint16_t* __restrict__ hi, uint16_t* __restrict__ lo,
                          long n)
{
    const long i = (long)blockIdx.x * blockDim.x + threadIdx.x;
    if (i < n) {
        uint16_t h, l;
        split1h(in[i], h, l);
        hi[i] = h;
        lo[i] = l;
    }
}

__global__ void f32_to_f16(const float* __restrict__ in,
                           uint16_t* __restrict__ out, long n)
{
    const long i = (long)blockIdx.x * blockDim.x + threadIdx.x;
    if (i < n) out[i] = f2h(in[i]);
}

// ---------------------------------------------------------------------------
// Rotary + relayout: Q -> fp16 hi/lo [h][s][96], K -> fp16 [h][s][96],
// V -> fp16 [h][d][s]
// ---------------------------------------------------------------------------
__global__ void rotary_relayout(const float* __restrict__ qkv,
                                const float* __restrict__ rope,
                                uint16_t* __restrict__ Qh, uint16_t* __restrict__ Ql,
                                uint16_t* __restrict__ Kf,
                                uint16_t* __restrict__ Vtf)
{
    const int s = blockIdx.x;
    const float* row = qkv + (long)s * QKV_F;

    for (int e = threadIdx.x; e < EMBED; e += blockDim.x) {
        const int h = e / HDIM;
        const int d = e % HDIM;
        const float f = rope[s * (HDIM / 2) + ((d < HDIM / 2) ? d : d - HDIM / 2)];
        float sn, cs;
        sincosf(f, &sn, &cs);

        const float qv = row[e];
        const float kv = row[EMBED + e];
        const float qp = (d < HDIM / 2) ? -row[e + HDIM / 2] : row[e - HDIM / 2];
        const float kp = (d < HDIM / 2) ? -row[EMBED + e + HDIM / 2]
                                        :  row[EMBED + e - HDIM / 2];

        const float qr = qv * cs + qp * sn;
        const float kr = kv * cs + kp * sn;

        const long oq = ((long)h * S_TOTAL + s) * HDIMP + d;
        uint16_t hh, ll;
        split1h(qr, hh, ll);
        Qh[oq] = hh;  Ql[oq] = ll;
        Kf[oq] = f2h(kr);

        Vtf[((long)h * HDIM + d) * S_TOTAL + s] = f2h(row[2 * EMBED + e]);
    }
}

// ---------------------------------------------------------------------------
// Entry point
// ---------------------------------------------------------------------------
extern "C" void kernel_launch(void* const* d_in, const int* in_sizes, int n_in,
                              void* d_out, int out_size)
{
    const float* x      = (const float*)d_in[0];
    const float* qkv_w  = (const float*)d_in[1];
    const float* qkv_b  = (const float*)d_in[2];
    const float* proj_w = (const float*)d_in[3];
    const float* proj_b = (const float*)d_in[4];
    const float* rope   = (const float*)d_in[5];
    float* out = (float*)d_out;

    cudaFuncSetAttribute(gemm_f16ax2<64>,
                         cudaFuncAttributeMaxDynamicSharedMemorySize, 2 * STG2B<64>());
    cudaFuncSetAttribute(gemm_fp16<64>,
                         cudaFuncAttributeMaxDynamicSharedMemorySize, 2 * STG1B<64>());
    cudaFuncSetAttribute(flash_attn,
                         cudaFuncAttributeMaxDynamicSharedMemorySize, FSMEM_B);

    float* qkv;
    uint16_t *xh, *xl, *wf, *pwf;
    uint16_t *Qh, *Ql, *Kf, *Vtf, *cf;
    cudaGetSymbolAddress((void**)&qkv, g_qkv);
    cudaGetSymbolAddress((void**)&xh,  g_xh16);  cudaGetSymbolAddress((void**)&xl, g_xl16);
    cudaGetSymbolAddress((void**)&wf,  g_wf);    cudaGetSymbolAddress((void**)&pwf, g_pwf);
    cudaGetSymbolAddress((void**)&Qh,  g_Qh16);  cudaGetSymbolAddress((void**)&Ql, g_Ql16);
    cudaGetSymbolAddress((void**)&Kf,  g_Kf16);
    cudaGetSymbolAddress((void**)&Vtf, g_Vtf);
    cudaGetSymbolAddress((void**)&cf,  g_cf);

    // 0) conversions
    {
        long n1 = (long)S_TOTAL * EMBED;
        long n2 = (long)QKV_F * EMBED;
        long n3 = (long)EMBED * EMBED;
        split_f16<<<(unsigned)((n1 + 255) / 256), 256>>>(x, xh, xl, n1);
        f32_to_f16<<<(unsigned)((n2 + 255) / 256), 256>>>(qkv_w, wf, n2);
        f32_to_f16<<<(unsigned)((n3 + 255) / 256), 256>>>(proj_w, pwf, n3);
    }

    // 1a) QK part of QKV (fp16 A-split x2, BK=64)
    {
        dim3 grid(QK_F / BN, S_TOTAL / BM, 1);
        gemm_f16ax2<64><<<grid, 256, 2 * STG2B<64>()>>>(xh, xl, wf, qkv_b, qkv,
            QK_F, EMBED, EMBED, EMBED, QKV_F, 0, 0, 0, 0, 0, 0, 1, 1.0f);
    }

    // 1b) V part of QKV (fp16 x1, BK=64)
    {
        dim3 grid(EMBED / BN, S_TOTAL / BM, 1);
        gemm_fp16<64><<<grid, 256, 2 * STG1B<64>()>>>(xh, wf + (long)QK_F * EMBED,
            qkv_b + QK_F, qkv + QK_F,
            EMBED, EMBED, EMBED, EMBED, QKV_F, 0, 0, 0, 0, 0, 0, 1, 1.0f);
    }

    // 2) rotary + relayout
    rotary_relayout<<<S_TOTAL, 256>>>(qkv, rope, Qh, Ql, Kf, Vtf);

    // 3) fused attention -> fp16 ctx
    {
        dim3 grid(1, SEG_LEN / FQT, NSEG * HEADS);
        flash_attn<<<grid, 256, FSMEM_B>>>(Qh, Ql, Kf, Vtf, cf);
    }

    // 4) out = ctx @ proj_w^T + proj_b  (fp16 x1, BK=64)
    {
        dim3 grid(EMBED / BN, S_TOTAL / BM, 1);
        gemm_fp16<64><<<grid, 256, 2 * STG1B<64>()>>>(cf, pwf, proj_b, out,
            EMBED, EMBED, EMBED, EMBED, EMBED, 0, 0, 0, 0, 0, 0, 1, 1.0f);
    }
}

// round 15
// speedup vs baseline: 2.1057x; 1.0033x over previous
#include <cuda_runtime.h>
#include <cuda_bf16.h>
#include <cuda_fp16.h>
#include <stdint.h>
#include <stddef.h>
#include <math.h>

// Round 14: byte-identical logic to round 13 — that bench died in the GB300
// broker (container failed twice; third infra failure this session, rounds 1
// and 10 resubmissions both ran cleanly). Re-bench for an attributable
// datapoint on the flash-attention fusion.
//
// Under test: scores GEMM + softmax + PV (327 us, 770 MB round-trip at round
// 12) fused into one kernel: per 128 q-rows, loop 16 k-tiles of 64;
// S = (Qh+Ql)@K^T (2-pass fp16), online softmax, P fragments reused as A
// operands for P@V straight from registers. QKV/proj GEMMs identical to
// round 12 (699.8 us).

// ---------------------------------------------------------------------------
// Problem constants
// ---------------------------------------------------------------------------
#define EMBED   1280
#define HEADS   16
#define HDIM    80
#define HDIMP   96            // padded head dim for Q/K (zero tail)
#define S_TOTAL 4096
#define NSEG    4
#define SEG_LEN 1024
#define QKV_F   (3 * EMBED)   // 3840
#define QK_F    (2 * EMBED)   // 2560

// ---------------------------------------------------------------------------
// Scratch
// ---------------------------------------------------------------------------
__device__ float    g_qkv[(size_t)S_TOTAL * QKV_F];

__device__ uint16_t g_xh16[(size_t)S_TOTAL * EMBED], g_xl16[(size_t)S_TOTAL * EMBED];
__device__ uint16_t g_wf[(size_t)QKV_F * EMBED];
__device__ uint16_t g_pwf[(size_t)EMBED * EMBED];
__device__ uint16_t g_Qh16[(size_t)HEADS * S_TOTAL * HDIMP];
__device__ uint16_t g_Ql16[(size_t)HEADS * S_TOTAL * HDIMP];
__device__ uint16_t g_Kf16[(size_t)HEADS * S_TOTAL * HDIMP];
__device__ uint16_t g_Vtf[(size_t)HEADS * HDIM * S_TOTAL];
__device__ uint16_t g_cf[(size_t)S_TOTAL * EMBED];

// ---------------------------------------------------------------------------
// helpers
// ---------------------------------------------------------------------------
__device__ __forceinline__ uint16_t f2h(float x)
{
    __half h = __float2half_rn(x);
    return *reinterpret_cast<uint16_t*>(&h);
}

__device__ __forceinline__ uint32_t pack_h2(float a, float b)
{
    __half2 h = __floats2half2_rn(a, b);
    return *reinterpret_cast<uint32_t*>(&h);
}

__device__ __forceinline__ void split1h(float x, uint16_t& hi, uint16_t& lo)
{
    __half h = __float2half_rn(x);
    float r = x - __half2float(h);
    hi = *reinterpret_cast<uint16_t*>(&h);
    __half l = __float2half_rn(r);
    lo = *reinterpret_cast<uint16_t*>(&l);
}

__device__ __forceinline__ void mma_fp16(float* c, const uint32_t* a,
                                         uint32_t b0, uint32_t b1)
{
    asm volatile(
        "mma.sync.aligned.m16n8k16.row.col.f32.f16.f16.f32 "
        "{%0,%1,%2,%3}, {%4,%5,%6,%7}, {%8,%9}, {%0,%1,%2,%3};"
        : "+f"(c[0]), "+f"(c[1]), "+f"(c[2]), "+f"(c[3])
        : "r"(a[0]), "r"(a[1]), "r"(a[2]), "r"(a[3]), "r"(b0), "r"(b1));
}

__device__ __forceinline__ void ldsm_x4(uint32_t* r, uint32_t addr)
{
    asm volatile("ldmatrix.sync.aligned.m8n8.x4.shared.b16 {%0,%1,%2,%3}, [%4];"
                 : "=r"(r[0]), "=r"(r[1]), "=r"(r[2]), "=r"(r[3]) : "r"(addr));
}

__device__ __forceinline__ void cp_async16(uint32_t dst_smem, const void* src)
{
    asm volatile("cp.async.cg.shared.global [%0], [%1], 16;"
                 :: "r"(dst_smem), "l"(src));
}
__device__ __forceinline__ void cp_async16z(uint32_t dst_smem, const void* src, int src_bytes)
{
    asm volatile("cp.async.cg.shared.global [%0], [%1], 16, %2;"
                 :: "r"(dst_smem), "l"(src), "r"(src_bytes));
}
__device__ __forceinline__ void cp_commit()
{
    asm volatile("cp.async.commit_group;");
}
template <int N>
__device__ __forceinline__ void cp_wait()
{
    asm volatile("cp.async.wait_group %0;" :: "n"(N));
}

// ---------------------------------------------------------------------------
// GEMM tiling (QKV / proj kernels, as round 12)
// ---------------------------------------------------------------------------
#define BM 128
#define BN 128
template <int BK_> struct TileCfg {
    static constexpr int BKP = BK_ / 2 + 4;
    static constexpr int SUBu = 128 * BKP;
    static constexpr int TPR  = BK_ / 8;
    static constexpr int RSTEP = 256 / TPR;
};
template <int BK_> constexpr int STG2B() { return 3 * TileCfg<BK_>::SUBu * 4; }
template <int BK_> constexpr int STG1B() { return 2 * TileCfg<BK_>::SUBu * 4; }

// ---------------------------------------------------------------------------
// fp16 A-split x2 batched GEMM (round 12, unchanged)
// ---------------------------------------------------------------------------
template <int BK_>
__global__ __launch_bounds__(256, 2)
void gemm_f16ax2(const uint16_t* __restrict__ Ah, const uint16_t* __restrict__ Al,
                 const uint16_t* __restrict__ Bf,
                 const float* __restrict__ bias, float* __restrict__ C,
                 int N, int K, int lda, int ldb, int ldc,
                 long oAs, long oAh_, long oBs, long oBh_, long oCs, long oCh_,
                 int nh, float alpha)
{
    using T = TileCfg<BK_>;
    constexpr int BKP = T::BKP;
    constexpr int SUBu = T::SUBu;
    constexpr int STGu = 3 * SUBu;
    extern __shared__ uint32_t sm[];

    const int z   = blockIdx.z;
    const int seg = z / nh;
    const int h   = z % nh;
    Ah += oAs * seg + oAh_ * h;  Al += oAs * seg + oAh_ * h;
    Bf += oBs * seg + oBh_ * h;
    C  += oCs * seg + oCh_ * h;

    const int brow = blockIdx.y * BM;
    const int bcol = blockIdx.x * BN;

    const int tid  = threadIdx.x;
    const int warp = tid >> 5;
    const int lane = tid & 31;
    const int wm = (warp >> 1) * 32;
    const int wn = (warp & 1) * 64;
    const int lg = lane >> 2;
    const int lq = lane & 3;

    const uint32_t smem_base = (uint32_t)__cvta_generic_to_shared(sm);
    const int lm_r = lane & 15;
    const int lm_c = (lane >> 4) * 4;
    const int lrow0 = tid / T::TPR;
    const int chk   = tid % T::TPR;

    float acc[2][8][4];
#pragma unroll
    for (int i = 0; i < 2; i++)
#pragma unroll
        for (int j = 0; j < 8; j++)
#pragma unroll
            for (int q = 0; q < 4; q++) acc[i][j][q] = 0.f;

    const int nit = K / BK_;

    auto load_stage = [&](int stage, int k0) {
        const uint32_t sb = smem_base + (uint32_t)stage * STGu * 4;
#pragma unroll
        for (int row = lrow0; row < 128; row += T::RSTEP) {
            const uint32_t doff = (uint32_t)(row * BKP + chk * 4) * 4;
            const long acol = (long)k0 + chk * 8;
            cp_async16(sb + 0 * SUBu * 4 + doff,
                       Ah + (long)(brow + row) * lda + acol);
            cp_async16(sb + 1 * SUBu * 4 + doff,
                       Al + (long)(brow + row) * lda + acol);
            const int bn  = bcol + row;
            const int ok  = (bn < N) ? 16 : 0;
            const int bno = (bn < N) ? bn : 0;
            cp_async16z(sb + 2 * SUBu * 4 + doff,
                        Bf + (long)bno * ldb + acol, ok);
        }
    };

    load_stage(0, 0);
    cp_commit();

    const uint32_t aOff0 = (uint32_t)((wm + lm_r) * BKP + lm_c) * 4;
    const uint32_t aOff1 = (uint32_t)((wm + 16 + lm_r) * BKP + lm_c) * 4;
    const uint32_t bOffBase = (uint32_t)((wn + lm_r) * BKP + lm_c) * 4;

    for (int it = 0; it < nit; it++) {
        if (it + 1 < nit) {
            load_stage((it + 1) & 1, (it + 1) * BK_);
            cp_commit();
            cp_wait<1>();
        } else {
            cp_wait<0>();
        }
        __syncthreads();

        const uint32_t stageB = smem_base + (uint32_t)(it & 1) * STGu * 4;
        const uint32_t aBaseH = stageB;
        const uint32_t aBaseL = stageB + SUBu * 4;
        const uint32_t bBase  = stageB + 2 * SUBu * 4;

#pragma unroll
        for (int kc = 0; kc < BK_ / 16; kc++) {
            const uint32_t kbyte = (uint32_t)(kc * 8) * 4;

            uint32_t aH[2][4], aL[2][4];
            ldsm_x4(aH[0], aBaseH + aOff0 + kbyte);
            ldsm_x4(aH[1], aBaseH + aOff1 + kbyte);
            ldsm_x4(aL[0], aBaseL + aOff0 + kbyte);
            ldsm_x4(aL[1], aBaseL + aOff1 + kbyte);

            uint32_t b[4][4];
#pragma unroll
            for (int ntp = 0; ntp < 4; ntp++)
                ldsm_x4(b[ntp], bBase + bOffBase + (uint32_t)(ntp * 16 * BKP) * 4 + kbyte);

#pragma unroll
            for (int ntp = 0; ntp < 4; ntp++)
#pragma unroll
                for (int half = 0; half < 2; half++)
#pragma unroll
                    for (int mt = 0; mt < 2; mt++)
                        mma_fp16(acc[mt][ntp * 2 + half], aH[mt],
                                 b[ntp][half], b[ntp][2 + half]);
#pragma unroll
            for (int ntp = 0; ntp < 4; ntp++)
#pragma unroll
                for (int half = 0; half < 2; half++)
#pragma unroll
                    for (int mt = 0; mt < 2; mt++)
                        mma_fp16(acc[mt][ntp * 2 + half], aL[mt],
                                 b[ntp][half], b[ntp][2 + half]);
        }
        __syncthreads();
    }

#pragma unroll
    for (int mt = 0; mt < 2; mt++) {
        const int r0 = brow + wm + mt * 16 + lg;
#pragma unroll
        for (int nt = 0; nt < 8; nt++) {
            const int c0 = bcol + wn + nt * 8 + lq * 2;
            float* p0 = C + (long)r0 * ldc;
            float* p1 = C + (long)(r0 + 8) * ldc;
            const float b0 = bias ? bias[min(c0, N - 1)] : 0.f;
            const float b1 = bias ? bias[min(c0 + 1, N - 1)] : 0.f;
            if (c0 < N) {
                p0[c0] = alpha * acc[mt][nt][0] + b0;
                p1[c0] = alpha * acc[mt][nt][2] + b0;
            }
            if (c0 + 1 < N) {
                p0[c0 + 1] = alpha * acc[mt][nt][1] + b1;
                p1[c0 + 1] = alpha * acc[mt][nt][3] + b1;
            }
        }
    }
}

// ---------------------------------------------------------------------------
// fp16 single-pass batched GEMM (round 12, unchanged)
// ---------------------------------------------------------------------------
template <int BK_>
__global__ __launch_bounds__(256, 2)
void gemm_fp16(const uint16_t* __restrict__ Af, const uint16_t* __restrict__ Bf,
               const float* __restrict__ bias, float* __restrict__ C,
               int N, int K, int lda, int ldb, int ldc,
               long oAs, long oAh_, long oBs, long oBh_, long oCs, long oCh_,
               int nh, float alpha)
{
    using T = TileCfg<BK_>;
    constexpr int BKP = T::BKP;
    constexpr int SUBu = T::SUBu;
    constexpr int STGu = 2 * SUBu;
    extern __shared__ uint32_t sm[];

    const int z   = blockIdx.z;
    const int seg = z / nh;
    const int h   = z % nh;
    Af += oAs * seg + oAh_ * h;
    Bf += oBs * seg + oBh_ * h;
    C  += oCs * seg + oCh_ * h;

    const int brow = blockIdx.y * BM;
    const int bcol = blockIdx.x * BN;

    const int tid  = threadIdx.x;
    const int warp = tid >> 5;
    const int lane = tid & 31;
    const int wm = (warp >> 1) * 32;
    const int wn = (warp & 1) * 64;
    const int lg = lane >> 2;
    const int lq = lane & 3;

    const uint32_t smem_base = (uint32_t)__cvta_generic_to_shared(sm);
    const int lm_r = lane & 15;
    const int lm_c = (lane >> 4) * 4;
    const int lrow0 = tid / T::TPR;
    const int chk   = tid % T::TPR;

    float acc[2][8][4];
#pragma unroll
    for (int i = 0; i < 2; i++)
#pragma unroll
        for (int j = 0; j < 8; j++)
#pragma unroll
            for (int q = 0; q < 4; q++) acc[i][j][q] = 0.f;

    const int nit = K / BK_;

    auto load_stage = [&](int stage, int k0) {
        const uint32_t sb = smem_base + (uint32_t)stage * STGu * 4;
#pragma unroll
        for (int row = lrow0; row < 128; row += T::RSTEP) {
            const uint32_t doff = (uint32_t)(row * BKP + chk * 4) * 4;
            const long acol = (long)k0 + chk * 8;
            cp_async16(sb + 0 * SUBu * 4 + doff,
                       Af + (long)(brow + row) * lda + acol);
            const int bn  = bcol + row;
            const int ok  = (bn < N) ? 16 : 0;
            const int bno = (bn < N) ? bn : 0;
            cp_async16z(sb + 1 * SUBu * 4 + doff,
                        Bf + (long)bno * ldb + acol, ok);
        }
    };

    load_stage(0, 0);
    cp_commit();

    const uint32_t aOff0 = (uint32_t)((wm + lm_r) * BKP + lm_c) * 4;
    const uint32_t aOff1 = (uint32_t)((wm + 16 + lm_r) * BKP + lm_c) * 4;
    const uint32_t bOffBase = (uint32_t)((wn + lm_r) * BKP + lm_c) * 4;

    for (int it = 0; it < nit; it++) {
        if (it + 1 < nit) {
            load_stage((it + 1) & 1, (it + 1) * BK_);
            cp_commit();
            cp_wait<1>();
        } else {
            cp_wait<0>();
        }
        __syncthreads();

        const uint32_t stageB = smem_base + (uint32_t)(it & 1) * STGu * 4;
        const uint32_t aBase = stageB;
        const uint32_t bBase = stageB + SUBu * 4;

#pragma unroll
        for (int kc = 0; kc < BK_ / 16; kc++) {
            const uint32_t kbyte = (uint32_t)(kc * 8) * 4;

            uint32_t a[2][4];
            ldsm_x4(a[0], aBase + aOff0 + kbyte);
            ldsm_x4(a[1], aBase + aOff1 + kbyte);

#pragma unroll
            for (int ntp = 0; ntp < 4; ntp++) {
                uint32_t b[4];
                ldsm_x4(b, bBase + bOffBase + (uint32_t)(ntp * 16 * BKP) * 4 + kbyte);
#pragma unroll
                for (int half = 0; half < 2; half++)
#pragma unroll
                    for (int mt = 0; mt < 2; mt++)
                        mma_fp16(acc[mt][ntp * 2 + half], a[mt],
                                 b[half], b[2 + half]);
            }
        }
        __syncthreads();
    }

#pragma unroll
    for (int mt = 0; mt < 2; mt++) {
        const int r0 = brow + wm + mt * 16 + lg;
#pragma unroll
        for (int nt = 0; nt < 8; nt++) {
            const int c0 = bcol + wn + nt * 8 + lq * 2;
            float* p0 = C + (long)r0 * ldc;
            float* p1 = C + (long)(r0 + 8) * ldc;
            const float b0 = bias ? bias[min(c0, N - 1)] : 0.f;
            const float b1 = bias ? bias[min(c0 + 1, N - 1)] : 0.f;
            if (c0 < N) {
                p0[c0] = alpha * acc[mt][nt][0] + b0;
                p1[c0] = alpha * acc[mt][nt][2] + b0;
            }
            if (c0 + 1 < N) {
                p0[c0 + 1] = alpha * acc[mt][nt][1] + b1;
                p1[c0 + 1] = alpha * acc[mt][nt][3] + b1;
            }
        }
    }
}

// ---------------------------------------------------------------------------
// Flash attention: per block 128 q rows x full head; 16 k-tiles of 64.
//   S = scale*(Qh+Ql)@K^T (fp16 2-pass), online softmax, O += P@V.
//   Warp w owns q rows [w*16, w*16+16). Output fp16 ctx [s][h*80+d].
// smem (bytes): Qh 0 (26624), Ql 26624, K buf 53248 (+13312), V buf 79872 (+11520)
// ---------------------------------------------------------------------------
#define FQT 128
#define FKT 64
#define FNJ (SEG_LEN / FKT)       // 16
#define QKROW 52                  // u32 per Q/K smem row (48 + 4)
#define VROW  36                  // u32 per V smem row (32 + 4)
#define FSQH 0
#define FSQL 26624
#define FSK  53248
#define FSKS 13312
#define FSV  79872
#define FSVS 11520
#define FSMEM_B 102912

__global__ __launch_bounds__(256, 2)
void flash_attn(const uint16_t* __restrict__ Qh, const uint16_t* __restrict__ Ql,
                const uint16_t* __restrict__ Kf, const uint16_t* __restrict__ Vtf,
                uint16_t* __restrict__ Cf)
{
    extern __shared__ uint32_t sm[];
    const uint32_t smem_base = (uint32_t)__cvta_generic_to_shared(sm);

    const int bh  = blockIdx.z;          // seg*HEADS + h
    const int seg = bh / HEADS;
    const int h   = bh % HEADS;
    const int q0  = blockIdx.y * FQT;    // q offset within segment

    const int tid  = threadIdx.x;
    const int warp = tid >> 5;
    const int lane = tid & 31;
    const int lg = lane >> 2;
    const int lq = lane & 3;
    const int lm_r = lane & 15;
    const int lm_c = (lane >> 4) * 4;

    const long qkbase = ((long)h * S_TOTAL + (long)seg * SEG_LEN);

    // ---- load Q (hi+lo) once: 128 rows x 96 fp16 = 12 x 16B chunks/row ----
    for (int c = tid; c < 2 * 128 * 12; c += 256) {
        const int arr = c / 1536;
        const int cc  = c % 1536;
        const int row = cc / 12;
        const int ch  = cc % 12;
        const uint32_t dst = smem_base + (arr ? FSQL : FSQH)
                           + (uint32_t)(row * QKROW) * 4 + ch * 16;
        const uint16_t* src = (arr ? Ql : Qh) + (qkbase + q0 + row) * HDIMP + ch * 8;
        cp_async16(dst, src);
    }
    cp_commit();

    // ---- K/V tile loader ----
    auto load_kv = [&](int buf, int j) {
        const uint32_t kb = smem_base + FSK + (uint32_t)buf * FSKS;
        const uint32_t vb = smem_base + FSV + (uint32_t)buf * FSVS;
        for (int c = tid; c < 64 * 12 + 80 * 8; c += 256) {
            if (c < 768) {
                const int row = c / 12, ch = c % 12;
                cp_async16(kb + (uint32_t)(row * QKROW) * 4 + ch * 16,
                           Kf + (qkbase + (long)j * FKT + row) * HDIMP + ch * 8);
            } else {
                const int v = c - 768;
                const int d = v / 8, ch = v % 8;
                cp_async16(vb + (uint32_t)(d * VROW) * 4 + ch * 16,
                           Vtf + ((long)h * HDIM + d) * S_TOTAL
                               + (long)seg * SEG_LEN + (long)j * FKT + ch * 8);
            }
        }
    };

    load_kv(0, 0);
    cp_commit();
    cp_wait<0>();
    __syncthreads();

    // ---- state ----
    float o[10][4];
#pragma unroll
    for (int g = 0; g < 10; g++)
#pragma unroll
        for (int q = 0; q < 4; q++) o[g][q] = 0.f;
    float m0 = -INFINITY, m1 = -INFINITY, l0 = 0.f, l1 = 0.f;

    const float scale = 0.11180339887498949f; // 1/sqrt(80)
    const uint32_t qOff = (uint32_t)((warp * 16 + lm_r) * QKROW + lm_c) * 4;

    for (int j = 0; j < FNJ; j++) {
        if (j + 1 < FNJ) { load_kv((j + 1) & 1, j + 1); cp_commit(); }

        const uint32_t kB = smem_base + FSK + (uint32_t)(j & 1) * FSKS;
        const uint32_t vB = smem_base + FSV + (uint32_t)(j & 1) * FSVS;

        // ---- S = (Qh+Ql) @ K^T ----
        float s[8][4];
#pragma unroll
        for (int t = 0; t < 8; t++)
#pragma unroll
            for (int q = 0; q < 4; q++) s[t][q] = 0.f;

#pragma unroll
        for (int kc = 0; kc < 6; kc++) {
            const uint32_t kbyte = (uint32_t)kc * 32;
            uint32_t qh[4], ql[4];
            ldsm_x4(qh, smem_base + FSQH + qOff + kbyte);
            ldsm_x4(ql, smem_base + FSQL + qOff + kbyte);
#pragma unroll
            for (int ntp = 0; ntp < 4; ntp++) {
                uint32_t kb[4];
                ldsm_x4(kb, kB + (uint32_t)((ntp * 16 + lm_r) * QKROW + lm_c) * 4 + kbyte);
                mma_fp16(s[2 * ntp],     qh, kb[0], kb[2]);
                mma_fp16(s[2 * ntp + 1], qh, kb[1], kb[3]);
                mma_fp16(s[2 * ntp],     ql, kb[0], kb[2]);
                mma_fp16(s[2 * ntp + 1], ql, kb[1], kb[3]);
            }
        }

        // ---- online softmax (rows r=wq+lg and r+8) ----
        float mt0 = -INFINITY, mt1 = -INFINITY;
#pragma unroll
        for (int t = 0; t < 8; t++) {
            s[t][0] *= scale; s[t][1] *= scale;
            s[t][2] *= scale; s[t][3] *= scale;
            mt0 = fmaxf(mt0, fmaxf(s[t][0], s[t][1]));
            mt1 = fmaxf(mt1, fmaxf(s[t][2], s[t][3]));
        }
        mt0 = fmaxf(mt0, __shfl_xor_sync(0xffffffffu, mt0, 1));
        mt0 = fmaxf(mt0, __shfl_xor_sync(0xffffffffu, mt0, 2));
        mt1 = fmaxf(mt1, __shfl_xor_sync(0xffffffffu, mt1, 1));
        mt1 = fmaxf(mt1, __shfl_xor_sync(0xffffffffu, mt1, 2));

        const float mn0 = fmaxf(m0, mt0);
        const float mn1 = fmaxf(m1, mt1);
        const float c0 = __expf(m0 - mn0);
        const float c1 = __expf(m1 - mn1);
        m0 = mn0; m1 = mn1;

        float ls0 = 0.f, ls1 = 0.f;
#pragma unroll
        for (int t = 0; t < 8; t++) {
            s[t][0] = __expf(s[t][0] - mn0);
            s[t][1] = __expf(s[t][1] - mn0);
            s[t][2] = __expf(s[t][2] - mn1);
            s[t][3] = __expf(s[t][3] - mn1);
            ls0 += s[t][0] + s[t][1];
            ls1 += s[t][2] + s[t][3];
        }
        ls0 += __shfl_xor_sync(0xffffffffu, ls0, 1);
        ls0 += __shfl_xor_sync(0xffffffffu, ls0, 2);
        ls1 += __shfl_xor_sync(0xffffffffu, ls1, 1);
        ls1 += __shfl_xor_sync(0xffffffffu, ls1, 2);
        l0 = l0 * c0 + ls0;
        l1 = l1 * c1 + ls1;

#pragma unroll
        for (int g = 0; g < 10; g++) {
            o[g][0] *= c0; o[g][1] *= c0;
            o[g][2] *= c1; o[g][3] *= c1;
        }

        // ---- O += P @ V  (P fragments straight from registers) ----
#pragma unroll
        for (int u = 0; u < 4; u++) {
            uint32_t pa[4];
            pa[0] = pack_h2(s[2 * u][0],     s[2 * u][1]);
            pa[1] = pack_h2(s[2 * u][2],     s[2 * u][3]);
            pa[2] = pack_h2(s[2 * u + 1][0], s[2 * u + 1][1]);
            pa[3] = pack_h2(s[2 * u + 1][2], s[2 * u + 1][3]);
#pragma unroll
            for (int g = 0; g < 5; g++) {
                uint32_t vb[4];
                ldsm_x4(vb, vB + (uint32_t)((g * 16 + lm_r) * VROW + lm_c) * 4
                            + (uint32_t)u * 32);
                mma_fp16(o[2 * g],     pa, vb[0], vb[2]);
                mma_fp16(o[2 * g + 1], pa, vb[1], vb[3]);
            }
        }

        if (j + 1 < FNJ) cp_wait<0>();
        __syncthreads();
    }

    // ---- epilogue: O /= l, fp16 out ----
    const float r0inv = 1.f / l0;
    const float r1inv = 1.f / l1;
    const long qrow = (long)seg * SEG_LEN + q0 + warp * 16 + lg;
    uint16_t* out0 = Cf + qrow * EMBED + h * HDIM;
    uint16_t* out1 = out0 + 8 * EMBED;
#pragma unroll
    for (int g = 0; g < 10; g++) {
        const int c0 = g * 8 + lq * 2;
        const uint32_t v0 = pack_h2(o[g][0] * r0inv, o[g][1] * r0inv);
        const uint32_t v1 = pack_h2(o[g][2] * r1inv, o[g][3] * r1inv);
        *(uint32_t*)(out0 + c0) = v0;
        *(uint32_t*)(out1 + c0) = v1;
    }
}

// ---------------------------------------------------------------------------
// elementwise conversions
// ---------------------------------------------------------------------------
__global__ void split_f16(const float* __restrict__ in,
                          uint16_t* __restrict__ hi, uint16_t* __restrict__ lo,
                          long n)
{
    const long i = (long)blockIdx.x * blockDim.x + threadIdx.x;
    if (i < n) {
        uint16_t h, l;
        split1h(in[i], h, l);
        hi[i] = h;
        lo[i] = l;
    }
}

__global__ void f32_to_f16(const float* __restrict__ in,
                           uint16_t* __restrict__ out, long n)
{
    const long i = (long)blockIdx.x * blockDim.x + threadIdx.x;
    if (i < n) out[i] = f2h(in[i]);
}

// ---------------------------------------------------------------------------
// Rotary + relayout: Q -> fp16 hi/lo [h][s][96], K -> fp16 [h][s][96],
// V -> fp16 [h][d][s]
// ---------------------------------------------------------------------------
__global__ void rotary_relayout(const float* __restrict__ qkv,
                                const float* __restrict__ rope,
                                uint16_t* __restrict__ Qh, uint16_t* __restrict__ Ql,
                                uint16_t* __restrict__ Kf,
                                uint16_t* __restrict__ Vtf)
{
    const int s = blockIdx.x;
    const float* row = qkv + (long)s * QKV_F;

    for (int e = threadIdx.x; e < EMBED; e += blockDim.x) {
        const int h = e / HDIM;
        const int d = e % HDIM;
        const float f = rope[s * (HDIM / 2) + ((d < HDIM / 2) ? d : d - HDIM / 2)];
        float sn, cs;
        sincosf(f, &sn, &cs);

        const float qv = row[e];
        const float kv = row[EMBED + e];
        const float qp = (d < HDIM / 2) ? -row[e + HDIM / 2] : row[e - HDIM / 2];
        const float kp = (d < HDIM / 2) ? -row[EMBED + e + HDIM / 2]
                                        :  row[EMBED + e - HDIM / 2];

        const float qr = qv * cs + qp * sn;
        const float kr = kv * cs + kp * sn;

        const long oq = ((long)h * S_TOTAL + s) * HDIMP + d;
        uint16_t hh, ll;
        split1h(qr, hh, ll);
        Qh[oq] = hh;  Ql[oq] = ll;
        Kf[oq] = f2h(kr);

        Vtf[((long)h * HDIM + d) * S_TOTAL + s] = f2h(row[2 * EMBED + e]);
    }
}

// ---------------------------------------------------------------------------
// Entry point
// ---------------------------------------------------------------------------
extern "C" void kernel_launch(void* const* d_in, const int* in_sizes, int n_in,
                              void* d_out, int out_size)
{
    const float* x      = (const float*)d_in[0];
    const float* qkv_w  = (const float*)d_in[1];
    const float* qkv_b  = (const float*)d_in[2];
    const float* proj_w = (const float*)d_in[3];
    const float* proj_b = (const float*)d_in[4];
    const float* rope   = (const float*)d_in[5];
    float* out = (float*)d_out;

    cudaFuncSetAttribute(gemm_f16ax2<64>,
                         cudaFuncAttributeMaxDynamicSharedMemorySize, 2 * STG2B<64>());
    cudaFuncSetAttribute(gemm_fp16<64>,
                         cudaFuncAttributeMaxDynamicSharedMemorySize, 2 * STG1B<64>());
    cudaFuncSetAttribute(flash_attn,
                         cudaFuncAttributeMaxDynamicSharedMemorySize, FSMEM_B);

    float* qkv;
    uint16_t *xh, *xl, *wf, *pwf;
    uint16_t *Qh, *Ql, *Kf, *Vtf, *cf;
    cudaGetSymbolAddress((void**)&qkv, g_qkv);
    cudaGetSymbolAddress((void**)&xh,  g_xh16);  cudaGetSymbolAddress((void**)&xl, g_xl16);
    cudaGetSymbolAddress((void**)&wf,  g_wf);    cudaGetSymbolAddress((void**)&pwf, g_pwf);
    cudaGetSymbolAddress((void**)&Qh,  g_Qh16);  cudaGetSymbolAddress((void**)&Ql, g_Ql16);
    cudaGetSymbolAddress((void**)&Kf,  g_Kf16);
    cudaGetSymbolAddress((void**)&Vtf, g_Vtf);
    cudaGetSymbolAddress((void**)&cf,  g_cf);

    // 0) conversions
    {
        long n1 = (long)S_TOTAL * EMBED;
        long n2 = (long)QKV_F * EMBED;
        long n3 = (long)EMBED * EMBED;
        split_f16<<<(unsigned)((n1 + 255) / 256), 256>>>(x, xh, xl, n1);
        f32_to_f16<<<(unsigned)((n2 + 255) / 256), 256>>>(qkv_w, wf, n2);
        f32_to_f16<<<(unsigned)((n3 + 255) / 256), 256>>>(proj_w, pwf, n3);
    }

    // 1a) QK part of QKV (fp16 A-split x2, BK=64)
    {
        dim3 grid(QK_F / BN, S_TOTAL / BM, 1);
        gemm_f16ax2<64><<<grid, 256, 2 * STG2B<64>()>>>(xh, xl, wf, qkv_b, qkv,
            QK_F, EMBED, EMBED, EMBED, QKV_F, 0, 0, 0, 0, 0, 0, 1, 1.0f);
    }

    // 1b) V part of QKV (fp16 x1, BK=64)
    {
        dim3 grid(EMBED / BN, S_TOTAL / BM, 1);
        gemm_fp16<64><<<grid, 256, 2 * STG1B<64>()>>>(xh, wf + (long)QK_F * EMBED,
            qkv_b + QK_F, qkv + QK_F,
            EMBED, EMBED, EMBED, EMBED, QKV_F, 0, 0, 0, 0, 0, 0, 1, 1.0f);
    }

    // 2) rotary + relayout
    rotary_relayout<<<S_TOTAL, 256>>>(qkv, rope, Qh, Ql, Kf, Vtf);

    // 3) fused attention -> fp16 ctx
    {
        dim3 grid(1, SEG_LEN / FQT, NSEG * HEADS);
        flash_attn<<<grid, 256, FSMEM_B>>>(Qh, Ql, Kf, Vtf, cf);
    }

    // 4) out = ctx @ proj_w^T + proj_b  (fp16 x1, BK=64)
    {
        dim3 grid(EMBED / BN, S_TOTAL / BM, 1);
        gemm_fp16<64><<<grid, 256, 2 * STG1B<64>()>>>(cf, pwf, proj_b, out,
            EMBED, EMBED, EMBED, EMBED, EMBED, 0, 0, 0, 0, 0, 0, 1, 1.0f);
    }
}

// round 16
// speedup vs baseline: 2.1361x; 1.0144x over previous
#include <cuda_runtime.h>
#include <cuda_bf16.h>
#include <cuda_fp16.h>
#include <stdint.h>
#include <stddef.h>
#include <math.h>

// Round 16: remove HDIMP=96 padding (legacy of the standalone scores GEMM).
// Flash S-mma runs exactly K=80 = 5 k16-chunks -> 17% of S-mma work and Q/K
// smem traffic deleted (pad chunks multiplied zeros). rotary uses __sincosf
// (args in [0,6.3]; error ~5e-7, noise vs fp16 rounding). All else identical
// to round 15 (577.5 us, rel_err 6.27e-4).

// ---------------------------------------------------------------------------
// Problem constants
// ---------------------------------------------------------------------------
#define EMBED   1280
#define HEADS   16
#define HDIM    80
#define S_TOTAL 4096
#define NSEG    4
#define SEG_LEN 1024
#define QKV_F   (3 * EMBED)   // 3840
#define QK_F    (2 * EMBED)   // 2560

// ---------------------------------------------------------------------------
// Scratch
// ---------------------------------------------------------------------------
__device__ float    g_qkv[(size_t)S_TOTAL * QKV_F];

__device__ uint16_t g_xh16[(size_t)S_TOTAL * EMBED], g_xl16[(size_t)S_TOTAL * EMBED];
__device__ uint16_t g_wf[(size_t)QKV_F * EMBED];
__device__ uint16_t g_pwf[(size_t)EMBED * EMBED];
__device__ uint16_t g_Qh16[(size_t)HEADS * S_TOTAL * HDIM];
__device__ uint16_t g_Ql16[(size_t)HEADS * S_TOTAL * HDIM];
__device__ uint16_t g_Kf16[(size_t)HEADS * S_TOTAL * HDIM];
__device__ uint16_t g_Vtf[(size_t)HEADS * HDIM * S_TOTAL];
__device__ uint16_t g_cf[(size_t)S_TOTAL * EMBED];

// ---------------------------------------------------------------------------
// helpers
// ---------------------------------------------------------------------------
__device__ __forceinline__ uint16_t f2h(float x)
{
    __half h = __float2half_rn(x);
    return *reinterpret_cast<uint16_t*>(&h);
}

__device__ __forceinline__ uint32_t pack_h2(float a, float b)
{
    __half2 h = __floats2half2_rn(a, b);
    return *reinterpret_cast<uint32_t*>(&h);
}

__device__ __forceinline__ void split1h(float x, uint16_t& hi, uint16_t& lo)
{
    __half h = __float2half_rn(x);
    float r = x - __half2float(h);
    hi = *reinterpret_cast<uint16_t*>(&h);
    __half l = __float2half_rn(r);
    lo = *reinterpret_cast<uint16_t*>(&l);
}

__device__ __forceinline__ void mma_fp16(float* c, const uint32_t* a,
                                         uint32_t b0, uint32_t b1)
{
    asm volatile(
        "mma.sync.aligned.m16n8k16.row.col.f32.f16.f16.f32 "
        "{%0,%1,%2,%3}, {%4,%5,%6,%7}, {%8,%9}, {%0,%1,%2,%3};"
        : "+f"(c[0]), "+f"(c[1]), "+f"(c[2]), "+f"(c[3])
        : "r"(a[0]), "r"(a[1]), "r"(a[2]), "r"(a[3]), "r"(b0), "r"(b1));
}

__device__ __forceinline__ void ldsm_x4(uint32_t* r, uint32_t addr)
{
    asm volatile("ldmatrix.sync.aligned.m8n8.x4.shared.b16 {%0,%1,%2,%3}, [%4];"
                 : "=r"(r[0]), "=r"(r[1]), "=r"(r[2]), "=r"(r[3]) : "r"(addr));
}

__device__ __forceinline__ void cp_async16(uint32_t dst_smem, const void* src)
{
    asm volatile("cp.async.cg.shared.global [%0], [%1], 16;"
                 :: "r"(dst_smem), "l"(src));
}
__device__ __forceinline__ void cp_async16z(uint32_t dst_smem, const void* src, int src_bytes)
{
    asm volatile("cp.async.cg.shared.global [%0], [%1], 16, %2;"
                 :: "r"(dst_smem), "l"(src), "r"(src_bytes));
}
__device__ __forceinline__ void cp_commit()
{
    asm volatile("cp.async.commit_group;");
}
template <int N>
__device__ __forceinline__ void cp_wait()
{
    asm volatile("cp.async.wait_group %0;" :: "n"(N));
}

// ---------------------------------------------------------------------------
// GEMM tiling (QKV / proj kernels, as rounds 12-15)
// ---------------------------------------------------------------------------
#define BM 128
#define BN 128
template <int BK_> struct TileCfg {
    static constexpr int BKP = BK_ / 2 + 4;
    static constexpr int SUBu = 128 * BKP;
    static constexpr int TPR  = BK_ / 8;
    static constexpr int RSTEP = 256 / TPR;
};
template <int BK_> constexpr int STG2B() { return 3 * TileCfg<BK_>::SUBu * 4; }
template <int BK_> constexpr int STG1B() { return 2 * TileCfg<BK_>::SUBu * 4; }

// ---------------------------------------------------------------------------
// fp16 A-split x2 batched GEMM (unchanged)
// ---------------------------------------------------------------------------
template <int BK_>
__global__ __launch_bounds__(256, 2)
void gemm_f16ax2(const uint16_t* __restrict__ Ah, const uint16_t* __restrict__ Al,
                 const uint16_t* __restrict__ Bf,
                 const float* __restrict__ bias, float* __restrict__ C,
                 int N, int K, int lda, int ldb, int ldc,
                 long oAs, long oAh_, long oBs, long oBh_, long oCs, long oCh_,
                 int nh, float alpha)
{
    using T = TileCfg<BK_>;
    constexpr int BKP = T::BKP;
    constexpr int SUBu = T::SUBu;
    constexpr int STGu = 3 * SUBu;
    extern __shared__ uint32_t sm[];

    const int z   = blockIdx.z;
    const int seg = z / nh;
    const int h   = z % nh;
    Ah += oAs * seg + oAh_ * h;  Al += oAs * seg + oAh_ * h;
    Bf += oBs * seg + oBh_ * h;
    C  += oCs * seg + oCh_ * h;

    const int brow = blockIdx.y * BM;
    const int bcol = blockIdx.x * BN;

    const int tid  = threadIdx.x;
    const int warp = tid >> 5;
    const int lane = tid & 31;
    const int wm = (warp >> 1) * 32;
    const int wn = (warp & 1) * 64;
    const int lg = lane >> 2;
    const int lq = lane & 3;

    const uint32_t smem_base = (uint32_t)__cvta_generic_to_shared(sm);
    const int lm_r = lane & 15;
    const int lm_c = (lane >> 4) * 4;
    const int lrow0 = tid / T::TPR;
    const int chk   = tid % T::TPR;

    float acc[2][8][4];
#pragma unroll
    for (int i = 0; i < 2; i++)
#pragma unroll
        for (int j = 0; j < 8; j++)
#pragma unroll
            for (int q = 0; q < 4; q++) acc[i][j][q] = 0.f;

    const int nit = K / BK_;

    auto load_stage = [&](int stage, int k0) {
        const uint32_t sb = smem_base + (uint32_t)stage * STGu * 4;
#pragma unroll
        for (int row = lrow0; row < 128; row += T::RSTEP) {
            const uint32_t doff = (uint32_t)(row * BKP + chk * 4) * 4;
            const long acol = (long)k0 + chk * 8;
            cp_async16(sb + 0 * SUBu * 4 + doff,
                       Ah + (long)(brow + row) * lda + acol);
            cp_async16(sb + 1 * SUBu * 4 + doff,
                       Al + (long)(brow + row) * lda + acol);
            const int bn  = bcol + row;
            const int ok  = (bn < N) ? 16 : 0;
            const int bno = (bn < N) ? bn : 0;
            cp_async16z(sb + 2 * SUBu * 4 + doff,
                        Bf + (long)bno * ldb + acol, ok);
        }
    };

    load_stage(0, 0);
    cp_commit();

    const uint32_t aOff0 = (uint32_t)((wm + lm_r) * BKP + lm_c) * 4;
    const uint32_t aOff1 = (uint32_t)((wm + 16 + lm_r) * BKP + lm_c) * 4;
    const uint32_t bOffBase = (uint32_t)((wn + lm_r) * BKP + lm_c) * 4;

    for (int it = 0; it < nit; it++) {
        if (it + 1 < nit) {
            load_stage((it + 1) & 1, (it + 1) * BK_);
            cp_commit();
            cp_wait<1>();
        } else {
            cp_wait<0>();
        }
        __syncthreads();

        const uint32_t stageB = smem_base + (uint32_t)(it & 1) * STGu * 4;
        const uint32_t aBaseH = stageB;
        const uint32_t aBaseL = stageB + SUBu * 4;
        const uint32_t bBase  = stageB + 2 * SUBu * 4;

#pragma unroll
        for (int kc = 0; kc < BK_ / 16; kc++) {
            const uint32_t kbyte = (uint32_t)(kc * 8) * 4;

            uint32_t aH[2][4], aL[2][4];
            ldsm_x4(aH[0], aBaseH + aOff0 + kbyte);
            ldsm_x4(aH[1], aBaseH + aOff1 + kbyte);
            ldsm_x4(aL[0], aBaseL + aOff0 + kbyte);
            ldsm_x4(aL[1], aBaseL + aOff1 + kbyte);

            uint32_t b[4][4];
#pragma unroll
            for (int ntp = 0; ntp < 4; ntp++)
                ldsm_x4(b[ntp], bBase + bOffBase + (uint32_t)(ntp * 16 * BKP) * 4 + kbyte);

#pragma unroll
            for (int ntp = 0; ntp < 4; ntp++)
#pragma unroll
                for (int half = 0; half < 2; half++)
#pragma unroll
                    for (int mt = 0; mt < 2; mt++)
                        mma_fp16(acc[mt][ntp * 2 + half], aH[mt],
                                 b[ntp][half], b[ntp][2 + half]);
#pragma unroll
            for (int ntp = 0; ntp < 4; ntp++)
#pragma unroll
                for (int half = 0; half < 2; half++)
#pragma unroll
                    for (int mt = 0; mt < 2; mt++)
                        mma_fp16(acc[mt][ntp * 2 + half], aL[mt],
                                 b[ntp][half], b[ntp][2 + half]);
        }
        __syncthreads();
    }

#pragma unroll
    for (int mt = 0; mt < 2; mt++) {
        const int r0 = brow + wm + mt * 16 + lg;
#pragma unroll
        for (int nt = 0; nt < 8; nt++) {
            const int c0 = bcol + wn + nt * 8 + lq * 2;
            float* p0 = C + (long)r0 * ldc;
            float* p1 = C + (long)(r0 + 8) * ldc;
            const float b0 = bias ? bias[min(c0, N - 1)] : 0.f;
            const float b1 = bias ? bias[min(c0 + 1, N - 1)] : 0.f;
            if (c0 < N) {
                p0[c0] = alpha * acc[mt][nt][0] + b0;
                p1[c0] = alpha * acc[mt][nt][2] + b0;
            }
            if (c0 + 1 < N) {
                p0[c0 + 1] = alpha * acc[mt][nt][1] + b1;
                p1[c0 + 1] = alpha * acc[mt][nt][3] + b1;
            }
        }
    }
}

// ---------------------------------------------------------------------------
// fp16 single-pass batched GEMM (unchanged)
// ---------------------------------------------------------------------------
template <int BK_>
__global__ __launch_bounds__(256, 2)
void gemm_fp16(const uint16_t* __restrict__ Af, const uint16_t* __restrict__ Bf,
               const float* __restrict__ bias, float* __restrict__ C,
               int N, int K, int lda, int ldb, int ldc,
               long oAs, long oAh_, long oBs, long oBh_, long oCs, long oCh_,
               int nh, float alpha)
{
    using T = TileCfg<BK_>;
    constexpr int BKP = T::BKP;
    constexpr int SUBu = T::SUBu;
    constexpr int STGu = 2 * SUBu;
    extern __shared__ uint32_t sm[];

    const int z   = blockIdx.z;
    const int seg = z / nh;
    const int h   = z % nh;
    Af += oAs * seg + oAh_ * h;
    Bf += oBs * seg + oBh_ * h;
    C  += oCs * seg + oCh_ * h;

    const int brow = blockIdx.y * BM;
    const int bcol = blockIdx.x * BN;

    const int tid  = threadIdx.x;
    const int warp = tid >> 5;
    const int lane = tid & 31;
    const int wm = (warp >> 1) * 32;
    const int wn = (warp & 1) * 64;
    const int lg = lane >> 2;
    const int lq = lane & 3;

    const uint32_t smem_base = (uint32_t)__cvta_generic_to_shared(sm);
    const int lm_r = lane & 15;
    const int lm_c = (lane >> 4) * 4;
    const int lrow0 = tid / T::TPR;
    const int chk   = tid % T::TPR;

    float acc[2][8][4];
#pragma unroll
    for (int i = 0; i < 2; i++)
#pragma unroll
        for (int j = 0; j < 8; j++)
#pragma unroll
            for (int q = 0; q < 4; q++) acc[i][j][q] = 0.f;

    const int nit = K / BK_;

    auto load_stage = [&](int stage, int k0) {
        const uint32_t sb = smem_base + (uint32_t)stage * STGu * 4;
#pragma unroll
        for (int row = lrow0; row < 128; row += T::RSTEP) {
            const uint32_t doff = (uint32_t)(row * BKP + chk * 4) * 4;
            const long acol = (long)k0 + chk * 8;
            cp_async16(sb + 0 * SUBu * 4 + doff,
                       Af + (long)(brow + row) * lda + acol);
            const int bn  = bcol + row;
            const int ok  = (bn < N) ? 16 : 0;
            const int bno = (bn < N) ? bn : 0;
            cp_async16z(sb + 1 * SUBu * 4 + doff,
                        Bf + (long)bno * ldb + acol, ok);
        }
    };

    load_stage(0, 0);
    cp_commit();

    const uint32_t aOff0 = (uint32_t)((wm + lm_r) * BKP + lm_c) * 4;
    const uint32_t aOff1 = (uint32_t)((wm + 16 + lm_r) * BKP + lm_c) * 4;
    const uint32_t bOffBase = (uint32_t)((wn + lm_r) * BKP + lm_c) * 4;

    for (int it = 0; it < nit; it++) {
        if (it + 1 < nit) {
            load_stage((it + 1) & 1, (it + 1) * BK_);
            cp_commit();
            cp_wait<1>();
        } else {
            cp_wait<0>();
        }
        __syncthreads();

        const uint32_t stageB = smem_base + (uint32_t)(it & 1) * STGu * 4;
        const uint32_t aBase = stageB;
        const uint32_t bBase = stageB + SUBu * 4;

#pragma unroll
        for (int kc = 0; kc < BK_ / 16; kc++) {
            const uint32_t kbyte = (uint32_t)(kc * 8) * 4;

            uint32_t a[2][4];
            ldsm_x4(a[0], aBase + aOff0 + kbyte);
            ldsm_x4(a[1], aBase + aOff1 + kbyte);

#pragma unroll
            for (int ntp = 0; ntp < 4; ntp++) {
                uint32_t b[4];
                ldsm_x4(b, bBase + bOffBase + (uint32_t)(ntp * 16 * BKP) * 4 + kbyte);
#pragma unroll
                for (int half = 0; half < 2; half++)
#pragma unroll
                    for (int mt = 0; mt < 2; mt++)
                        mma_fp16(acc[mt][ntp * 2 + half], a[mt],
                                 b[half], b[2 + half]);
            }
        }
        __syncthreads();
    }

#pragma unroll
    for (int mt = 0; mt < 2; mt++) {
        const int r0 = brow + wm + mt * 16 + lg;
#pragma unroll
        for (int nt = 0; nt < 8; nt++) {
            const int c0 = bcol + wn + nt * 8 + lq * 2;
            float* p0 = C + (long)r0 * ldc;
            float* p1 = C + (long)(r0 + 8) * ldc;
            const float b0 = bias ? bias[min(c0, N - 1)] : 0.f;
            const float b1 = bias ? bias[min(c0 + 1, N - 1)] : 0.f;
            if (c0 < N) {
                p0[c0] = alpha * acc[mt][nt][0] + b0;
                p1[c0] = alpha * acc[mt][nt][2] + b0;
            }
            if (c0 + 1 < N) {
                p0[c0 + 1] = alpha * acc[mt][nt][1] + b1;
                p1[c0 + 1] = alpha * acc[mt][nt][3] + b1;
            }
        }
    }
}

// ---------------------------------------------------------------------------
// Flash attention, HDIM=80 exact (no pad): per block 128 q rows x full head;
// 16 k-tiles of 64. S = scale*(Qh+Ql)@K^T (5 k16-chunks), online softmax,
// O += P@V from registers. Warp w owns q rows [w*16, w*16+16).
// smem: Qh 0 (22528), Ql 22528, K 45056 (+11264 x2), V 67584 (+11520 x2)
// ---------------------------------------------------------------------------
#define FQT 128
#define FKT 64
#define FNJ (SEG_LEN / FKT)       // 16
#define QKROW 44                  // u32 per Q/K smem row (40 + 4)
#define VROW  36                  // u32 per V smem row (32 + 4)
#define FSQH 0
#define FSQL 22528
#define FSK  45056
#define FSKS 11264
#define FSV  67584
#define FSVS 11520
#define FSMEM_B 90624

__global__ __launch_bounds__(256, 2)
void flash_attn(const uint16_t* __restrict__ Qh, const uint16_t* __restrict__ Ql,
                const uint16_t* __restrict__ Kf, const uint16_t* __restrict__ Vtf,
                uint16_t* __restrict__ Cf)
{
    extern __shared__ uint32_t sm[];
    const uint32_t smem_base = (uint32_t)__cvta_generic_to_shared(sm);

    const int bh  = blockIdx.z;          // seg*HEADS + h
    const int seg = bh / HEADS;
    const int h   = bh % HEADS;
    const int q0  = blockIdx.y * FQT;

    const int tid  = threadIdx.x;
    const int warp = tid >> 5;
    const int lane = tid & 31;
    const int lg = lane >> 2;
    const int lq = lane & 3;
    const int lm_r = lane & 15;
    const int lm_c = (lane >> 4) * 4;

    const long qkbase = ((long)h * S_TOTAL + (long)seg * SEG_LEN);

    // ---- load Q (hi+lo) once: 128 rows x 80 fp16 = 10 x 16B chunks/row ----
    for (int c = tid; c < 2 * 128 * 10; c += 256) {
        const int arr = c / 1280;
        const int cc  = c % 1280;
        const int row = cc / 10;
        const int ch  = cc % 10;
        const uint32_t dst = smem_base + (arr ? FSQL : FSQH)
                           + (uint32_t)(row * QKROW) * 4 + ch * 16;
        const uint16_t* src = (arr ? Ql : Qh) + (qkbase + q0 + row) * HDIM + ch * 8;
        cp_async16(dst, src);
    }
    cp_commit();

    // ---- K/V tile loader ----
    auto load_kv = [&](int buf, int j) {
        const uint32_t kb = smem_base + FSK + (uint32_t)buf * FSKS;
        const uint32_t vb = smem_base + FSV + (uint32_t)buf * FSVS;
        for (int c = tid; c < 64 * 10 + 80 * 8; c += 256) {
            if (c < 640) {
                const int row = c / 10, ch = c % 10;
                cp_async16(kb + (uint32_t)(row * QKROW) * 4 + ch * 16,
                           Kf + (qkbase + (long)j * FKT + row) * HDIM + ch * 8);
            } else {
                const int v = c - 640;
                const int d = v / 8, ch = v % 8;
                cp_async16(vb + (uint32_t)(d * VROW) * 4 + ch * 16,
                           Vtf + ((long)h * HDIM + d) * S_TOTAL
                               + (long)seg * SEG_LEN + (long)j * FKT + ch * 8);
            }
        }
    };

    load_kv(0, 0);
    cp_commit();
    cp_wait<0>();
    __syncthreads();

    // ---- state ----
    float o[10][4];
#pragma unroll
    for (int g = 0; g < 10; g++)
#pragma unroll
        for (int q = 0; q < 4; q++) o[g][q] = 0.f;
    float m0 = -INFINITY, m1 = -INFINITY, l0 = 0.f, l1 = 0.f;

    const float scale = 0.11180339887498949f; // 1/sqrt(80)
    const uint32_t qOff = (uint32_t)((warp * 16 + lm_r) * QKROW + lm_c) * 4;

    for (int j = 0; j < FNJ; j++) {
        if (j + 1 < FNJ) { load_kv((j + 1) & 1, j + 1); cp_commit(); }

        const uint32_t kB = smem_base + FSK + (uint32_t)(j & 1) * FSKS;
        const uint32_t vB = smem_base + FSV + (uint32_t)(j & 1) * FSVS;

        // ---- S = (Qh+Ql) @ K^T  (K=80 = 5 chunks exactly) ----
        float s[8][4];
#pragma unroll
        for (int t = 0; t < 8; t++)
#pragma unroll
            for (int q = 0; q < 4; q++) s[t][q] = 0.f;

#pragma unroll
        for (int kc = 0; kc < 5; kc++) {
            const uint32_t kbyte = (uint32_t)kc * 32;
            uint32_t qh[4], ql[4];
            ldsm_x4(qh, smem_base + FSQH + qOff + kbyte);
            ldsm_x4(ql, smem_base + FSQL + qOff + kbyte);
#pragma unroll
            for (int ntp = 0; ntp < 4; ntp++) {
                uint32_t kb[4];
                ldsm_x4(kb, kB + (uint32_t)((ntp * 16 + lm_r) * QKROW + lm_c) * 4 + kbyte);
                mma_fp16(s[2 * ntp],     qh, kb[0], kb[2]);
                mma_fp16(s[2 * ntp + 1], qh, kb[1], kb[3]);
                mma_fp16(s[2 * ntp],     ql, kb[0], kb[2]);
                mma_fp16(s[2 * ntp + 1], ql, kb[1], kb[3]);
            }
        }

        // ---- online softmax ----
        float mt0 = -INFINITY, mt1 = -INFINITY;
#pragma unroll
        for (int t = 0; t < 8; t++) {
            s[t][0] *= scale; s[t][1] *= scale;
            s[t][2] *= scale; s[t][3] *= scale;
            mt0 = fmaxf(mt0, fmaxf(s[t][0], s[t][1]));
            mt1 = fmaxf(mt1, fmaxf(s[t][2], s[t][3]));
        }
        mt0 = fmaxf(mt0, __shfl_xor_sync(0xffffffffu, mt0, 1));
        mt0 = fmaxf(mt0, __shfl_xor_sync(0xffffffffu, mt0, 2));
        mt1 = fmaxf(mt1, __shfl_xor_sync(0xffffffffu, mt1, 1));
        mt1 = fmaxf(mt1, __shfl_xor_sync(0xffffffffu, mt1, 2));

        const float mn0 = fmaxf(m0, mt0);
        const float mn1 = fmaxf(m1, mt1);
        const float c0 = __expf(m0 - mn0);
        const float c1 = __expf(m1 - mn1);
        m0 = mn0; m1 = mn1;

        float ls0 = 0.f, ls1 = 0.f;
#pragma unroll
        for (int t = 0; t < 8; t++) {
            s[t][0] = __expf(s[t][0] - mn0);
            s[t][1] = __expf(s[t][1] - mn0);
            s[t][2] = __expf(s[t][2] - mn1);
            s[t][3] = __expf(s[t][3] - mn1);
            ls0 += s[t][0] + s[t][1];
            ls1 += s[t][2] + s[t][3];
        }
        ls0 += __shfl_xor_sync(0xffffffffu, ls0, 1);
        ls0 += __shfl_xor_sync(0xffffffffu, ls0, 2);
        ls1 += __shfl_xor_sync(0xffffffffu, ls1, 1);
        ls1 += __shfl_xor_sync(0xffffffffu, ls1, 2);
        l0 = l0 * c0 + ls0;
        l1 = l1 * c1 + ls1;

#pragma unroll
        for (int g = 0; g < 10; g++) {
            o[g][0] *= c0; o[g][1] *= c0;
            o[g][2] *= c1; o[g][3] *= c1;
        }

        // ---- O += P @ V ----
#pragma unroll
        for (int u = 0; u < 4; u++) {
            uint32_t pa[4];
            pa[0] = pack_h2(s[2 * u][0],     s[2 * u][1]);
            pa[1] = pack_h2(s[2 * u][2],     s[2 * u][3]);
            pa[2] = pack_h2(s[2 * u + 1][0], s[2 * u + 1][1]);
            pa[3] = pack_h2(s[2 * u + 1][2], s[2 * u + 1][3]);
#pragma unroll
            for (int g = 0; g < 5; g++) {
                uint32_t vb[4];
                ldsm_x4(vb, vB + (uint32_t)((g * 16 + lm_r) * VROW + lm_c) * 4
                            + (uint32_t)u * 32);
                mma_fp16(o[2 * g],     pa, vb[0], vb[2]);
                mma_fp16(o[2 * g + 1], pa, vb[1], vb[3]);
            }
        }

        if (j + 1 < FNJ) cp_wait<0>();
        __syncthreads();
    }

    // ---- epilogue ----
    const float r0inv = 1.f / l0;
    const float r1inv = 1.f / l1;
    const long qrow = (long)seg * SEG_LEN + q0 + warp * 16 + lg;
    uint16_t* out0 = Cf + qrow * EMBED + h * HDIM;
    uint16_t* out1 = out0 + 8 * EMBED;
#pragma unroll
    for (int g = 0; g < 10; g++) {
        const int c0 = g * 8 + lq * 2;
        const uint32_t v0 = pack_h2(o[g][0] * r0inv, o[g][1] * r0inv);
        const uint32_t v1 = pack_h2(o[g][2] * r1inv, o[g][3] * r1inv);
        *(uint32_t*)(out0 + c0) = v0;
        *(uint32_t*)(out1 + c0) = v1;
    }
}

// ---------------------------------------------------------------------------
// elementwise conversions
// ---------------------------------------------------------------------------
__global__ void split_f16(const float* __restrict__ in,
                          uint16_t* __restrict__ hi, uint16_t* __restrict__ lo,
                          long n)
{
    const long i = (long)blockIdx.x * blockDim.x + threadIdx.x;
    if (i < n) {
        uint16_t h, l;
        split1h(in[i], h, l);
        hi[i] = h;
        lo[i] = l;
    }
}

__global__ void f32_to_f16(const float* __restrict__ in,
                           uint16_t* __restrict__ out, long n)
{
    const long i = (long)blockIdx.x * blockDim.x + threadIdx.x;
    if (i < n) out[i] = f2h(in[i]);
}

// ---------------------------------------------------------------------------
// Rotary + relayout: Q -> fp16 hi/lo [h][s][80], K -> fp16 [h][s][80],
// V -> fp16 [h][d][s]. Fast __sincosf (args in [0, 6.3]).
// ---------------------------------------------------------------------------
__global__ void rotary_relayout(const float* __restrict__ qkv,
                                const float* __restrict__ rope,
                                uint16_t* __restrict__ Qh, uint16_t* __restrict__ Ql,
                                uint16_t* __restrict__ Kf,
                                uint16_t* __restrict__ Vtf)
{
    const int s = blockIdx.x;
    const float* row = qkv + (long)s * QKV_F;

    for (int e = threadIdx.x; e < EMBED; e += blockDim.x) {
        const int h = e / HDIM;
        const int d = e % HDIM;
        const float f = rope[s * (HDIM / 2) + ((d < HDIM / 2) ? d : d - HDIM / 2)];
        float sn, cs;
        __sincosf(f, &sn, &cs);

        const float qv = row[e];
        const float kv = row[EMBED + e];
        const float qp = (d < HDIM / 2) ? -row[e + HDIM / 2] : row[e - HDIM / 2];
        const float kp = (d < HDIM / 2) ? -row[EMBED + e + HDIM / 2]
                                        :  row[EMBED + e - HDIM / 2];

        const float qr = qv * cs + qp * sn;
        const float kr = kv * cs + kp * sn;

        const long oq = ((long)h * S_TOTAL + s) * HDIM + d;
        uint16_t hh, ll;
        split1h(qr, hh, ll);
        Qh[oq] = hh;  Ql[oq] = ll;
        Kf[oq] = f2h(kr);

        Vtf[((long)h * HDIM + d) * S_TOTAL + s] = f2h(row[2 * EMBED + e]);
    }
}

// ---------------------------------------------------------------------------
// Entry point
// ---------------------------------------------------------------------------
extern "C" void kernel_launch(void* const* d_in, const int* in_sizes, int n_in,
                              void* d_out, int out_size)
{
    const float* x      = (const float*)d_in[0];
    const float* qkv_w  = (const float*)d_in[1];
    const float* qkv_b  = (const float*)d_in[2];
    const float* proj_w = (const float*)d_in[3];
    const float* proj_b = (const float*)d_in[4];
    const float* rope   = (const float*)d_in[5];
    float* out = (float*)d_out;

    cudaFuncSetAttribute(gemm_f16ax2<64>,
                         cudaFuncAttributeMaxDynamicSharedMemorySize, 2 * STG2B<64>());
    cudaFuncSetAttribute(gemm_fp16<64>,
                         cudaFuncAttributeMaxDynamicSharedMemorySize, 2 * STG1B<64>());
    cudaFuncSetAttribute(flash_attn,
                         cudaFuncAttributeMaxDynamicSharedMemorySize, FSMEM_B);

    float* qkv;
    uint16_t *xh, *xl, *wf, *pwf;
    uint16_t *Qh, *Ql, *Kf, *Vtf, *cf;
    cudaGetSymbolAddress((void**)&qkv, g_qkv);
    cudaGetSymbolAddress((void**)&xh,  g_xh16);  cudaGetSymbolAddress((void**)&xl, g_xl16);
    cudaGetSymbolAddress((void**)&wf,  g_wf);    cudaGetSymbolAddress((void**)&pwf, g_pwf);
    cudaGetSymbolAddress((void**)&Qh,  g_Qh16);  cudaGetSymbolAddress((void**)&Ql, g_Ql16);
    cudaGetSymbolAddress((void**)&Kf,  g_Kf16);
    cudaGetSymbolAddress((void**)&Vtf, g_Vtf);
    cudaGetSymbolAddress((void**)&cf,  g_cf);

    // 0) conversions
    {
        long n1 = (long)S_TOTAL * EMBED;
        long n2 = (long)QKV_F * EMBED;
        long n3 = (long)EMBED * EMBED;
        split_f16<<<(unsigned)((n1 + 255) / 256), 256>>>(x, xh, xl, n1);
        f32_to_f16<<<(unsigned)((n2 + 255) / 256), 256>>>(qkv_w, wf, n2);
        f32_to_f16<<<(unsigned)((n3 + 255) / 256), 256>>>(proj_w, pwf, n3);
    }

    // 1a) QK part of QKV (fp16 A-split x2, BK=64)
    {
        dim3 grid(QK_F / BN, S_TOTAL / BM, 1);
        gemm_f16ax2<64><<<grid, 256, 2 * STG2B<64>()>>>(xh, xl, wf, qkv_b, qkv,
            QK_F, EMBED, EMBED, EMBED, QKV_F, 0, 0, 0, 0, 0, 0, 1, 1.0f);
    }

    // 1b) V part of QKV (fp16 x1, BK=64)
    {
        dim3 grid(EMBED / BN, S_TOTAL / BM, 1);
        gemm_fp16<64><<<grid, 256, 2 * STG1B<64>()>>>(xh, wf + (long)QK_F * EMBED,
            qkv_b + QK_F, qkv + QK_F,
            EMBED, EMBED, EMBED, EMBED, QKV_F, 0, 0, 0, 0, 0, 0, 1, 1.0f);
    }

    // 2) rotary + relayout
    rotary_relayout<<<S_TOTAL, 256>>>(qkv, rope, Qh, Ql, Kf, Vtf);

    // 3) fused attention -> fp16 ctx
    {
        dim3 grid(1, SEG_LEN / FQT, NSEG * HEADS);
        flash_attn<<<grid, 256, FSMEM_B>>>(Qh, Ql, Kf, Vtf, cf);
    }

    // 4) out = ctx @ proj_w^T + proj_b  (fp16 x1, BK=64)
    {
        dim3 grid(EMBED / BN, S_TOTAL / BM, 1);
        gemm_fp16<64><<<grid, 256, 2 * STG1B<64>()>>>(cf, pwf, proj_b, out,
            EMBED, EMBED, EMBED, EMBED, EMBED, 0, 0, 0, 0, 0, 0, 1, 1.0f);
    }
}

// round 17
// speedup vs baseline: 2.2751x; 1.0651x over previous
#include <cuda_runtime.h>
#include <cuda_bf16.h>
#include <cuda_fp16.h>
#include <stdint.h>
#include <stddef.h>
#include <math.h>

// Round 17: QKV restructure. K's 2-pass precision was wasted (its output is
// rounded to single fp16 for flash anyway), so: Q-only 2-pass (N=1280), K+V
// merged single-pass (N=2560, contiguous qkv_w rows). 20% less QKV mma work.
// Flash / proj / rotary identical to round 16 (569.3 us, rel_err 6.268e-4).
// Predicted rel_err ~6.8e-4 (adds one one-sided rounding event on K).

// ---------------------------------------------------------------------------
// Problem constants
// ---------------------------------------------------------------------------
#define EMBED   1280
#define HEADS   16
#define HDIM    80
#define S_TOTAL 4096
#define NSEG    4
#define SEG_LEN 1024
#define QKV_F   (3 * EMBED)   // 3840
#define QK_F    (2 * EMBED)   // 2560

// ---------------------------------------------------------------------------
// Scratch
// ---------------------------------------------------------------------------
__device__ float    g_qkv[(size_t)S_TOTAL * QKV_F];

__device__ uint16_t g_xh16[(size_t)S_TOTAL * EMBED], g_xl16[(size_t)S_TOTAL * EMBED];
__device__ uint16_t g_wf[(size_t)QKV_F * EMBED];
__device__ uint16_t g_pwf[(size_t)EMBED * EMBED];
__device__ uint16_t g_Qh16[(size_t)HEADS * S_TOTAL * HDIM];
__device__ uint16_t g_Ql16[(size_t)HEADS * S_TOTAL * HDIM];
__device__ uint16_t g_Kf16[(size_t)HEADS * S_TOTAL * HDIM];
__device__ uint16_t g_Vtf[(size_t)HEADS * HDIM * S_TOTAL];
__device__ uint16_t g_cf[(size_t)S_TOTAL * EMBED];

// ---------------------------------------------------------------------------
// helpers
// ---------------------------------------------------------------------------
__device__ __forceinline__ uint16_t f2h(float x)
{
    __half h = __float2half_rn(x);
    return *reinterpret_cast<uint16_t*>(&h);
}

__device__ __forceinline__ uint32_t pack_h2(float a, float b)
{
    __half2 h = __floats2half2_rn(a, b);
    return *reinterpret_cast<uint32_t*>(&h);
}

__device__ __forceinline__ void split1h(float x, uint16_t& hi, uint16_t& lo)
{
    __half h = __float2half_rn(x);
    float r = x - __half2float(h);
    hi = *reinterpret_cast<uint16_t*>(&h);
    __half l = __float2half_rn(r);
    lo = *reinterpret_cast<uint16_t*>(&l);
}

__device__ __forceinline__ void mma_fp16(float* c, const uint32_t* a,
                                         uint32_t b0, uint32_t b1)
{
    asm volatile(
        "mma.sync.aligned.m16n8k16.row.col.f32.f16.f16.f32 "
        "{%0,%1,%2,%3}, {%4,%5,%6,%7}, {%8,%9}, {%0,%1,%2,%3};"
        : "+f"(c[0]), "+f"(c[1]), "+f"(c[2]), "+f"(c[3])
        : "r"(a[0]), "r"(a[1]), "r"(a[2]), "r"(a[3]), "r"(b0), "r"(b1));
}

__device__ __forceinline__ void ldsm_x4(uint32_t* r, uint32_t addr)
{
    asm volatile("ldmatrix.sync.aligned.m8n8.x4.shared.b16 {%0,%1,%2,%3}, [%4];"
                 : "=r"(r[0]), "=r"(r[1]), "=r"(r[2]), "=r"(r[3]) : "r"(addr));
}

__device__ __forceinline__ void cp_async16(uint32_t dst_smem, const void* src)
{
    asm volatile("cp.async.cg.shared.global [%0], [%1], 16;"
                 :: "r"(dst_smem), "l"(src));
}
__device__ __forceinline__ void cp_async16z(uint32_t dst_smem, const void* src, int src_bytes)
{
    asm volatile("cp.async.cg.shared.global [%0], [%1], 16, %2;"
                 :: "r"(dst_smem), "l"(src), "r"(src_bytes));
}
__device__ __forceinline__ void cp_commit()
{
    asm volatile("cp.async.commit_group;");
}
template <int N>
__device__ __forceinline__ void cp_wait()
{
    asm volatile("cp.async.wait_group %0;" :: "n"(N));
}

// ---------------------------------------------------------------------------
// GEMM tiling
// ---------------------------------------------------------------------------
#define BM 128
#define BN 128
template <int BK_> struct TileCfg {
    static constexpr int BKP = BK_ / 2 + 4;
    static constexpr int SUBu = 128 * BKP;
    static constexpr int TPR  = BK_ / 8;
    static constexpr int RSTEP = 256 / TPR;
};
template <int BK_> constexpr int STG2B() { return 3 * TileCfg<BK_>::SUBu * 4; }
template <int BK_> constexpr int STG1B() { return 2 * TileCfg<BK_>::SUBu * 4; }

// ---------------------------------------------------------------------------
// fp16 A-split x2 batched GEMM (unchanged)
// ---------------------------------------------------------------------------
template <int BK_>
__global__ __launch_bounds__(256, 2)
void gemm_f16ax2(const uint16_t* __restrict__ Ah, const uint16_t* __restrict__ Al,
                 const uint16_t* __restrict__ Bf,
                 const float* __restrict__ bias, float* __restrict__ C,
                 int N, int K, int lda, int ldb, int ldc,
                 long oAs, long oAh_, long oBs, long oBh_, long oCs, long oCh_,
                 int nh, float alpha)
{
    using T = TileCfg<BK_>;
    constexpr int BKP = T::BKP;
    constexpr int SUBu = T::SUBu;
    constexpr int STGu = 3 * SUBu;
    extern __shared__ uint32_t sm[];

    const int z   = blockIdx.z;
    const int seg = z / nh;
    const int h   = z % nh;
    Ah += oAs * seg + oAh_ * h;  Al += oAs * seg + oAh_ * h;
    Bf += oBs * seg + oBh_ * h;
    C  += oCs * seg + oCh_ * h;

    const int brow = blockIdx.y * BM;
    const int bcol = blockIdx.x * BN;

    const int tid  = threadIdx.x;
    const int warp = tid >> 5;
    const int lane = tid & 31;
    const int wm = (warp >> 1) * 32;
    const int wn = (warp & 1) * 64;
    const int lg = lane >> 2;
    const int lq = lane & 3;

    const uint32_t smem_base = (uint32_t)__cvta_generic_to_shared(sm);
    const int lm_r = lane & 15;
    const int lm_c = (lane >> 4) * 4;
    const int lrow0 = tid / T::TPR;
    const int chk   = tid % T::TPR;

    float acc[2][8][4];
#pragma unroll
    for (int i = 0; i < 2; i++)
#pragma unroll
        for (int j = 0; j < 8; j++)
#pragma unroll
            for (int q = 0; q < 4; q++) acc[i][j][q] = 0.f;

    const int nit = K / BK_;

    auto load_stage = [&](int stage, int k0) {
        const uint32_t sb = smem_base + (uint32_t)stage * STGu * 4;
#pragma unroll
        for (int row = lrow0; row < 128; row += T::RSTEP) {
            const uint32_t doff = (uint32_t)(row * BKP + chk * 4) * 4;
            const long acol = (long)k0 + chk * 8;
            cp_async16(sb + 0 * SUBu * 4 + doff,
                       Ah + (long)(brow + row) * lda + acol);
            cp_async16(sb + 1 * SUBu * 4 + doff,
                       Al + (long)(brow + row) * lda + acol);
            const int bn  = bcol + row;
            const int ok  = (bn < N) ? 16 : 0;
            const int bno = (bn < N) ? bn : 0;
            cp_async16z(sb + 2 * SUBu * 4 + doff,
                        Bf + (long)bno * ldb + acol, ok);
        }
    };

    load_stage(0, 0);
    cp_commit();

    const uint32_t aOff0 = (uint32_t)((wm + lm_r) * BKP + lm_c) * 4;
    const uint32_t aOff1 = (uint32_t)((wm + 16 + lm_r) * BKP + lm_c) * 4;
    const uint32_t bOffBase = (uint32_t)((wn + lm_r) * BKP + lm_c) * 4;

    for (int it = 0; it < nit; it++) {
        if (it + 1 < nit) {
            load_stage((it + 1) & 1, (it + 1) * BK_);
            cp_commit();
            cp_wait<1>();
        } else {
            cp_wait<0>();
        }
        __syncthreads();

        const uint32_t stageB = smem_base + (uint32_t)(it & 1) * STGu * 4;
        const uint32_t aBaseH = stageB;
        const uint32_t aBaseL = stageB + SUBu * 4;
        const uint32_t bBase  = stageB + 2 * SUBu * 4;

#pragma unroll
        for (int kc = 0; kc < BK_ / 16; kc++) {
            const uint32_t kbyte = (uint32_t)(kc * 8) * 4;

            uint32_t aH[2][4], aL[2][4];
            ldsm_x4(aH[0], aBaseH + aOff0 + kbyte);
            ldsm_x4(aH[1], aBaseH + aOff1 + kbyte);
            ldsm_x4(aL[0], aBaseL + aOff0 + kbyte);
            ldsm_x4(aL[1], aBaseL + aOff1 + kbyte);

            uint32_t b[4][4];
#pragma unroll
            for (int ntp = 0; ntp < 4; ntp++)
                ldsm_x4(b[ntp], bBase + bOffBase + (uint32_t)(ntp * 16 * BKP) * 4 + kbyte);

#pragma unroll
            for (int ntp = 0; ntp < 4; ntp++)
#pragma unroll
                for (int half = 0; half < 2; half++)
#pragma unroll
                    for (int mt = 0; mt < 2; mt++)
                        mma_fp16(acc[mt][ntp * 2 + half], aH[mt],
                                 b[ntp][half], b[ntp][2 + half]);
#pragma unroll
            for (int ntp = 0; ntp < 4; ntp++)
#pragma unroll
                for (int half = 0; half < 2; half++)
#pragma unroll
                    for (int mt = 0; mt < 2; mt++)
                        mma_fp16(acc[mt][ntp * 2 + half], aL[mt],
                                 b[ntp][half], b[ntp][2 + half]);
        }
        __syncthreads();
    }

#pragma unroll
    for (int mt = 0; mt < 2; mt++) {
        const int r0 = brow + wm + mt * 16 + lg;
#pragma unroll
        for (int nt = 0; nt < 8; nt++) {
            const int c0 = bcol + wn + nt * 8 + lq * 2;
            float* p0 = C + (long)r0 * ldc;
            float* p1 = C + (long)(r0 + 8) * ldc;
            const float b0 = bias ? bias[min(c0, N - 1)] : 0.f;
            const float b1 = bias ? bias[min(c0 + 1, N - 1)] : 0.f;
            if (c0 < N) {
                p0[c0] = alpha * acc[mt][nt][0] + b0;
                p1[c0] = alpha * acc[mt][nt][2] + b0;
            }
            if (c0 + 1 < N) {
                p0[c0 + 1] = alpha * acc[mt][nt][1] + b1;
                p1[c0 + 1] = alpha * acc[mt][nt][3] + b1;
            }
        }
    }
}

// ---------------------------------------------------------------------------
// fp16 single-pass batched GEMM (unchanged)
// ---------------------------------------------------------------------------
template <int BK_>
__global__ __launch_bounds__(256, 2)
void gemm_fp16(const uint16_t* __restrict__ Af, const uint16_t* __restrict__ Bf,
               const float* __restrict__ bias, float* __restrict__ C,
               int N, int K, int lda, int ldb, int ldc,
               long oAs, long oAh_, long oBs, long oBh_, long oCs, long oCh_,
               int nh, float alpha)
{
    using T = TileCfg<BK_>;
    constexpr int BKP = T::BKP;
    constexpr int SUBu = T::SUBu;
    constexpr int STGu = 2 * SUBu;
    extern __shared__ uint32_t sm[];

    const int z   = blockIdx.z;
    const int seg = z / nh;
    const int h   = z % nh;
    Af += oAs * seg + oAh_ * h;
    Bf += oBs * seg + oBh_ * h;
    C  += oCs * seg + oCh_ * h;

    const int brow = blockIdx.y * BM;
    const int bcol = blockIdx.x * BN;

    const int tid  = threadIdx.x;
    const int warp = tid >> 5;
    const int lane = tid & 31;
    const int wm = (warp >> 1) * 32;
    const int wn = (warp & 1) * 64;
    const int lg = lane >> 2;
    const int lq = lane & 3;

    const uint32_t smem_base = (uint32_t)__cvta_generic_to_shared(sm);
    const int lm_r = lane & 15;
    const int lm_c = (lane >> 4) * 4;
    const int lrow0 = tid / T::TPR;
    const int chk   = tid % T::TPR;

    float acc[2][8][4];
#pragma unroll
    for (int i = 0; i < 2; i++)
#pragma unroll
        for (int j = 0; j < 8; j++)
#pragma unroll
            for (int q = 0; q < 4; q++) acc[i][j][q] = 0.f;

    const int nit = K / BK_;

    auto load_stage = [&](int stage, int k0) {
        const uint32_t sb = smem_base + (uint32_t)stage * STGu * 4;
#pragma unroll
        for (int row = lrow0; row < 128; row += T::RSTEP) {
            const uint32_t doff = (uint32_t)(row * BKP + chk * 4) * 4;
            const long acol = (long)k0 + chk * 8;
            cp_async16(sb + 0 * SUBu * 4 + doff,
                       Af + (long)(brow + row) * lda + acol);
            const int bn  = bcol + row;
            const int ok  = (bn < N) ? 16 : 0;
            const int bno = (bn < N) ? bn : 0;
            cp_async16z(sb + 1 * SUBu * 4 + doff,
                        Bf + (long)bno * ldb + acol, ok);
        }
    };

    load_stage(0, 0);
    cp_commit();

    const uint32_t aOff0 = (uint32_t)((wm + lm_r) * BKP + lm_c) * 4;
    const uint32_t aOff1 = (uint32_t)((wm + 16 + lm_r) * BKP + lm_c) * 4;
    const uint32_t bOffBase = (uint32_t)((wn + lm_r) * BKP + lm_c) * 4;

    for (int it = 0; it < nit; it++) {
        if (it + 1 < nit) {
            load_stage((it + 1) & 1, (it + 1) * BK_);
            cp_commit();
            cp_wait<1>();
        } else {
            cp_wait<0>();
        }
        __syncthreads();

        const uint32_t stageB = smem_base + (uint32_t)(it & 1) * STGu * 4;
        const uint32_t aBase = stageB;
        const uint32_t bBase = stageB + SUBu * 4;

#pragma unroll
        for (int kc = 0; kc < BK_ / 16; kc++) {
            const uint32_t kbyte = (uint32_t)(kc * 8) * 4;

            uint32_t a[2][4];
            ldsm_x4(a[0], aBase + aOff0 + kbyte);
            ldsm_x4(a[1], aBase + aOff1 + kbyte);

#pragma unroll
            for (int ntp = 0; ntp < 4; ntp++) {
                uint32_t b[4];
                ldsm_x4(b, bBase + bOffBase + (uint32_t)(ntp * 16 * BKP) * 4 + kbyte);
#pragma unroll
                for (int half = 0; half < 2; half++)
#pragma unroll
                    for (int mt = 0; mt < 2; mt++)
                        mma_fp16(acc[mt][ntp * 2 + half], a[mt],
                                 b[half], b[2 + half]);
            }
        }
        __syncthreads();
    }

#pragma unroll
    for (int mt = 0; mt < 2; mt++) {
        const int r0 = brow + wm + mt * 16 + lg;
#pragma unroll
        for (int nt = 0; nt < 8; nt++) {
            const int c0 = bcol + wn + nt * 8 + lq * 2;
            float* p0 = C + (long)r0 * ldc;
            float* p1 = C + (long)(r0 + 8) * ldc;
            const float b0 = bias ? bias[min(c0, N - 1)] : 0.f;
            const float b1 = bias ? bias[min(c0 + 1, N - 1)] : 0.f;
            if (c0 < N) {
                p0[c0] = alpha * acc[mt][nt][0] + b0;
                p1[c0] = alpha * acc[mt][nt][2] + b0;
            }
            if (c0 + 1 < N) {
                p0[c0 + 1] = alpha * acc[mt][nt][1] + b1;
                p1[c0 + 1] = alpha * acc[mt][nt][3] + b1;
            }
        }
    }
}

// ---------------------------------------------------------------------------
// Flash attention, HDIM=80 exact (round 16, unchanged)
// ---------------------------------------------------------------------------
#define FQT 128
#define FKT 64
#define FNJ (SEG_LEN / FKT)       // 16
#define QKROW 44                  // u32 per Q/K smem row (40 + 4)
#define VROW  36                  // u32 per V smem row (32 + 4)
#define FSQH 0
#define FSQL 22528
#define FSK  45056
#define FSKS 11264
#define FSV  67584
#define FSVS 11520
#define FSMEM_B 90624

__global__ __launch_bounds__(256, 2)
void flash_attn(const uint16_t* __restrict__ Qh, const uint16_t* __restrict__ Ql,
                const uint16_t* __restrict__ Kf, const uint16_t* __restrict__ Vtf,
                uint16_t* __restrict__ Cf)
{
    extern __shared__ uint32_t sm[];
    const uint32_t smem_base = (uint32_t)__cvta_generic_to_shared(sm);

    const int bh  = blockIdx.z;
    const int seg = bh / HEADS;
    const int h   = bh % HEADS;
    const int q0  = blockIdx.y * FQT;

    const int tid  = threadIdx.x;
    const int warp = tid >> 5;
    const int lane = tid & 31;
    const int lg = lane >> 2;
    const int lq = lane & 3;
    const int lm_r = lane & 15;
    const int lm_c = (lane >> 4) * 4;

    const long qkbase = ((long)h * S_TOTAL + (long)seg * SEG_LEN);

    for (int c = tid; c < 2 * 128 * 10; c += 256) {
        const int arr = c / 1280;
        const int cc  = c % 1280;
        const int row = cc / 10;
        const int ch  = cc % 10;
        const uint32_t dst = smem_base + (arr ? FSQL : FSQH)
                           + (uint32_t)(row * QKROW) * 4 + ch * 16;
        const uint16_t* src = (arr ? Ql : Qh) + (qkbase + q0 + row) * HDIM + ch * 8;
        cp_async16(dst, src);
    }
    cp_commit();

    auto load_kv = [&](int buf, int j) {
        const uint32_t kb = smem_base + FSK + (uint32_t)buf * FSKS;
        const uint32_t vb = smem_base + FSV + (uint32_t)buf * FSVS;
        for (int c = tid; c < 64 * 10 + 80 * 8; c += 256) {
            if (c < 640) {
                const int row = c / 10, ch = c % 10;
                cp_async16(kb + (uint32_t)(row * QKROW) * 4 + ch * 16,
                           Kf + (qkbase + (long)j * FKT + row) * HDIM + ch * 8);
            } else {
                const int v = c - 640;
                const int d = v / 8, ch = v % 8;
                cp_async16(vb + (uint32_t)(d * VROW) * 4 + ch * 16,
                           Vtf + ((long)h * HDIM + d) * S_TOTAL
                               + (long)seg * SEG_LEN + (long)j * FKT + ch * 8);
            }
        }
    };

    load_kv(0, 0);
    cp_commit();
    cp_wait<0>();
    __syncthreads();

    float o[10][4];
#pragma unroll
    for (int g = 0; g < 10; g++)
#pragma unroll
        for (int q = 0; q < 4; q++) o[g][q] = 0.f;
    float m0 = -INFINITY, m1 = -INFINITY, l0 = 0.f, l1 = 0.f;

    const float scale = 0.11180339887498949f; // 1/sqrt(80)
    const uint32_t qOff = (uint32_t)((warp * 16 + lm_r) * QKROW + lm_c) * 4;

    for (int j = 0; j < FNJ; j++) {
        if (j + 1 < FNJ) { load_kv((j + 1) & 1, j + 1); cp_commit(); }

        const uint32_t kB = smem_base + FSK + (uint32_t)(j & 1) * FSKS;
        const uint32_t vB = smem_base + FSV + (uint32_t)(j & 1) * FSVS;

        float s[8][4];
#pragma unroll
        for (int t = 0; t < 8; t++)
#pragma unroll
            for (int q = 0; q < 4; q++) s[t][q] = 0.f;

#pragma unroll
        for (int kc = 0; kc < 5; kc++) {
            const uint32_t kbyte = (uint32_t)kc * 32;
            uint32_t qh[4], ql[4];
            ldsm_x4(qh, smem_base + FSQH + qOff + kbyte);
            ldsm_x4(ql, smem_base + FSQL + qOff + kbyte);
#pragma unroll
            for (int ntp = 0; ntp < 4; ntp++) {
                uint32_t kb[4];
                ldsm_x4(kb, kB + (uint32_t)((ntp * 16 + lm_r) * QKROW + lm_c) * 4 + kbyte);
                mma_fp16(s[2 * ntp],     qh, kb[0], kb[2]);
                mma_fp16(s[2 * ntp + 1], qh, kb[1], kb[3]);
                mma_fp16(s[2 * ntp],     ql, kb[0], kb[2]);
                mma_fp16(s[2 * ntp + 1], ql, kb[1], kb[3]);
            }
        }

        float mt0 = -INFINITY, mt1 = -INFINITY;
#pragma unroll
        for (int t = 0; t < 8; t++) {
            s[t][0] *= scale; s[t][1] *= scale;
            s[t][2] *= scale; s[t][3] *= scale;
            mt0 = fmaxf(mt0, fmaxf(s[t][0], s[t][1]));
            mt1 = fmaxf(mt1, fmaxf(s[t][2], s[t][3]));
        }
        mt0 = fmaxf(mt0, __shfl_xor_sync(0xffffffffu, mt0, 1));
        mt0 = fmaxf(mt0, __shfl_xor_sync(0xffffffffu, mt0, 2));
        mt1 = fmaxf(mt1, __shfl_xor_sync(0xffffffffu, mt1, 1));
        mt1 = fmaxf(mt1, __shfl_xor_sync(0xffffffffu, mt1, 2));

        const float mn0 = fmaxf(m0, mt0);
        const float mn1 = fmaxf(m1, mt1);
        const float c0 = __expf(m0 - mn0);
        const float c1 = __expf(m1 - mn1);
        m0 = mn0; m1 = mn1;

        float ls0 = 0.f, ls1 = 0.f;
#pragma unroll
        for (int t = 0; t < 8; t++) {
            s[t][0] = __expf(s[t][0] - mn0);
            s[t][1] = __expf(s[t][1] - mn0);
            s[t][2] = __expf(s[t][2] - mn1);
            s[t][3] = __expf(s[t][3] - mn1);
            ls0 += s[t][0] + s[t][1];
            ls1 += s[t][2] + s[t][3];
        }
        ls0 += __shfl_xor_sync(0xffffffffu, ls0, 1);
        ls0 += __shfl_xor_sync(0xffffffffu, ls0, 2);
        ls1 += __shfl_xor_sync(0xffffffffu, ls1, 1);
        ls1 += __shfl_xor_sync(0xffffffffu, ls1, 2);
        l0 = l0 * c0 + ls0;
        l1 = l1 * c1 + ls1;

#pragma unroll
        for (int g = 0; g < 10; g++) {
            o[g][0] *= c0; o[g][1] *= c0;
            o[g][2] *= c1; o[g][3] *= c1;
        }

#pragma unroll
        for (int u = 0; u < 4; u++) {
            uint32_t pa[4];
            pa[0] = pack_h2(s[2 * u][0],     s[2 * u][1]);
            pa[1] = pack_h2(s[2 * u][2],     s[2 * u][3]);
            pa[2] = pack_h2(s[2 * u + 1][0], s[2 * u + 1][1]);
            pa[3] = pack_h2(s[2 * u + 1][2], s[2 * u + 1][3]);
#pragma unroll
            for (int g = 0; g < 5; g++) {
                uint32_t vb[4];
                ldsm_x4(vb, vB + (uint32_t)((g * 16 + lm_r) * VROW + lm_c) * 4
                            + (uint32_t)u * 32);
                mma_fp16(o[2 * g],     pa, vb[0], vb[2]);
                mma_fp16(o[2 * g + 1], pa, vb[1], vb[3]);
            }
        }

        if (j + 1 < FNJ) cp_wait<0>();
        __syncthreads();
    }

    const float r0inv = 1.f / l0;
    const float r1inv = 1.f / l1;
    const long qrow = (long)seg * SEG_LEN + q0 + warp * 16 + lg;
    uint16_t* out0 = Cf + qrow * EMBED + h * HDIM;
    uint16_t* out1 = out0 + 8 * EMBED;
#pragma unroll
    for (int g = 0; g < 10; g++) {
        const int c0 = g * 8 + lq * 2;
        const uint32_t v0 = pack_h2(o[g][0] * r0inv, o[g][1] * r0inv);
        const uint32_t v1 = pack_h2(o[g][2] * r1inv, o[g][3] * r1inv);
        *(uint32_t*)(out0 + c0) = v0;
        *(uint32_t*)(out1 + c0) = v1;
    }
}

// ---------------------------------------------------------------------------
// elementwise conversions
// ---------------------------------------------------------------------------
__global__ void split_f16(const float* __restrict__ in,
                          uint16_t* __restrict__ hi, uint16_t* __restrict__ lo,
                          long n)
{
    const long i = (long)blockIdx.x * blockDim.x + threadIdx.x;
    if (i < n) {
        uint16_t h, l;
        split1h(in[i], h, l);
        hi[i] = h;
        lo[i] = l;
    }
}

__global__ void f32_to_f16(const float* __restrict__ in,
                           uint16_t* __restrict__ out, long n)
{
    const long i = (long)blockIdx.x * blockDim.x + threadIdx.x;
    if (i < n) out[i] = f2h(in[i]);
}

// ---------------------------------------------------------------------------
// Rotary + relayout (round 16, unchanged)
// ---------------------------------------------------------------------------
__global__ void rotary_relayout(const float* __restrict__ qkv,
                                const float* __restrict__ rope,
                                uint16_t* __restrict__ Qh, uint16_t* __restrict__ Ql,
                                uint16_t* __restrict__ Kf,
                                uint16_t* __restrict__ Vtf)
{
    const int s = blockIdx.x;
    const float* row = qkv + (long)s * QKV_F;

    for (int e = threadIdx.x; e < EMBED; e += blockDim.x) {
        const int h = e / HDIM;
        const int d = e % HDIM;
        const float f = rope[s * (HDIM / 2) + ((d < HDIM / 2) ? d : d - HDIM / 2)];
        float sn, cs;
        __sincosf(f, &sn, &cs);

        const float qv = row[e];
        const float kv = row[EMBED + e];
        const float qp = (d < HDIM / 2) ? -row[e + HDIM / 2] : row[e - HDIM / 2];
        const float kp = (d < HDIM / 2) ? -row[EMBED + e + HDIM / 2]
                                        :  row[EMBED + e - HDIM / 2];

        const float qr = qv * cs + qp * sn;
        const float kr = kv * cs + kp * sn;

        const long oq = ((long)h * S_TOTAL + s) * HDIM + d;
        uint16_t hh, ll;
        split1h(qr, hh, ll);
        Qh[oq] = hh;  Ql[oq] = ll;
        Kf[oq] = f2h(kr);

        Vtf[((long)h * HDIM + d) * S_TOTAL + s] = f2h(row[2 * EMBED + e]);
    }
}

// ---------------------------------------------------------------------------
// Entry point
// ---------------------------------------------------------------------------
extern "C" void kernel_launch(void* const* d_in, const int* in_sizes, int n_in,
                              void* d_out, int out_size)
{
    const float* x      = (const float*)d_in[0];
    const float* qkv_w  = (const float*)d_in[1];
    const float* qkv_b  = (const float*)d_in[2];
    const float* proj_w = (const float*)d_in[3];
    const float* proj_b = (const float*)d_in[4];
    const float* rope   = (const float*)d_in[5];
    float* out = (float*)d_out;

    cudaFuncSetAttribute(gemm_f16ax2<64>,
                         cudaFuncAttributeMaxDynamicSharedMemorySize, 2 * STG2B<64>());
    cudaFuncSetAttribute(gemm_fp16<64>,
                         cudaFuncAttributeMaxDynamicSharedMemorySize, 2 * STG1B<64>());
    cudaFuncSetAttribute(flash_attn,
                         cudaFuncAttributeMaxDynamicSharedMemorySize, FSMEM_B);

    float* qkv;
    uint16_t *xh, *xl, *wf, *pwf;
    uint16_t *Qh, *Ql, *Kf, *Vtf, *cf;
    cudaGetSymbolAddress((void**)&qkv, g_qkv);
    cudaGetSymbolAddress((void**)&xh,  g_xh16);  cudaGetSymbolAddress((void**)&xl, g_xl16);
    cudaGetSymbolAddress((void**)&wf,  g_wf);    cudaGetSymbolAddress((void**)&pwf, g_pwf);
    cudaGetSymbolAddress((void**)&Qh,  g_Qh16);  cudaGetSymbolAddress((void**)&Ql, g_Ql16);
    cudaGetSymbolAddress((void**)&Kf,  g_Kf16);
    cudaGetSymbolAddress((void**)&Vtf, g_Vtf);
    cudaGetSymbolAddress((void**)&cf,  g_cf);

    // 0) conversions
    {
        long n1 = (long)S_TOTAL * EMBED;
        long n2 = (long)QKV_F * EMBED;
        long n3 = (long)EMBED * EMBED;
        split_f16<<<(unsigned)((n1 + 255) / 256), 256>>>(x, xh, xl, n1);
        f32_to_f16<<<(unsigned)((n2 + 255) / 256), 256>>>(qkv_w, wf, n2);
        f32_to_f16<<<(unsigned)((n3 + 255) / 256), 256>>>(proj_w, pwf, n3);
    }

    // 1a) Q part of QKV (fp16 A-split x2, BK=64): qkv[:, 0:1280]
    {
        dim3 grid(EMBED / BN, S_TOTAL / BM, 1);
        gemm_f16ax2<64><<<grid, 256, 2 * STG2B<64>()>>>(xh, xl, wf, qkv_b, qkv,
            EMBED, EMBED, EMBED, EMBED, QKV_F, 0, 0, 0, 0, 0, 0, 1, 1.0f);
    }

    // 1b) K+V part of QKV (fp16 x1, BK=64): qkv[:, 1280:3840]
    {
        dim3 grid(QK_F / BN, S_TOTAL / BM, 1);
        gemm_fp16<64><<<grid, 256, 2 * STG1B<64>()>>>(xh, wf + (long)EMBED * EMBED,
            qkv_b + EMBED, qkv + EMBED,
            QK_F, EMBED, EMBED, EMBED, QKV_F, 0, 0, 0, 0, 0, 0, 1, 1.0f);
    }

    // 2) rotary + relayout
    rotary_relayout<<<S_TOTAL, 256>>>(qkv, rope, Qh, Ql, Kf, Vtf);

    // 3) fused attention -> fp16 ctx
    {
        dim3 grid(1, SEG_LEN / FQT, NSEG * HEADS);
        flash_attn<<<grid, 256, FSMEM_B>>>(Qh, Ql, Kf, Vtf, cf);
    }

    // 4) out = ctx @ proj_w^T + proj_b  (fp16 x1, BK=64)
    {
        dim3 grid(EMBED / BN, S_TOTAL / BM, 1);
        gemm_fp16<64><<<grid, 256, 2 * STG1B<64>()>>>(cf, pwf, proj_b, out,
            EMBED, EMBED, EMBED, EMBED, EMBED, 0, 0, 0, 0, 0, 0, 1, 1.0f);
    }
}